// round 1
// baseline (speedup 1.0000x reference)
#include <cuda_runtime.h>
#include <math.h>

#define NMAX 50048
#define EMAX 1000000

// ---------------- scratch (no allocations allowed) ----------------
__device__ int   g_src[EMAX];
__device__ int   g_dst[EMAX];
__device__ int   g_col[EMAX];
__device__ int   g_rowptr[NMAX + 1];
__device__ int   g_deg[NMAX];
__device__ int   g_cur[NMAX];
__device__ int   g_flag;   // 1 => edge_index is int32, 0 => int64
__device__ float g_h [(size_t)NMAX * 128];
__device__ float g_xl[(size_t)NMAX * 128];
__device__ float g_xr[(size_t)NMAX * 128];

// ---------------- edge format detection + conversion ----------------
// If edge_index is int64 (values < 2^31), every odd 32-bit word is 0.
// If int32, odd words are random node ids (prob all-zero ~ (1/N)^1024 = 0).
__global__ void detect_fmt(const void* ei, int e) {
    __shared__ int any;
    if (threadIdx.x == 0) any = 0;
    __syncthreads();
    const int* w = (const int*)ei;
    int lim = 2048 < e ? 2048 : e;
    for (int i = threadIdx.x; i < lim; i += 256) {
        if (w[2 * i + 1] != 0) any = 1;
    }
    __syncthreads();
    if (threadIdx.x == 0) g_flag = any;
}

__global__ void convert_edges(const void* ei, int e) {
    int i = blockIdx.x * blockDim.x + threadIdx.x;
    if (i >= e) return;
    if (g_flag == 0) {
        const long long* p = (const long long*)ei;
        g_src[i] = (int)p[i];
        g_dst[i] = (int)p[e + i];
    } else {
        const int* p = (const int*)ei;
        g_src[i] = p[i];
        g_dst[i] = p[e + i];
    }
}

// ---------------- CSR build ----------------
__global__ void zero_counts(int n) {
    int i = blockIdx.x * blockDim.x + threadIdx.x;
    if (i < n) { g_deg[i] = 0; g_cur[i] = 0; }
}

__global__ void hist_deg(int e) {
    int i = blockIdx.x * blockDim.x + threadIdx.x;
    if (i < e) atomicAdd(&g_deg[g_dst[i]], 1);
}

// single-block exclusive scan over g_deg -> g_rowptr (n up to ~64k)
__global__ void scan_kernel(int n) {
    const int T = 1024;
    __shared__ int ps[T];
    int t = threadIdx.x;
    int C = (n + T - 1) / T;
    int b0 = t * C;
    int b1 = b0 + C; if (b1 > n) b1 = n; if (b0 > n) b0 = n;
    int s = 0;
    for (int i = b0; i < b1; ++i) s += g_deg[i];
    ps[t] = s;
    __syncthreads();
    for (int o = 1; o < T; o <<= 1) {
        int v = (t >= o) ? ps[t - o] : 0;
        __syncthreads();
        ps[t] += v;
        __syncthreads();
    }
    int run = (t > 0) ? ps[t - 1] : 0;
    for (int i = b0; i < b1; ++i) { g_rowptr[i] = run; run += g_deg[i]; }
    if (t == T - 1) g_rowptr[n] = ps[T - 1];
}

__global__ void scatter_edges(int e) {
    int i = blockIdx.x * blockDim.x + threadIdx.x;
    if (i >= e) return;
    int d = g_dst[i];
    int pos = g_rowptr[d] + atomicAdd(&g_cur[d], 1);
    g_col[pos] = i;   // store edge id (for deterministic ordering)
}

// sort each node's incoming edge ids (deterministic fp order), then map to src
__global__ void sort_resolve(int n) {
    int i = blockIdx.x * blockDim.x + threadIdx.x;
    if (i >= n) return;
    int b = g_rowptr[i], e = g_rowptr[i + 1];
    for (int k = b + 1; k < e; ++k) {
        int v = g_col[k];
        int j = k - 1;
        while (j >= b && g_col[j] > v) { g_col[j + 1] = g_col[j]; --j; }
        g_col[j + 1] = v;
    }
    for (int k = b; k < e; ++k) g_col[k] = g_src[g_col[k]];
}

// ---------------- input projection: h = gelu(x @ W_in + b_in), [N,128]->[N,32]
__global__ __launch_bounds__(256) void gemm_in(
    const float* __restrict__ x, const float* __restrict__ W,
    const float* __restrict__ b, float* __restrict__ h, int n)
{
    __shared__ float Ws[128 * 32];
    __shared__ float xs[8 * 128];
    int tid = threadIdx.x;
    for (int i = tid; i < 128 * 32; i += 256) Ws[i] = W[i];
    int node0 = blockIdx.x * 8;
    for (int i = tid; i < 8 * 128; i += 256) {
        int r = i >> 7;
        int row = node0 + r;
        xs[i] = (row < n) ? x[(size_t)row * 128 + (i & 127)] : 0.f;
    }
    __syncthreads();
    int r = tid >> 5, c = tid & 31;
    float acc = 0.f;
    #pragma unroll 8
    for (int k = 0; k < 128; ++k) acc = fmaf(xs[r * 128 + k], Ws[k * 32 + c], acc);
    acc += b[c];
    float gl = 0.5f * acc * (1.f + erff(acc * 0.70710678118654752f));
    int row = node0 + r;
    if (row < n) h[(size_t)row * 32 + c] = gl;
}

// ---------------- generic GEMM: C[n,128] = A[n,K] @ W[K,128] + bias
// BM=64, BN=128, BK=32, per-thread 8x4 register tile, 256 threads
__global__ __launch_bounds__(256) void gemm128(
    const float* __restrict__ A, const float* __restrict__ W,
    const float* __restrict__ bias, float* __restrict__ C,
    int n, int K)
{
    __shared__ __align__(16) float As[32][68];   // transposed, padded
    __shared__ __align__(16) float Ws[32][128];
    int tid  = threadIdx.x;
    int row0 = blockIdx.x * 64;
    int tcol = tid & 31;
    int trow = tid >> 5;
    float acc[8][4];
    #pragma unroll
    for (int i = 0; i < 8; ++i)
        #pragma unroll
        for (int j = 0; j < 4; ++j) acc[i][j] = 0.f;

    for (int kc = 0; kc < K; kc += 32) {
        #pragma unroll
        for (int j = 0; j < 2; ++j) {
            int idx = tid + 256 * j;
            int r   = idx >> 3;
            int k4  = idx & 7;
            int row = row0 + r;
            float4 v = make_float4(0.f, 0.f, 0.f, 0.f);
            if (row < n)
                v = *reinterpret_cast<const float4*>(&A[(size_t)row * K + kc + k4 * 4]);
            As[k4 * 4 + 0][r] = v.x;
            As[k4 * 4 + 1][r] = v.y;
            As[k4 * 4 + 2][r] = v.z;
            As[k4 * 4 + 3][r] = v.w;
        }
        #pragma unroll
        for (int j = 0; j < 4; ++j) {
            int idx = tid + 256 * j;
            int k   = idx >> 5;
            int c4  = idx & 31;
            *reinterpret_cast<float4*>(&Ws[k][c4 * 4]) =
                *reinterpret_cast<const float4*>(&W[(size_t)(kc + k) * 128 + c4 * 4]);
        }
        __syncthreads();
        #pragma unroll
        for (int kk = 0; kk < 32; ++kk) {
            float4 bq = *reinterpret_cast<const float4*>(&Ws[kk][tcol * 4]);
            float4 a0 = *reinterpret_cast<const float4*>(&As[kk][trow * 8]);
            float4 a1 = *reinterpret_cast<const float4*>(&As[kk][trow * 8 + 4]);
            float av[8] = {a0.x, a0.y, a0.z, a0.w, a1.x, a1.y, a1.z, a1.w};
            float bv[4] = {bq.x, bq.y, bq.z, bq.w};
            #pragma unroll
            for (int i = 0; i < 8; ++i)
                #pragma unroll
                for (int j = 0; j < 4; ++j)
                    acc[i][j] = fmaf(av[i], bv[j], acc[i][j]);
        }
        __syncthreads();
    }
    float4 bb = *reinterpret_cast<const float4*>(&bias[tcol * 4]);
    float bv[4] = {bb.x, bb.y, bb.z, bb.w};
    #pragma unroll
    for (int i = 0; i < 8; ++i) {
        int row = row0 + trow * 8 + i;
        if (row < n) {
            float4 o;
            o.x = acc[i][0] + bv[0];
            o.y = acc[i][1] + bv[1];
            o.z = acc[i][2] + bv[2];
            o.w = acc[i][3] + bv[3];
            *reinterpret_cast<float4*>(&C[(size_t)row * 128 + tcol * 4]) = o;
        }
    }
}

// ---------------- fused GATv2 aggregation + LayerNorm + GELU + residual
// one block (128 threads) per node; warp w == head w; online softmax over
// incoming edges (self-loop processed first, CSR edges sorted by edge id).
__global__ __launch_bounds__(128) void gat_agg(
    const float* __restrict__ att, const float* __restrict__ bo,
    const float* __restrict__ gam, const float* __restrict__ bet,
    int resflag, int n)
{
    int i = blockIdx.x;
    if (i >= n) return;
    int c    = threadIdx.x;
    int lane = c & 31;
    int warp = c >> 5;

    float xl_c  = g_xl[(size_t)i * 128 + c];
    float att_c = att[c];

    // self loop
    float xr_self = g_xr[(size_t)i * 128 + c];
    float t = xl_c + xr_self;
    t = t > 0.f ? t : 0.2f * t;
    float v = t * att_c;
    #pragma unroll
    for (int o = 16; o; o >>= 1) v += __shfl_xor_sync(0xffffffffu, v, o);
    float m = v, den = 1.f, acc = xr_self;

    int beg = g_rowptr[i], end = g_rowptr[i + 1];
    for (int k = beg; k < end; ++k) {
        int s = g_col[k];
        float xr_sc = g_xr[(size_t)s * 128 + c];
        float tt = xl_c + xr_sc;
        tt = tt > 0.f ? tt : 0.2f * tt;
        float vv = tt * att_c;
        #pragma unroll
        for (int o = 16; o; o >>= 1) vv += __shfl_xor_sync(0xffffffffu, vv, o);
        if (vv <= m) {
            float p = __expf(vv - m);
            den += p;
            acc = fmaf(p, xr_sc, acc);
        } else {
            float sc = __expf(m - vv);
            den = fmaf(den, sc, 1.f);
            acc = fmaf(acc, sc, xr_sc);
            m = vv;
        }
    }
    float o_c = acc / (den + 1e-16f) + bo[c];

    // LayerNorm over 128 channels
    __shared__ float rs[4], rq[4];
    float s1 = o_c, s2 = o_c * o_c;
    #pragma unroll
    for (int o = 16; o; o >>= 1) {
        s1 += __shfl_xor_sync(0xffffffffu, s1, o);
        s2 += __shfl_xor_sync(0xffffffffu, s2, o);
    }
    if (lane == 0) { rs[warp] = s1; rq[warp] = s2; }
    __syncthreads();
    float sum = rs[0] + rs[1] + rs[2] + rs[3];
    float sq  = rq[0] + rq[1] + rq[2] + rq[3];
    float mu  = sum * (1.f / 128.f);
    float var = sq * (1.f / 128.f) - mu * mu;
    var = var > 0.f ? var : 0.f;
    float y  = gam[c] * (o_c - mu) * rsqrtf(var + 1e-5f) + bet[c];
    float gl = 0.5f * y * (1.f + erff(y * 0.70710678118654752f));

    size_t idx = (size_t)i * 128 + c;
    g_h[idx] = resflag ? (g_h[idx] + gl) : gl;
}

// ---------------- final L2 row normalization (in place on d_out)
__global__ __launch_bounds__(128) void l2norm(float* __restrict__ out, int n)
{
    int i = blockIdx.x;
    if (i >= n) return;
    int c = threadIdx.x;
    int lane = c & 31, warp = c >> 5;
    float v = out[(size_t)i * 128 + c];
    float s = v * v;
    #pragma unroll
    for (int o = 16; o; o >>= 1) s += __shfl_xor_sync(0xffffffffu, s, o);
    __shared__ float rs[4];
    if (lane == 0) rs[warp] = s;
    __syncthreads();
    float tot = rs[0] + rs[1] + rs[2] + rs[3];
    float norm = sqrtf(tot);
    norm = fmaxf(norm, 1e-12f);
    out[(size_t)i * 128 + c] = v / norm;
}

// ---------------- host launcher ----------------
extern "C" void kernel_launch(void* const* d_in, const int* in_sizes, int n_in,
                              void* d_out, int out_size)
{
    const float* x    = (const float*)d_in[0];
    const void*  ei   = d_in[1];
    const float* W_in = (const float*)d_in[2];
    const float* b_in = (const float*)d_in[3];
    const float *Wl[3], *bl[3], *Wr[3], *br[3], *att[3], *bo[3], *gg[3], *be[3];
    for (int l = 0; l < 3; ++l) {
        int base = 4 + l * 8;
        Wl[l]  = (const float*)d_in[base + 0];
        bl[l]  = (const float*)d_in[base + 1];
        Wr[l]  = (const float*)d_in[base + 2];
        br[l]  = (const float*)d_in[base + 3];
        att[l] = (const float*)d_in[base + 4];
        bo[l]  = (const float*)d_in[base + 5];
        gg[l]  = (const float*)d_in[base + 6];
        be[l]  = (const float*)d_in[base + 7];
    }
    const float* W_out = (const float*)d_in[28];
    const float* b_out = (const float*)d_in[29];

    int n = in_sizes[0] / 128;
    int e = in_sizes[1] / 2;

    float *hbuf, *xlbuf, *xrbuf;
    cudaGetSymbolAddress((void**)&hbuf,  g_h);
    cudaGetSymbolAddress((void**)&xlbuf, g_xl);
    cudaGetSymbolAddress((void**)&xrbuf, g_xr);

    // CSR build (same graph every layer)
    detect_fmt<<<1, 256>>>(ei, e);
    convert_edges<<<(e + 255) / 256, 256>>>(ei, e);
    zero_counts<<<(n + 255) / 256, 256>>>(n);
    hist_deg<<<(e + 255) / 256, 256>>>(e);
    scan_kernel<<<1, 1024>>>(n);
    scatter_edges<<<(e + 255) / 256, 256>>>(e);
    sort_resolve<<<(n + 255) / 256, 256>>>(n);

    // input projection
    gemm_in<<<(n + 7) / 8, 256>>>(x, W_in, b_in, hbuf, n);

    int ic = 32;
    for (int l = 0; l < 3; ++l) {
        gemm128<<<(n + 63) / 64, 256>>>(hbuf, Wl[l], bl[l], xlbuf, n, ic);
        gemm128<<<(n + 63) / 64, 256>>>(hbuf, Wr[l], br[l], xrbuf, n, ic);
        gat_agg<<<n, 128>>>(att[l], bo[l], gg[l], be[l], (l > 0) ? 1 : 0, n);
        ic = 128;
    }

    gemm128<<<(n + 63) / 64, 256>>>(hbuf, W_out, b_out, (float*)d_out, n, 128);
    l2norm<<<n, 128>>>((float*)d_out, n);
}

// round 2
// speedup vs baseline: 1.0114x; 1.0114x over previous
#include <cuda_runtime.h>
#include <math.h>

typedef unsigned long long ull;

#define NMAX 50048
#define EMAX 1000000

// ---------------- scratch (no allocations allowed) ----------------
__device__ int   g_src[EMAX];
__device__ int   g_dst[EMAX];
__device__ int   g_col[EMAX];
__device__ int   g_rowptr[NMAX + 1];
__device__ int   g_deg[NMAX];
__device__ int   g_cur[NMAX];
__device__ int   g_flag;   // 1 => edge_index is int32, 0 => int64
__device__ float g_h [(size_t)NMAX * 128];
__device__ float g_xl[(size_t)NMAX * 128];
__device__ float g_xr[(size_t)NMAX * 128];

// ---------------- f32x2 packed-FMA helpers (sm_103a FFMA2) ----------------
__device__ __forceinline__ ull pack2f(float x, float y) {
    ull r; asm("mov.b64 %0, {%1,%2};" : "=l"(r) : "f"(x), "f"(y)); return r;
}
__device__ __forceinline__ ull dup2f(float x) {
    ull r; asm("mov.b64 %0, {%1,%1};" : "=l"(r) : "f"(x)); return r;
}
__device__ __forceinline__ void ffma2(ull& d, ull a, ull b) {
    asm("fma.rn.f32x2 %0, %1, %2, %0;" : "+l"(d) : "l"(a), "l"(b));
}
__device__ __forceinline__ void unpack2f(ull v, float& lo, float& hi) {
    asm("mov.b64 {%0,%1}, %2;" : "=f"(lo), "=f"(hi) : "l"(v));
}

// ---------------- edge format detection ----------------
__global__ void detect_fmt(const void* ei, int e) {
    __shared__ int any;
    if (threadIdx.x == 0) any = 0;
    __syncthreads();
    const int* w = (const int*)ei;
    int lim = 2048 < e ? 2048 : e;
    for (int i = threadIdx.x; i < lim; i += 256) {
        if (w[2 * i + 1] != 0) any = 1;
    }
    __syncthreads();
    if (threadIdx.x == 0) g_flag = any;
}

__global__ void zero_counts(int n) {
    int i = blockIdx.x * blockDim.x + threadIdx.x;
    if (i < n) { g_deg[i] = 0; g_cur[i] = 0; }
}

// convert + degree histogram fused
__global__ void convert_hist(const void* ei, int e) {
    int i = blockIdx.x * blockDim.x + threadIdx.x;
    if (i >= e) return;
    int s, d;
    if (g_flag == 0) {
        const long long* p = (const long long*)ei;
        s = (int)p[i]; d = (int)p[e + i];
    } else {
        const int* p = (const int*)ei;
        s = p[i]; d = p[e + i];
    }
    g_src[i] = s;
    g_dst[i] = d;
    atomicAdd(&g_deg[d], 1);
}

// single-block exclusive scan over g_deg -> g_rowptr
__global__ void scan_kernel(int n) {
    const int T = 1024;
    __shared__ int ps[T];
    int t = threadIdx.x;
    int C = (n + T - 1) / T;
    int b0 = t * C;
    int b1 = b0 + C; if (b1 > n) b1 = n; if (b0 > n) b0 = n;
    int s = 0;
    for (int i = b0; i < b1; ++i) s += g_deg[i];
    ps[t] = s;
    __syncthreads();
    for (int o = 1; o < T; o <<= 1) {
        int v = (t >= o) ? ps[t - o] : 0;
        __syncthreads();
        ps[t] += v;
        __syncthreads();
    }
    int run = (t > 0) ? ps[t - 1] : 0;
    for (int i = b0; i < b1; ++i) { g_rowptr[i] = run; run += g_deg[i]; }
    if (t == T - 1) g_rowptr[n] = ps[T - 1];
}

__global__ void scatter_edges(int e) {
    int i = blockIdx.x * blockDim.x + threadIdx.x;
    if (i >= e) return;
    int d = g_dst[i];
    int pos = g_rowptr[d] + atomicAdd(&g_cur[d], 1);
    g_col[pos] = i;   // edge id, for deterministic ordering
}

// sort each node's incoming edge ids in a LOCAL buffer (L1-cached), then map to src
__global__ void sort_resolve(int n) {
    int i = blockIdx.x * blockDim.x + threadIdx.x;
    if (i >= n) return;
    int b = g_rowptr[i], e = g_rowptr[i + 1];
    int d = e - b;
    if (d <= 1) {
        if (d == 1) g_col[b] = g_src[g_col[b]];
        return;
    }
    if (d <= 160) {
        int loc[160];
        for (int k = 0; k < d; ++k) loc[k] = g_col[b + k];
        for (int k = 1; k < d; ++k) {
            int v = loc[k];
            int j = k - 1;
            while (j >= 0 && loc[j] > v) { loc[j + 1] = loc[j]; --j; }
            loc[j + 1] = v;
        }
        for (int k = 0; k < d; ++k) g_col[b + k] = g_src[loc[k]];
    } else {
        for (int k = b + 1; k < e; ++k) {
            int v = g_col[k];
            int j = k - 1;
            while (j >= b && g_col[j] > v) { g_col[j + 1] = g_col[j]; --j; }
            g_col[j + 1] = v;
        }
        for (int k = b; k < e; ++k) g_col[k] = g_src[g_col[k]];
    }
}

// ---------------- input projection: h = gelu(x @ W_in + b_in), [N,128]->[N,32]
__global__ __launch_bounds__(256) void gemm_in(
    const float* __restrict__ x, const float* __restrict__ W,
    const float* __restrict__ b, float* __restrict__ h, int n)
{
    __shared__ float Ws[128 * 32];
    __shared__ float xs[8 * 128];
    int tid = threadIdx.x;
    for (int i = tid; i < 128 * 32; i += 256) Ws[i] = W[i];
    int node0 = blockIdx.x * 8;
    for (int i = tid; i < 8 * 128; i += 256) {
        int r = i >> 7;
        int row = node0 + r;
        xs[i] = (row < n) ? x[(size_t)row * 128 + (i & 127)] : 0.f;
    }
    __syncthreads();
    int r = tid >> 5, c = tid & 31;
    float acc = 0.f;
    #pragma unroll 8
    for (int k = 0; k < 128; ++k) acc = fmaf(xs[r * 128 + k], Ws[k * 32 + c], acc);
    acc += b[c];
    float gl = 0.5f * acc * (1.f + erff(acc * 0.70710678118654752f));
    int row = node0 + r;
    if (row < n) h[(size_t)row * 32 + c] = gl;
}

// ---------------- FFMA2 GEMM: C[n,128] = A[n,K] @ W[K,128] + bias
// BM=128, BN=128, BK=16, 256 threads, 8x8 thread tile, accumulators packed
// along M (f32x2). blockIdx.y selects weight set (dual Wl/Wr launch).
// A must have >= row0+128 valid rows of storage (g_h does: NMAX).
__global__ __launch_bounds__(256) void gemm_ffma2(
    const float* __restrict__ A,
    const float* __restrict__ W0, const float* __restrict__ b0, float* __restrict__ C0,
    const float* __restrict__ W1, const float* __restrict__ b1, float* __restrict__ C1,
    int n, int K)
{
    const float* W    = blockIdx.y ? W1 : W0;
    const float* bias = blockIdx.y ? b1 : b0;
    float*       C    = blockIdx.y ? C1 : C0;

    __shared__ __align__(16) float As[2][16][132];   // [k][m], padded
    __shared__ __align__(16) float Ws[2][16][128];
    int tid  = threadIdx.x;
    int row0 = blockIdx.x * 128;
    int trow = tid >> 4;   // 0..15  -> rows trow*8 .. +7
    int tcol = tid & 15;   // 0..15  -> cols tcol*8 .. +7

    ull accp[4][8];
    #pragma unroll
    for (int p = 0; p < 4; ++p)
        #pragma unroll
        for (int j = 0; j < 8; ++j) accp[p][j] = 0ull;

    int chunks = K >> 4;
    float4 ra[2], rw[2];

    // prologue: load + store chunk 0
    #pragma unroll
    for (int j = 0; j < 2; ++j) {
        int idx = tid * 2 + j;
        int r = idx >> 2, k4 = idx & 3;
        ra[j] = *reinterpret_cast<const float4*>(&A[(size_t)(row0 + r) * K + k4 * 4]);
        int k = idx >> 5, c4 = idx & 31;
        rw[j] = *reinterpret_cast<const float4*>(&W[(size_t)k * 128 + c4 * 4]);
    }
    #pragma unroll
    for (int j = 0; j < 2; ++j) {
        int idx = tid * 2 + j;
        int r = idx >> 2, k4 = idx & 3;
        As[0][k4 * 4 + 0][r] = ra[j].x;
        As[0][k4 * 4 + 1][r] = ra[j].y;
        As[0][k4 * 4 + 2][r] = ra[j].z;
        As[0][k4 * 4 + 3][r] = ra[j].w;
        int k = idx >> 5, c4 = idx & 31;
        *reinterpret_cast<float4*>(&Ws[0][k][c4 * 4]) = rw[j];
    }
    __syncthreads();

    for (int c = 0; c < chunks; ++c) {
        int buf = c & 1;
        if (c + 1 < chunks) {
            int kc = (c + 1) * 16;
            #pragma unroll
            for (int j = 0; j < 2; ++j) {
                int idx = tid * 2 + j;
                int r = idx >> 2, k4 = idx & 3;
                ra[j] = *reinterpret_cast<const float4*>(&A[(size_t)(row0 + r) * K + kc + k4 * 4]);
                int k = idx >> 5, c4 = idx & 31;
                rw[j] = *reinterpret_cast<const float4*>(&W[(size_t)(kc + k) * 128 + c4 * 4]);
            }
        }
        #pragma unroll
        for (int kk = 0; kk < 16; ++kk) {
            float4 a0 = *reinterpret_cast<const float4*>(&As[buf][kk][trow * 8]);
            float4 a1 = *reinterpret_cast<const float4*>(&As[buf][kk][trow * 8 + 4]);
            float4 q0 = *reinterpret_cast<const float4*>(&Ws[buf][kk][tcol * 8]);
            float4 q1 = *reinterpret_cast<const float4*>(&Ws[buf][kk][tcol * 8 + 4]);
            ull ap[4];
            ap[0] = pack2f(a0.x, a0.y);
            ap[1] = pack2f(a0.z, a0.w);
            ap[2] = pack2f(a1.x, a1.y);
            ap[3] = pack2f(a1.z, a1.w);
            ull bd[8];
            bd[0] = dup2f(q0.x); bd[1] = dup2f(q0.y);
            bd[2] = dup2f(q0.z); bd[3] = dup2f(q0.w);
            bd[4] = dup2f(q1.x); bd[5] = dup2f(q1.y);
            bd[6] = dup2f(q1.z); bd[7] = dup2f(q1.w);
            #pragma unroll
            for (int p = 0; p < 4; ++p)
                #pragma unroll
                for (int j = 0; j < 8; ++j)
                    ffma2(accp[p][j], ap[p], bd[j]);
        }
        if (c + 1 < chunks) {
            int nb = buf ^ 1;
            #pragma unroll
            for (int j = 0; j < 2; ++j) {
                int idx = tid * 2 + j;
                int r = idx >> 2, k4 = idx & 3;
                As[nb][k4 * 4 + 0][r] = ra[j].x;
                As[nb][k4 * 4 + 1][r] = ra[j].y;
                As[nb][k4 * 4 + 2][r] = ra[j].z;
                As[nb][k4 * 4 + 3][r] = ra[j].w;
                int k = idx >> 5, c4 = idx & 31;
                *reinterpret_cast<float4*>(&Ws[nb][k][c4 * 4]) = rw[j];
            }
        }
        __syncthreads();
    }

    // epilogue
    float4 bb0 = *reinterpret_cast<const float4*>(&bias[tcol * 8]);
    float4 bb1 = *reinterpret_cast<const float4*>(&bias[tcol * 8 + 4]);
    float bv[8] = {bb0.x, bb0.y, bb0.z, bb0.w, bb1.x, bb1.y, bb1.z, bb1.w};
    #pragma unroll
    for (int p = 0; p < 4; ++p) {
        float lo[8], hi[8];
        #pragma unroll
        for (int j = 0; j < 8; ++j) unpack2f(accp[p][j], lo[j], hi[j]);
        int r0 = row0 + trow * 8 + 2 * p;
        if (r0 < n) {
            float4 o0 = make_float4(lo[0] + bv[0], lo[1] + bv[1], lo[2] + bv[2], lo[3] + bv[3]);
            float4 o1 = make_float4(lo[4] + bv[4], lo[5] + bv[5], lo[6] + bv[6], lo[7] + bv[7]);
            *reinterpret_cast<float4*>(&C[(size_t)r0 * 128 + tcol * 8])     = o0;
            *reinterpret_cast<float4*>(&C[(size_t)r0 * 128 + tcol * 8 + 4]) = o1;
        }
        if (r0 + 1 < n) {
            float4 o0 = make_float4(hi[0] + bv[0], hi[1] + bv[1], hi[2] + bv[2], hi[3] + bv[3]);
            float4 o1 = make_float4(hi[4] + bv[4], hi[5] + bv[5], hi[6] + bv[6], hi[7] + bv[7]);
            *reinterpret_cast<float4*>(&C[(size_t)(r0 + 1) * 128 + tcol * 8])     = o0;
            *reinterpret_cast<float4*>(&C[(size_t)(r0 + 1) * 128 + tcol * 8 + 4]) = o1;
        }
    }
}

// ---------------- fused GATv2 aggregation + LayerNorm + GELU + residual
__global__ __launch_bounds__(128) void gat_agg(
    const float* __restrict__ att, const float* __restrict__ bo,
    const float* __restrict__ gam, const float* __restrict__ bet,
    int resflag, int n)
{
    int i = blockIdx.x;
    if (i >= n) return;
    int c    = threadIdx.x;
    int lane = c & 31;
    int warp = c >> 5;

    float xl_c  = g_xl[(size_t)i * 128 + c];
    float att_c = __ldg(&att[c]);

    // self loop first
    float xr_self = g_xr[(size_t)i * 128 + c];
    float t = xl_c + xr_self;
    t = t > 0.f ? t : 0.2f * t;
    float v = t * att_c;
    #pragma unroll
    for (int o = 16; o; o >>= 1) v += __shfl_xor_sync(0xffffffffu, v, o);
    float m = v, den = 1.f, acc = xr_self;

    int beg = g_rowptr[i], end = g_rowptr[i + 1];
    int k = beg;
    for (; k + 2 <= end; k += 2) {
        int s0 = g_col[k];
        int s1 = g_col[k + 1];
        float x0 = g_xr[(size_t)s0 * 128 + c];
        float x1 = g_xr[(size_t)s1 * 128 + c];
        float t0 = xl_c + x0; t0 = t0 > 0.f ? t0 : 0.2f * t0;
        float t1 = xl_c + x1; t1 = t1 > 0.f ? t1 : 0.2f * t1;
        float v0 = t0 * att_c;
        float v1 = t1 * att_c;
        #pragma unroll
        for (int o = 16; o; o >>= 1) {
            v0 += __shfl_xor_sync(0xffffffffu, v0, o);
            v1 += __shfl_xor_sync(0xffffffffu, v1, o);
        }
        if (v0 <= m) {
            float p = __expf(v0 - m);
            den += p;
            acc = fmaf(p, x0, acc);
        } else {
            float sc = __expf(m - v0);
            den = fmaf(den, sc, 1.f);
            acc = fmaf(acc, sc, x0);
            m = v0;
        }
        if (v1 <= m) {
            float p = __expf(v1 - m);
            den += p;
            acc = fmaf(p, x1, acc);
        } else {
            float sc = __expf(m - v1);
            den = fmaf(den, sc, 1.f);
            acc = fmaf(acc, sc, x1);
            m = v1;
        }
    }
    if (k < end) {
        int s = g_col[k];
        float xs = g_xr[(size_t)s * 128 + c];
        float tt = xl_c + xs;
        tt = tt > 0.f ? tt : 0.2f * tt;
        float vv = tt * att_c;
        #pragma unroll
        for (int o = 16; o; o >>= 1) vv += __shfl_xor_sync(0xffffffffu, vv, o);
        if (vv <= m) {
            float p = __expf(vv - m);
            den += p;
            acc = fmaf(p, xs, acc);
        } else {
            float sc = __expf(m - vv);
            den = fmaf(den, sc, 1.f);
            acc = fmaf(acc, sc, xs);
            m = vv;
        }
    }
    float o_c = acc / (den + 1e-16f) + __ldg(&bo[c]);

    // LayerNorm over 128 channels
    __shared__ float rs[4], rq[4];
    float s1 = o_c, s2 = o_c * o_c;
    #pragma unroll
    for (int o = 16; o; o >>= 1) {
        s1 += __shfl_xor_sync(0xffffffffu, s1, o);
        s2 += __shfl_xor_sync(0xffffffffu, s2, o);
    }
    if (lane == 0) { rs[warp] = s1; rq[warp] = s2; }
    __syncthreads();
    float sum = rs[0] + rs[1] + rs[2] + rs[3];
    float sq  = rq[0] + rq[1] + rq[2] + rq[3];
    float mu  = sum * (1.f / 128.f);
    float var = sq * (1.f / 128.f) - mu * mu;
    var = var > 0.f ? var : 0.f;
    float y  = __ldg(&gam[c]) * (o_c - mu) * rsqrtf(var + 1e-5f) + __ldg(&bet[c]);
    float gl = 0.5f * y * (1.f + erff(y * 0.70710678118654752f));

    size_t idx = (size_t)i * 128 + c;
    g_h[idx] = resflag ? (g_h[idx] + gl) : gl;
}

// ---------------- final L2 row normalization (in place on d_out)
__global__ __launch_bounds__(128) void l2norm(float* __restrict__ out, int n)
{
    int i = blockIdx.x;
    if (i >= n) return;
    int c = threadIdx.x;
    int lane = c & 31, warp = c >> 5;
    float v = out[(size_t)i * 128 + c];
    float s = v * v;
    #pragma unroll
    for (int o = 16; o; o >>= 1) s += __shfl_xor_sync(0xffffffffu, s, o);
    __shared__ float rs[4];
    if (lane == 0) rs[warp] = s;
    __syncthreads();
    float tot = rs[0] + rs[1] + rs[2] + rs[3];
    float norm = sqrtf(tot);
    norm = fmaxf(norm, 1e-12f);
    out[(size_t)i * 128 + c] = v / norm;
}

// ---------------- host launcher ----------------
extern "C" void kernel_launch(void* const* d_in, const int* in_sizes, int n_in,
                              void* d_out, int out_size)
{
    const float* x    = (const float*)d_in[0];
    const void*  ei   = d_in[1];
    const float* W_in = (const float*)d_in[2];
    const float* b_in = (const float*)d_in[3];
    const float *Wl[3], *bl[3], *Wr[3], *br[3], *att[3], *bo[3], *gg[3], *be[3];
    for (int l = 0; l < 3; ++l) {
        int base = 4 + l * 8;
        Wl[l]  = (const float*)d_in[base + 0];
        bl[l]  = (const float*)d_in[base + 1];
        Wr[l]  = (const float*)d_in[base + 2];
        br[l]  = (const float*)d_in[base + 3];
        att[l] = (const float*)d_in[base + 4];
        bo[l]  = (const float*)d_in[base + 5];
        gg[l]  = (const float*)d_in[base + 6];
        be[l]  = (const float*)d_in[base + 7];
    }
    const float* W_out = (const float*)d_in[28];
    const float* b_out = (const float*)d_in[29];

    int n = in_sizes[0] / 128;
    int e = in_sizes[1] / 2;

    float *hbuf, *xlbuf, *xrbuf;
    cudaGetSymbolAddress((void**)&hbuf,  g_h);
    cudaGetSymbolAddress((void**)&xlbuf, g_xl);
    cudaGetSymbolAddress((void**)&xrbuf, g_xr);

    // CSR build
    detect_fmt<<<1, 256>>>(ei, e);
    zero_counts<<<(n + 255) / 256, 256>>>(n);
    convert_hist<<<(e + 255) / 256, 256>>>(ei, e);
    scan_kernel<<<1, 1024>>>(n);
    scatter_edges<<<(e + 255) / 256, 256>>>(e);
    sort_resolve<<<(n + 255) / 256, 256>>>(n);

    // input projection
    gemm_in<<<(n + 7) / 8, 256>>>(x, W_in, b_in, hbuf, n);

    dim3 gdual((n + 127) / 128, 2);
    dim3 gsingle((n + 127) / 128, 1);

    int ic = 32;
    for (int l = 0; l < 3; ++l) {
        gemm_ffma2<<<gdual, 256>>>(hbuf,
                                   Wl[l], bl[l], xlbuf,
                                   Wr[l], br[l], xrbuf,
                                   n, ic);
        gat_agg<<<n, 128>>>(att[l], bo[l], gg[l], be[l], (l > 0) ? 1 : 0, n);
        ic = 128;
    }

    gemm_ffma2<<<gsingle, 256>>>(hbuf,
                                 W_out, b_out, (float*)d_out,
                                 W_out, b_out, (float*)d_out,
                                 n, 128);
    l2norm<<<n, 128>>>((float*)d_out, n);
}

// round 3
// speedup vs baseline: 1.0986x; 1.0863x over previous
#include <cuda_runtime.h>
#include <math.h>

typedef unsigned long long ull;

#define NMAX 50048
#define EMAX 1000000

// ---------------- scratch (no allocations allowed) ----------------
__device__ int   g_src[EMAX];
__device__ int   g_dst[EMAX];
__device__ int   g_col[EMAX];
__device__ int   g_rowptr[NMAX + 1];
__device__ int   g_deg[NMAX];
__device__ int   g_cur[NMAX];
__device__ int   g_part[64];
__device__ int   g_partoff[64];
__device__ int   g_flag;   // 1 => edge_index is int32, 0 => int64
__device__ float g_h [(size_t)NMAX * 128];
__device__ float g_xl[(size_t)NMAX * 128];
__device__ float g_xr[(size_t)NMAX * 128];

// ---------------- f32x2 packed-FMA helpers (sm_103a FFMA2) ----------------
__device__ __forceinline__ ull pack2f(float x, float y) {
    ull r; asm("mov.b64 %0, {%1,%2};" : "=l"(r) : "f"(x), "f"(y)); return r;
}
__device__ __forceinline__ ull dup2f(float x) {
    ull r; asm("mov.b64 %0, {%1,%1};" : "=l"(r) : "f"(x)); return r;
}
__device__ __forceinline__ void ffma2(ull& d, ull a, ull b) {
    asm("fma.rn.f32x2 %0, %1, %2, %0;" : "+l"(d) : "l"(a), "l"(b));
}
__device__ __forceinline__ void unpack2f(ull v, float& lo, float& hi) {
    asm("mov.b64 {%0,%1}, %2;" : "=f"(lo), "=f"(hi) : "l"(v));
}

// ---------------- zero counters + edge dtype detection ----------------
__global__ void zero_detect(const void* ei, int e, int n) {
    int i = blockIdx.x * blockDim.x + threadIdx.x;
    if (i < n) { g_deg[i] = 0; g_cur[i] = 0; }
    if (blockIdx.x == 0) {
        __shared__ int any;
        if (threadIdx.x == 0) any = 0;
        __syncthreads();
        const int* w = (const int*)ei;
        int lim = 2048 < e ? 2048 : e;
        for (int k = threadIdx.x; k < lim; k += 256)
            if (w[2 * k + 1] != 0) any = 1;
        __syncthreads();
        if (threadIdx.x == 0) g_flag = any;
    }
}

// convert + degree histogram fused
__global__ void convert_hist(const void* ei, int e) {
    int i = blockIdx.x * blockDim.x + threadIdx.x;
    if (i >= e) return;
    int s, d;
    if (g_flag == 0) {
        const long long* p = (const long long*)ei;
        s = (int)p[i]; d = (int)p[e + i];
    } else {
        const int* p = (const int*)ei;
        s = p[i]; d = p[e + i];
    }
    g_src[i] = s;
    g_dst[i] = d;
    atomicAdd(&g_deg[d], 1);
}

// ---------------- multi-block exclusive scan of g_deg -> g_rowptr --------
// phase 1: per-block (1024 elems) totals
__global__ __launch_bounds__(256) void scan_part(int n) {
    __shared__ int wsum[8];
    int b = blockIdx.x, t = threadIdx.x;
    int base = b * 1024 + t * 4;
    int s = 0;
    #pragma unroll
    for (int j = 0; j < 4; ++j) s += (base + j < n) ? g_deg[base + j] : 0;
    #pragma unroll
    for (int o = 16; o; o >>= 1) s += __shfl_xor_sync(0xffffffffu, s, o);
    if ((t & 31) == 0) wsum[t >> 5] = s;
    __syncthreads();
    if (t == 0) {
        int tot = 0;
        #pragma unroll
        for (int w = 0; w < 8; ++w) tot += wsum[w];
        g_part[b] = tot;
    }
}

// phase 2: scan of block totals (P <= 64)
__global__ void scan_top(int P, int n) {
    __shared__ int sp[64];
    int t = threadIdx.x;
    if (t < P) sp[t] = g_part[t];
    __syncthreads();
    if (t == 0) {
        int run = 0;
        for (int b = 0; b < P; ++b) { g_partoff[b] = run; run += sp[b]; }
        g_rowptr[n] = run;
    }
}

// phase 3: block-local exclusive scan + offset, writes g_rowptr
__global__ __launch_bounds__(256) void scan_down(int n) {
    __shared__ int wsum[8];
    int b = blockIdx.x, t = threadIdx.x;
    int base = b * 1024 + t * 4;
    int v[4];
    #pragma unroll
    for (int j = 0; j < 4; ++j) v[j] = (base + j < n) ? g_deg[base + j] : 0;
    int s = v[0] + v[1] + v[2] + v[3];
    int incl = s;
    int lane = t & 31;
    #pragma unroll
    for (int o = 1; o < 32; o <<= 1) {
        int u = __shfl_up_sync(0xffffffffu, incl, o);
        if (lane >= o) incl += u;
    }
    if (lane == 31) wsum[t >> 5] = incl;
    __syncthreads();
    int woff = 0;
    int myw = t >> 5;
    #pragma unroll
    for (int w = 0; w < 8; ++w) if (w < myw) woff += wsum[w];
    int run = g_partoff[b] + woff + (incl - s);
    #pragma unroll
    for (int j = 0; j < 4; ++j) {
        if (base + j < n) g_rowptr[base + j] = run;
        run += v[j];
    }
}

__global__ void scatter_edges(int e) {
    int i = blockIdx.x * blockDim.x + threadIdx.x;
    if (i >= e) return;
    int d = g_dst[i];
    int pos = g_rowptr[d] + atomicAdd(&g_cur[d], 1);
    g_col[pos] = i;   // edge id, for deterministic ordering
}

// sort each node's incoming edge ids in a local buffer, then map to src
__global__ void sort_resolve(int n) {
    int i = blockIdx.x * blockDim.x + threadIdx.x;
    if (i >= n) return;
    int b = g_rowptr[i], e = g_rowptr[i + 1];
    int d = e - b;
    if (d <= 1) {
        if (d == 1) g_col[b] = g_src[g_col[b]];
        return;
    }
    if (d <= 160) {
        int loc[160];
        for (int k = 0; k < d; ++k) loc[k] = g_col[b + k];
        for (int k = 1; k < d; ++k) {
            int v = loc[k];
            int j = k - 1;
            while (j >= 0 && loc[j] > v) { loc[j + 1] = loc[j]; --j; }
            loc[j + 1] = v;
        }
        for (int k = 0; k < d; ++k) g_col[b + k] = g_src[loc[k]];
    } else {
        for (int k = b + 1; k < e; ++k) {
            int v = g_col[k];
            int j = k - 1;
            while (j >= b && g_col[j] > v) { g_col[j + 1] = g_col[j]; --j; }
            g_col[j + 1] = v;
        }
        for (int k = b; k < e; ++k) g_col[k] = g_src[g_col[k]];
    }
}

// ---------------- input projection: h = gelu(x @ W_in + b_in), [N,128]->[N,32]
__global__ __launch_bounds__(256) void gemm_in(
    const float* __restrict__ x, const float* __restrict__ W,
    const float* __restrict__ b, float* __restrict__ h, int n)
{
    __shared__ __align__(16) float Ws[128 * 32];
    __shared__ __align__(16) float xs[8 * 128];
    int tid = threadIdx.x;
    for (int i = tid; i < 128 * 32 / 4; i += 256)
        *reinterpret_cast<float4*>(&Ws[i * 4]) = *reinterpret_cast<const float4*>(&W[i * 4]);
    int node0 = blockIdx.x * 8;
    for (int i = tid; i < 8 * 32; i += 256) {
        int r = i >> 5;
        int row = node0 + r;
        float4 v = make_float4(0.f, 0.f, 0.f, 0.f);
        if (row < n) v = *reinterpret_cast<const float4*>(&x[(size_t)row * 128 + (i & 31) * 4]);
        *reinterpret_cast<float4*>(&xs[r * 128 + (i & 31) * 4]) = v;
    }
    __syncthreads();
    int r = tid >> 5, c = tid & 31;
    float acc = 0.f;
    const float4* xsr = reinterpret_cast<const float4*>(&xs[r * 128]);
    #pragma unroll
    for (int k4 = 0; k4 < 32; ++k4) {
        float4 xv = xsr[k4];
        acc = fmaf(xv.x, Ws[(k4 * 4 + 0) * 32 + c], acc);
        acc = fmaf(xv.y, Ws[(k4 * 4 + 1) * 32 + c], acc);
        acc = fmaf(xv.z, Ws[(k4 * 4 + 2) * 32 + c], acc);
        acc = fmaf(xv.w, Ws[(k4 * 4 + 3) * 32 + c], acc);
    }
    acc += b[c];
    float gl = 0.5f * acc * (1.f + erff(acc * 0.70710678118654752f));
    int row = node0 + r;
    if (row < n) h[(size_t)row * 32 + c] = gl;
}

// ---------------- FFMA2 GEMM: C[n,128] = A[n,K] @ W[K,128] + bias
__global__ __launch_bounds__(256) void gemm_ffma2(
    const float* __restrict__ A,
    const float* __restrict__ W0, const float* __restrict__ b0, float* __restrict__ C0,
    const float* __restrict__ W1, const float* __restrict__ b1, float* __restrict__ C1,
    int n, int K)
{
    const float* W    = blockIdx.y ? W1 : W0;
    const float* bias = blockIdx.y ? b1 : b0;
    float*       C    = blockIdx.y ? C1 : C0;

    __shared__ __align__(16) float As[2][16][132];   // [k][m], padded
    __shared__ __align__(16) float Ws[2][16][128];
    int tid  = threadIdx.x;
    int row0 = blockIdx.x * 128;
    int trow = tid >> 4;   // 0..15
    int tcol = tid & 15;   // 0..15

    ull accp[4][8];
    #pragma unroll
    for (int p = 0; p < 4; ++p)
        #pragma unroll
        for (int j = 0; j < 8; ++j) accp[p][j] = 0ull;

    int chunks = K >> 4;
    float4 ra[2], rw[2];

    #pragma unroll
    for (int j = 0; j < 2; ++j) {
        int idx = tid * 2 + j;
        int r = idx >> 2, k4 = idx & 3;
        ra[j] = *reinterpret_cast<const float4*>(&A[(size_t)(row0 + r) * K + k4 * 4]);
        int k = idx >> 5, c4 = idx & 31;
        rw[j] = *reinterpret_cast<const float4*>(&W[(size_t)k * 128 + c4 * 4]);
    }
    #pragma unroll
    for (int j = 0; j < 2; ++j) {
        int idx = tid * 2 + j;
        int r = idx >> 2, k4 = idx & 3;
        As[0][k4 * 4 + 0][r] = ra[j].x;
        As[0][k4 * 4 + 1][r] = ra[j].y;
        As[0][k4 * 4 + 2][r] = ra[j].z;
        As[0][k4 * 4 + 3][r] = ra[j].w;
        int k = idx >> 5, c4 = idx & 31;
        *reinterpret_cast<float4*>(&Ws[0][k][c4 * 4]) = rw[j];
    }
    __syncthreads();

    for (int c = 0; c < chunks; ++c) {
        int buf = c & 1;
        if (c + 1 < chunks) {
            int kc = (c + 1) * 16;
            #pragma unroll
            for (int j = 0; j < 2; ++j) {
                int idx = tid * 2 + j;
                int r = idx >> 2, k4 = idx & 3;
                ra[j] = *reinterpret_cast<const float4*>(&A[(size_t)(row0 + r) * K + kc + k4 * 4]);
                int k = idx >> 5, c4 = idx & 31;
                rw[j] = *reinterpret_cast<const float4*>(&W[(size_t)(kc + k) * 128 + c4 * 4]);
            }
        }
        #pragma unroll
        for (int kk = 0; kk < 16; ++kk) {
            float4 a0 = *reinterpret_cast<const float4*>(&As[buf][kk][trow * 8]);
            float4 a1 = *reinterpret_cast<const float4*>(&As[buf][kk][trow * 8 + 4]);
            float4 q0 = *reinterpret_cast<const float4*>(&Ws[buf][kk][tcol * 8]);
            float4 q1 = *reinterpret_cast<const float4*>(&Ws[buf][kk][tcol * 8 + 4]);
            ull ap[4];
            ap[0] = pack2f(a0.x, a0.y);
            ap[1] = pack2f(a0.z, a0.w);
            ap[2] = pack2f(a1.x, a1.y);
            ap[3] = pack2f(a1.z, a1.w);
            ull bd[8];
            bd[0] = dup2f(q0.x); bd[1] = dup2f(q0.y);
            bd[2] = dup2f(q0.z); bd[3] = dup2f(q0.w);
            bd[4] = dup2f(q1.x); bd[5] = dup2f(q1.y);
            bd[6] = dup2f(q1.z); bd[7] = dup2f(q1.w);
            #pragma unroll
            for (int p = 0; p < 4; ++p)
                #pragma unroll
                for (int j = 0; j < 8; ++j)
                    ffma2(accp[p][j], ap[p], bd[j]);
        }
        if (c + 1 < chunks) {
            int nb = buf ^ 1;
            #pragma unroll
            for (int j = 0; j < 2; ++j) {
                int idx = tid * 2 + j;
                int r = idx >> 2, k4 = idx & 3;
                As[nb][k4 * 4 + 0][r] = ra[j].x;
                As[nb][k4 * 4 + 1][r] = ra[j].y;
                As[nb][k4 * 4 + 2][r] = ra[j].z;
                As[nb][k4 * 4 + 3][r] = ra[j].w;
                int k = idx >> 5, c4 = idx & 31;
                *reinterpret_cast<float4*>(&Ws[nb][k][c4 * 4]) = rw[j];
            }
        }
        __syncthreads();
    }

    float4 bb0 = *reinterpret_cast<const float4*>(&bias[tcol * 8]);
    float4 bb1 = *reinterpret_cast<const float4*>(&bias[tcol * 8 + 4]);
    float bv[8] = {bb0.x, bb0.y, bb0.z, bb0.w, bb1.x, bb1.y, bb1.z, bb1.w};
    #pragma unroll
    for (int p = 0; p < 4; ++p) {
        float lo[8], hi[8];
        #pragma unroll
        for (int j = 0; j < 8; ++j) unpack2f(accp[p][j], lo[j], hi[j]);
        int r0 = row0 + trow * 8 + 2 * p;
        if (r0 < n) {
            float4 o0 = make_float4(lo[0] + bv[0], lo[1] + bv[1], lo[2] + bv[2], lo[3] + bv[3]);
            float4 o1 = make_float4(lo[4] + bv[4], lo[5] + bv[5], lo[6] + bv[6], lo[7] + bv[7]);
            *reinterpret_cast<float4*>(&C[(size_t)r0 * 128 + tcol * 8])     = o0;
            *reinterpret_cast<float4*>(&C[(size_t)r0 * 128 + tcol * 8 + 4]) = o1;
        }
        if (r0 + 1 < n) {
            float4 o0 = make_float4(hi[0] + bv[0], hi[1] + bv[1], hi[2] + bv[2], hi[3] + bv[3]);
            float4 o1 = make_float4(hi[4] + bv[4], hi[5] + bv[5], hi[6] + bv[6], hi[7] + bv[7]);
            *reinterpret_cast<float4*>(&C[(size_t)(r0 + 1) * 128 + tcol * 8])     = o0;
            *reinterpret_cast<float4*>(&C[(size_t)(r0 + 1) * 128 + tcol * 8 + 4]) = o1;
        }
    }
}

// ---------------- fused GATv2 aggregation + LayerNorm + GELU + residual
__global__ __launch_bounds__(128) void gat_agg(
    const float* __restrict__ att, const float* __restrict__ bo,
    const float* __restrict__ gam, const float* __restrict__ bet,
    int resflag, int n)
{
    int i = blockIdx.x;
    if (i >= n) return;
    int c    = threadIdx.x;
    int lane = c & 31;
    int warp = c >> 5;

    float xl_c  = g_xl[(size_t)i * 128 + c];
    float att_c = __ldg(&att[c]);

    // self loop first
    float xr_self = g_xr[(size_t)i * 128 + c];
    float t = xl_c + xr_self;
    t = t > 0.f ? t : 0.2f * t;
    float v = t * att_c;
    #pragma unroll
    for (int o = 16; o; o >>= 1) v += __shfl_xor_sync(0xffffffffu, v, o);
    float m = v, den = 1.f, acc = xr_self;

    auto merge = [&](float vv, float xv) {
        if (vv <= m) {
            float p = __expf(vv - m);
            den += p;
            acc = fmaf(p, xv, acc);
        } else {
            float sc = __expf(m - vv);
            den = fmaf(den, sc, 1.f);
            acc = fmaf(acc, sc, xv);
            m = vv;
        }
    };

    int beg = g_rowptr[i], end = g_rowptr[i + 1];
    int k = beg;
    for (; k + 4 <= end; k += 4) {
        int s0 = g_col[k];
        int s1 = g_col[k + 1];
        int s2 = g_col[k + 2];
        int s3 = g_col[k + 3];
        float x0 = g_xr[(size_t)s0 * 128 + c];
        float x1 = g_xr[(size_t)s1 * 128 + c];
        float x2 = g_xr[(size_t)s2 * 128 + c];
        float x3 = g_xr[(size_t)s3 * 128 + c];
        float t0 = xl_c + x0; t0 = t0 > 0.f ? t0 : 0.2f * t0;
        float t1 = xl_c + x1; t1 = t1 > 0.f ? t1 : 0.2f * t1;
        float t2 = xl_c + x2; t2 = t2 > 0.f ? t2 : 0.2f * t2;
        float t3 = xl_c + x3; t3 = t3 > 0.f ? t3 : 0.2f * t3;
        float v0 = t0 * att_c;
        float v1 = t1 * att_c;
        float v2 = t2 * att_c;
        float v3 = t3 * att_c;
        #pragma unroll
        for (int o = 16; o; o >>= 1) {
            v0 += __shfl_xor_sync(0xffffffffu, v0, o);
            v1 += __shfl_xor_sync(0xffffffffu, v1, o);
            v2 += __shfl_xor_sync(0xffffffffu, v2, o);
            v3 += __shfl_xor_sync(0xffffffffu, v3, o);
        }
        merge(v0, x0);
        merge(v1, x1);
        merge(v2, x2);
        merge(v3, x3);
    }
    for (; k < end; ++k) {
        int s = g_col[k];
        float xs = g_xr[(size_t)s * 128 + c];
        float tt = xl_c + xs;
        tt = tt > 0.f ? tt : 0.2f * tt;
        float vv = tt * att_c;
        #pragma unroll
        for (int o = 16; o; o >>= 1) vv += __shfl_xor_sync(0xffffffffu, vv, o);
        merge(vv, xs);
    }
    float o_c = acc / (den + 1e-16f) + __ldg(&bo[c]);

    // LayerNorm over 128 channels
    __shared__ float rs[4], rq[4];
    float s1 = o_c, s2 = o_c * o_c;
    #pragma unroll
    for (int o = 16; o; o >>= 1) {
        s1 += __shfl_xor_sync(0xffffffffu, s1, o);
        s2 += __shfl_xor_sync(0xffffffffu, s2, o);
    }
    if (lane == 0) { rs[warp] = s1; rq[warp] = s2; }
    __syncthreads();
    float sum = rs[0] + rs[1] + rs[2] + rs[3];
    float sq  = rq[0] + rq[1] + rq[2] + rq[3];
    float mu  = sum * (1.f / 128.f);
    float var = sq * (1.f / 128.f) - mu * mu;
    var = var > 0.f ? var : 0.f;
    float y  = __ldg(&gam[c]) * (o_c - mu) * rsqrtf(var + 1e-5f) + __ldg(&bet[c]);
    float gl = 0.5f * y * (1.f + erff(y * 0.70710678118654752f));

    size_t idx = (size_t)i * 128 + c;
    g_h[idx] = resflag ? (g_h[idx] + gl) : gl;
}

// ---------------- final L2 row normalization (in place on d_out)
__global__ __launch_bounds__(128) void l2norm(float* __restrict__ out, int n)
{
    int i = blockIdx.x;
    if (i >= n) return;
    int c = threadIdx.x;
    int lane = c & 31, warp = c >> 5;
    float v = out[(size_t)i * 128 + c];
    float s = v * v;
    #pragma unroll
    for (int o = 16; o; o >>= 1) s += __shfl_xor_sync(0xffffffffu, s, o);
    __shared__ float rs[4];
    if (lane == 0) rs[warp] = s;
    __syncthreads();
    float tot = rs[0] + rs[1] + rs[2] + rs[3];
    float norm = sqrtf(tot);
    norm = fmaxf(norm, 1e-12f);
    out[(size_t)i * 128 + c] = v / norm;
}

// ---------------- host launcher ----------------
extern "C" void kernel_launch(void* const* d_in, const int* in_sizes, int n_in,
                              void* d_out, int out_size)
{
    const float* x    = (const float*)d_in[0];
    const void*  ei   = d_in[1];
    const float* W_in = (const float*)d_in[2];
    const float* b_in = (const float*)d_in[3];
    const float *Wl[3], *bl[3], *Wr[3], *br[3], *att[3], *bo[3], *gg[3], *be[3];
    for (int l = 0; l < 3; ++l) {
        int base = 4 + l * 8;
        Wl[l]  = (const float*)d_in[base + 0];
        bl[l]  = (const float*)d_in[base + 1];
        Wr[l]  = (const float*)d_in[base + 2];
        br[l]  = (const float*)d_in[base + 3];
        att[l] = (const float*)d_in[base + 4];
        bo[l]  = (const float*)d_in[base + 5];
        gg[l]  = (const float*)d_in[base + 6];
        be[l]  = (const float*)d_in[base + 7];
    }
    const float* W_out = (const float*)d_in[28];
    const float* b_out = (const float*)d_in[29];

    int n = in_sizes[0] / 128;
    int e = in_sizes[1] / 2;
    int P = (n + 1023) / 1024;

    float *hbuf, *xlbuf, *xrbuf;
    cudaGetSymbolAddress((void**)&hbuf,  g_h);
    cudaGetSymbolAddress((void**)&xlbuf, g_xl);
    cudaGetSymbolAddress((void**)&xrbuf, g_xr);

    dim3 gdual((n + 127) / 128, 2);
    dim3 gsingle((n + 127) / 128, 1);

    // 0-1: edge convert + degree histogram
    zero_detect<<<(n + 255) / 256, 256>>>(ei, e, n);
    convert_hist<<<(e + 255) / 256, 256>>>(ei, e);
    // 2-3: input projection + layer-0 dual GEMM (independent of CSR)
    gemm_in<<<(n + 7) / 8, 256>>>(x, W_in, b_in, hbuf, n);
    gemm_ffma2<<<gdual, 256>>>(hbuf, Wl[0], bl[0], xlbuf, Wr[0], br[0], xrbuf, n, 32);
    // 4-8: finish CSR
    scan_part<<<P, 256>>>(n);
    scan_top<<<1, 64>>>(P, n);
    scan_down<<<P, 256>>>(n);
    scatter_edges<<<(e + 255) / 256, 256>>>(e);
    sort_resolve<<<(n + 255) / 256, 256>>>(n);

    // layers
    gat_agg<<<n, 128>>>(att[0], bo[0], gg[0], be[0], 0, n);
    for (int l = 1; l < 3; ++l) {
        gemm_ffma2<<<gdual, 256>>>(hbuf, Wl[l], bl[l], xlbuf, Wr[l], br[l], xrbuf, n, 128);
        gat_agg<<<n, 128>>>(att[l], bo[l], gg[l], be[l], 1, n);
    }

    gemm_ffma2<<<gsingle, 256>>>(hbuf, W_out, b_out, (float*)d_out,
                                 W_out, b_out, (float*)d_out, n, 128);
    l2norm<<<n, 128>>>((float*)d_out, n);
}

// round 4
// speedup vs baseline: 1.5886x; 1.4460x over previous
#include <cuda_runtime.h>
#include <math.h>

typedef unsigned long long ull;

#define NMAX 50048
#define EMAX 1000000

// ---------------- scratch (no allocations allowed) ----------------
__device__ int   g_src[EMAX];
__device__ int   g_dst[EMAX];
__device__ int   g_col[EMAX];
__device__ int   g_rowptr[NMAX + 1];
__device__ int   g_deg[NMAX];
__device__ int   g_cur[NMAX];
__device__ int   g_flag;   // 1 => edge_index is int32, 0 => int64
__device__ float g_h [(size_t)NMAX * 128];
__device__ float g_xl[(size_t)NMAX * 128];
__device__ float g_xr[(size_t)NMAX * 128];

// ---------------- f32x2 packed-FMA helpers (sm_103a FFMA2) ----------------
__device__ __forceinline__ ull pack2f(float x, float y) {
    ull r; asm("mov.b64 %0, {%1,%2};" : "=l"(r) : "f"(x), "f"(y)); return r;
}
__device__ __forceinline__ ull dup2f(float x) {
    ull r; asm("mov.b64 %0, {%1,%1};" : "=l"(r) : "f"(x)); return r;
}
__device__ __forceinline__ void ffma2(ull& d, ull a, ull b) {
    asm("fma.rn.f32x2 %0, %1, %2, %0;" : "+l"(d) : "l"(a), "l"(b));
}
__device__ __forceinline__ void unpack2f(ull v, float& lo, float& hi) {
    asm("mov.b64 {%0,%1}, %2;" : "=f"(lo), "=f"(hi) : "l"(v));
}

// ---------------- zero counters + edge dtype detection ----------------
__global__ void zero_detect(const void* ei, int e, int n) {
    int i = blockIdx.x * blockDim.x + threadIdx.x;
    if (i < n) { g_deg[i] = 0; g_cur[i] = 0; }
    if (blockIdx.x == 0) {
        __shared__ int any;
        if (threadIdx.x == 0) any = 0;
        __syncthreads();
        const int* w = (const int*)ei;
        int lim = 2048 < e ? 2048 : e;
        for (int k = threadIdx.x; k < lim; k += 256)
            if (w[2 * k + 1] != 0) any = 1;
        __syncthreads();
        if (threadIdx.x == 0) g_flag = any;
    }
}

// convert + degree histogram fused
__global__ void convert_hist(const void* ei, int e) {
    int i = blockIdx.x * blockDim.x + threadIdx.x;
    if (i >= e) return;
    int s, d;
    if (g_flag == 0) {
        const long long* p = (const long long*)ei;
        s = (int)p[i]; d = (int)p[e + i];
    } else {
        const int* p = (const int*)ei;
        s = p[i]; d = p[e + i];
    }
    g_src[i] = s;
    g_dst[i] = d;
    atomicAdd(&g_deg[d], 1);
}

// ---------------- single-block exclusive scan of g_deg -> g_rowptr -------
__global__ __launch_bounds__(1024) void scan_all(int n) {
    __shared__ int ws[32];
    int t = threadIdx.x;
    int lane = t & 31, w = t >> 5;
    int C = (n + 1023) >> 10;
    int b0 = t * C;
    int b1 = b0 + C; if (b1 > n) b1 = n; if (b0 > n) b0 = n;
    int s = 0;
    for (int i = b0; i < b1; ++i) s += g_deg[i];
    int incl = s;
    #pragma unroll
    for (int o = 1; o < 32; o <<= 1) {
        int u = __shfl_up_sync(0xffffffffu, incl, o);
        if (lane >= o) incl += u;
    }
    if (lane == 31) ws[w] = incl;
    __syncthreads();
    if (w == 0) {
        int v = ws[lane];
        int inc2 = v;
        #pragma unroll
        for (int o = 1; o < 32; o <<= 1) {
            int u = __shfl_up_sync(0xffffffffu, inc2, o);
            if (lane >= o) inc2 += u;
        }
        ws[lane] = inc2;
    }
    __syncthreads();
    int off = (w > 0 ? ws[w - 1] : 0) + (incl - s);
    int run = off;
    for (int i = b0; i < b1; ++i) { g_rowptr[i] = run; run += g_deg[i]; }
    if (t == 1023) g_rowptr[n] = off + s;
}

__global__ void scatter_edges(int e) {
    int i = blockIdx.x * blockDim.x + threadIdx.x;
    if (i >= e) return;
    int d = g_dst[i];
    int pos = g_rowptr[d] + atomicAdd(&g_cur[d], 1);
    g_col[pos] = i;   // edge id, for deterministic ordering
}

// warp-per-node rank sort of edge ids (unique), then map to src
__global__ __launch_bounds__(256) void sort_warp(int n) {
    int gw = (blockIdx.x * blockDim.x + threadIdx.x) >> 5;
    int lane = threadIdx.x & 31;
    if (gw >= n) return;
    int b = g_rowptr[gw], e = g_rowptr[gw + 1];
    int d = e - b;
    if (d <= 1) {
        if (d == 1 && lane == 0) g_col[b] = g_src[g_col[b]];
        return;
    }
    if (d <= 32) {
        int val = (lane < d) ? g_col[b + lane] : 0x7fffffff;
        int rank = 0;
        for (int j = 0; j < d; ++j) {
            int vj = __shfl_sync(0xffffffffu, val, j);
            rank += (vj < val);
        }
        if (lane < d) g_col[b + rank] = g_src[val];
    } else if (d <= 64) {
        int v0 = (lane < d)      ? g_col[b + lane]      : 0x7fffffff;
        int v1 = (32 + lane < d) ? g_col[b + 32 + lane] : 0x7fffffff;
        int r0 = 0, r1 = 0;
        for (int j = 0; j < d; ++j) {
            int vj = (j < 32) ? __shfl_sync(0xffffffffu, v0, j)
                              : __shfl_sync(0xffffffffu, v1, j - 32);
            r0 += (vj < v0);
            r1 += (vj < v1);
        }
        if (lane < d)      g_col[b + r0] = g_src[v0];
        if (32 + lane < d) g_col[b + r1] = g_src[v1];
    } else {
        if (lane == 0) {
            for (int k = b + 1; k < e; ++k) {
                int v = g_col[k];
                int j = k - 1;
                while (j >= b && g_col[j] > v) { g_col[j + 1] = g_col[j]; --j; }
                g_col[j + 1] = v;
            }
            for (int k = b; k < e; ++k) g_col[k] = g_src[g_col[k]];
        }
    }
}

// ---------------- input projection: h = gelu(x @ W_in + b_in), [N,128]->[N,32]
__global__ __launch_bounds__(256) void gemm_in(
    const float* __restrict__ x, const float* __restrict__ W,
    const float* __restrict__ b, float* __restrict__ h, int n)
{
    __shared__ __align__(16) float Ws[128 * 32];
    __shared__ __align__(16) float xs[8 * 128];
    int tid = threadIdx.x;
    for (int i = tid; i < 128 * 32 / 4; i += 256)
        *reinterpret_cast<float4*>(&Ws[i * 4]) = *reinterpret_cast<const float4*>(&W[i * 4]);
    int node0 = blockIdx.x * 8;
    for (int i = tid; i < 8 * 32; i += 256) {
        int r = i >> 5;
        int row = node0 + r;
        float4 v = make_float4(0.f, 0.f, 0.f, 0.f);
        if (row < n) v = *reinterpret_cast<const float4*>(&x[(size_t)row * 128 + (i & 31) * 4]);
        *reinterpret_cast<float4*>(&xs[r * 128 + (i & 31) * 4]) = v;
    }
    __syncthreads();
    int r = tid >> 5, c = tid & 31;
    float acc = 0.f;
    const float4* xsr = reinterpret_cast<const float4*>(&xs[r * 128]);
    #pragma unroll
    for (int k4 = 0; k4 < 32; ++k4) {
        float4 xv = xsr[k4];
        acc = fmaf(xv.x, Ws[(k4 * 4 + 0) * 32 + c], acc);
        acc = fmaf(xv.y, Ws[(k4 * 4 + 1) * 32 + c], acc);
        acc = fmaf(xv.z, Ws[(k4 * 4 + 2) * 32 + c], acc);
        acc = fmaf(xv.w, Ws[(k4 * 4 + 3) * 32 + c], acc);
    }
    acc += b[c];
    float gl = 0.5f * acc * (1.f + erff(acc * 0.70710678118654752f));
    int row = node0 + r;
    if (row < n) h[(size_t)row * 32 + c] = gl;
}

// ---------------- FFMA2 GEMM: C[n,128] = A[n,K] @ W[K,128] + bias
// dol2 != 0 => L2-normalize each output row (final projection) in epilogue
__global__ __launch_bounds__(256) void gemm_ffma2(
    const float* __restrict__ A,
    const float* __restrict__ W0, const float* __restrict__ b0, float* __restrict__ C0,
    const float* __restrict__ W1, const float* __restrict__ b1, float* __restrict__ C1,
    int n, int K, int dol2)
{
    const float* W    = blockIdx.y ? W1 : W0;
    const float* bias = blockIdx.y ? b1 : b0;
    float*       C    = blockIdx.y ? C1 : C0;

    __shared__ __align__(16) float As[2][16][132];   // [k][m], padded
    __shared__ __align__(16) float Ws[2][16][128];
    int tid  = threadIdx.x;
    int row0 = blockIdx.x * 128;
    int trow = tid >> 4;   // 0..15
    int tcol = tid & 15;   // 0..15

    ull accp[4][8];
    #pragma unroll
    for (int p = 0; p < 4; ++p)
        #pragma unroll
        for (int j = 0; j < 8; ++j) accp[p][j] = 0ull;

    int chunks = K >> 4;
    float4 ra[2], rw[2];

    #pragma unroll
    for (int j = 0; j < 2; ++j) {
        int idx = tid * 2 + j;
        int r = idx >> 2, k4 = idx & 3;
        ra[j] = *reinterpret_cast<const float4*>(&A[(size_t)(row0 + r) * K + k4 * 4]);
        int k = idx >> 5, c4 = idx & 31;
        rw[j] = *reinterpret_cast<const float4*>(&W[(size_t)k * 128 + c4 * 4]);
    }
    #pragma unroll
    for (int j = 0; j < 2; ++j) {
        int idx = tid * 2 + j;
        int r = idx >> 2, k4 = idx & 3;
        As[0][k4 * 4 + 0][r] = ra[j].x;
        As[0][k4 * 4 + 1][r] = ra[j].y;
        As[0][k4 * 4 + 2][r] = ra[j].z;
        As[0][k4 * 4 + 3][r] = ra[j].w;
        int k = idx >> 5, c4 = idx & 31;
        *reinterpret_cast<float4*>(&Ws[0][k][c4 * 4]) = rw[j];
    }
    __syncthreads();

    for (int c = 0; c < chunks; ++c) {
        int buf = c & 1;
        if (c + 1 < chunks) {
            int kc = (c + 1) * 16;
            #pragma unroll
            for (int j = 0; j < 2; ++j) {
                int idx = tid * 2 + j;
                int r = idx >> 2, k4 = idx & 3;
                ra[j] = *reinterpret_cast<const float4*>(&A[(size_t)(row0 + r) * K + kc + k4 * 4]);
                int k = idx >> 5, c4 = idx & 31;
                rw[j] = *reinterpret_cast<const float4*>(&W[(size_t)(kc + k) * 128 + c4 * 4]);
            }
        }
        #pragma unroll
        for (int kk = 0; kk < 16; ++kk) {
            float4 a0 = *reinterpret_cast<const float4*>(&As[buf][kk][trow * 8]);
            float4 a1 = *reinterpret_cast<const float4*>(&As[buf][kk][trow * 8 + 4]);
            float4 q0 = *reinterpret_cast<const float4*>(&Ws[buf][kk][tcol * 8]);
            float4 q1 = *reinterpret_cast<const float4*>(&Ws[buf][kk][tcol * 8 + 4]);
            ull ap[4];
            ap[0] = pack2f(a0.x, a0.y);
            ap[1] = pack2f(a0.z, a0.w);
            ap[2] = pack2f(a1.x, a1.y);
            ap[3] = pack2f(a1.z, a1.w);
            ull bd[8];
            bd[0] = dup2f(q0.x); bd[1] = dup2f(q0.y);
            bd[2] = dup2f(q0.z); bd[3] = dup2f(q0.w);
            bd[4] = dup2f(q1.x); bd[5] = dup2f(q1.y);
            bd[6] = dup2f(q1.z); bd[7] = dup2f(q1.w);
            #pragma unroll
            for (int p = 0; p < 4; ++p)
                #pragma unroll
                for (int j = 0; j < 8; ++j)
                    ffma2(accp[p][j], ap[p], bd[j]);
        }
        if (c + 1 < chunks) {
            int nb = buf ^ 1;
            #pragma unroll
            for (int j = 0; j < 2; ++j) {
                int idx = tid * 2 + j;
                int r = idx >> 2, k4 = idx & 3;
                As[nb][k4 * 4 + 0][r] = ra[j].x;
                As[nb][k4 * 4 + 1][r] = ra[j].y;
                As[nb][k4 * 4 + 2][r] = ra[j].z;
                As[nb][k4 * 4 + 3][r] = ra[j].w;
                int k = idx >> 5, c4 = idx & 31;
                *reinterpret_cast<float4*>(&Ws[nb][k][c4 * 4]) = rw[j];
            }
        }
        __syncthreads();
    }

    float4 bb0 = *reinterpret_cast<const float4*>(&bias[tcol * 8]);
    float4 bb1 = *reinterpret_cast<const float4*>(&bias[tcol * 8 + 4]);
    float bv[8] = {bb0.x, bb0.y, bb0.z, bb0.w, bb1.x, bb1.y, bb1.z, bb1.w};
    #pragma unroll
    for (int p = 0; p < 4; ++p) {
        float lo[8], hi[8];
        #pragma unroll
        for (int j = 0; j < 8; ++j) {
            unpack2f(accp[p][j], lo[j], hi[j]);
            lo[j] += bv[j];
            hi[j] += bv[j];
        }
        if (dol2) {
            // row-wise L2 norm: the 16 threads sharing trow hold the full row
            float slo = 0.f, shi = 0.f;
            #pragma unroll
            for (int j = 0; j < 8; ++j) { slo = fmaf(lo[j], lo[j], slo); shi = fmaf(hi[j], hi[j], shi); }
            #pragma unroll
            for (int o = 1; o < 16; o <<= 1) {
                slo += __shfl_xor_sync(0xffffffffu, slo, o);
                shi += __shfl_xor_sync(0xffffffffu, shi, o);
            }
            float ilo = 1.f / fmaxf(sqrtf(slo), 1e-12f);
            float ihi = 1.f / fmaxf(sqrtf(shi), 1e-12f);
            #pragma unroll
            for (int j = 0; j < 8; ++j) { lo[j] *= ilo; hi[j] *= ihi; }
        }
        int r0 = row0 + trow * 8 + 2 * p;
        if (r0 < n) {
            float4 o0 = make_float4(lo[0], lo[1], lo[2], lo[3]);
            float4 o1 = make_float4(lo[4], lo[5], lo[6], lo[7]);
            *reinterpret_cast<float4*>(&C[(size_t)r0 * 128 + tcol * 8])     = o0;
            *reinterpret_cast<float4*>(&C[(size_t)r0 * 128 + tcol * 8 + 4]) = o1;
        }
        if (r0 + 1 < n) {
            float4 o0 = make_float4(hi[0], hi[1], hi[2], hi[3]);
            float4 o1 = make_float4(hi[4], hi[5], hi[6], hi[7]);
            *reinterpret_cast<float4*>(&C[(size_t)(r0 + 1) * 128 + tcol * 8])     = o0;
            *reinterpret_cast<float4*>(&C[(size_t)(r0 + 1) * 128 + tcol * 8 + 4]) = o1;
        }
    }
}

// ---------------- fused GATv2 aggregation + LayerNorm + GELU + residual
// ONE WARP per node; lane owns channels 4*lane..4*lane+3 (head = lane/8).
// Logit reduce: 3-step shfl within 8-lane head group. Branchless online softmax.
__global__ __launch_bounds__(128) void gat_agg(
    const float* __restrict__ att, const float* __restrict__ bo,
    const float* __restrict__ gam, const float* __restrict__ bet,
    int resflag, int n)
{
    int warp = threadIdx.x >> 5;
    int lane = threadIdx.x & 31;
    int i = blockIdx.x * 4 + warp;
    if (i >= n) return;
    int c0 = lane * 4;

    float4 xl = *reinterpret_cast<const float4*>(&g_xl[(size_t)i * 128 + c0]);
    float4 a4 = __ldg(reinterpret_cast<const float4*>(&att[c0]));

    // self loop first
    float4 xs = *reinterpret_cast<const float4*>(&g_xr[(size_t)i * 128 + c0]);
    float t0 = xl.x + xs.x; t0 = fmaxf(t0, 0.2f * t0);
    float t1 = xl.y + xs.y; t1 = fmaxf(t1, 0.2f * t1);
    float t2 = xl.z + xs.z; t2 = fmaxf(t2, 0.2f * t2);
    float t3 = xl.w + xs.w; t3 = fmaxf(t3, 0.2f * t3);
    float v = fmaf(t0, a4.x, fmaf(t1, a4.y, fmaf(t2, a4.z, t3 * a4.w)));
    v += __shfl_xor_sync(0xffffffffu, v, 1);
    v += __shfl_xor_sync(0xffffffffu, v, 2);
    v += __shfl_xor_sync(0xffffffffu, v, 4);
    float m = v, den = 1.f;
    float4 acc = xs;

    int beg = g_rowptr[i], end = g_rowptr[i + 1];
    int k = beg;
    for (; k + 2 <= end; k += 2) {
        int s0 = g_col[k];
        int s1 = g_col[k + 1];
        float4 xa = *reinterpret_cast<const float4*>(&g_xr[(size_t)s0 * 128 + c0]);
        float4 xb = *reinterpret_cast<const float4*>(&g_xr[(size_t)s1 * 128 + c0]);
        float u0 = xl.x + xa.x; u0 = fmaxf(u0, 0.2f * u0);
        float u1 = xl.y + xa.y; u1 = fmaxf(u1, 0.2f * u1);
        float u2 = xl.z + xa.z; u2 = fmaxf(u2, 0.2f * u2);
        float u3 = xl.w + xa.w; u3 = fmaxf(u3, 0.2f * u3);
        float va = fmaf(u0, a4.x, fmaf(u1, a4.y, fmaf(u2, a4.z, u3 * a4.w)));
        float w0 = xl.x + xb.x; w0 = fmaxf(w0, 0.2f * w0);
        float w1 = xl.y + xb.y; w1 = fmaxf(w1, 0.2f * w1);
        float w2 = xl.z + xb.z; w2 = fmaxf(w2, 0.2f * w2);
        float w3 = xl.w + xb.w; w3 = fmaxf(w3, 0.2f * w3);
        float vb = fmaf(w0, a4.x, fmaf(w1, a4.y, fmaf(w2, a4.z, w3 * a4.w)));
        va += __shfl_xor_sync(0xffffffffu, va, 1);
        vb += __shfl_xor_sync(0xffffffffu, vb, 1);
        va += __shfl_xor_sync(0xffffffffu, va, 2);
        vb += __shfl_xor_sync(0xffffffffu, vb, 2);
        va += __shfl_xor_sync(0xffffffffu, va, 4);
        vb += __shfl_xor_sync(0xffffffffu, vb, 4);
        // merge a (order preserved)
        {
            float nm = fmaxf(m, va);
            float sc = __expf(m - nm);
            float pe = __expf(va - nm);
            den = fmaf(den, sc, pe);
            acc.x = fmaf(acc.x, sc, pe * xa.x);
            acc.y = fmaf(acc.y, sc, pe * xa.y);
            acc.z = fmaf(acc.z, sc, pe * xa.z);
            acc.w = fmaf(acc.w, sc, pe * xa.w);
            m = nm;
        }
        // merge b
        {
            float nm = fmaxf(m, vb);
            float sc = __expf(m - nm);
            float pe = __expf(vb - nm);
            den = fmaf(den, sc, pe);
            acc.x = fmaf(acc.x, sc, pe * xb.x);
            acc.y = fmaf(acc.y, sc, pe * xb.y);
            acc.z = fmaf(acc.z, sc, pe * xb.z);
            acc.w = fmaf(acc.w, sc, pe * xb.w);
            m = nm;
        }
    }
    if (k < end) {
        int s0 = g_col[k];
        float4 xa = *reinterpret_cast<const float4*>(&g_xr[(size_t)s0 * 128 + c0]);
        float u0 = xl.x + xa.x; u0 = fmaxf(u0, 0.2f * u0);
        float u1 = xl.y + xa.y; u1 = fmaxf(u1, 0.2f * u1);
        float u2 = xl.z + xa.z; u2 = fmaxf(u2, 0.2f * u2);
        float u3 = xl.w + xa.w; u3 = fmaxf(u3, 0.2f * u3);
        float va = fmaf(u0, a4.x, fmaf(u1, a4.y, fmaf(u2, a4.z, u3 * a4.w)));
        va += __shfl_xor_sync(0xffffffffu, va, 1);
        va += __shfl_xor_sync(0xffffffffu, va, 2);
        va += __shfl_xor_sync(0xffffffffu, va, 4);
        float nm = fmaxf(m, va);
        float sc = __expf(m - nm);
        float pe = __expf(va - nm);
        den = fmaf(den, sc, pe);
        acc.x = fmaf(acc.x, sc, pe * xa.x);
        acc.y = fmaf(acc.y, sc, pe * xa.y);
        acc.z = fmaf(acc.z, sc, pe * xa.z);
        acc.w = fmaf(acc.w, sc, pe * xa.w);
        m = nm;
    }

    float inv = 1.f / (den + 1e-16f);
    float4 bo4 = __ldg(reinterpret_cast<const float4*>(&bo[c0]));
    float o0 = fmaf(acc.x, inv, bo4.x);
    float o1 = fmaf(acc.y, inv, bo4.y);
    float o2 = fmaf(acc.z, inv, bo4.z);
    float o3 = fmaf(acc.w, inv, bo4.w);

    // LayerNorm over 128 channels (warp-wide butterfly)
    float s1 = o0 + o1 + o2 + o3;
    float s2 = fmaf(o0, o0, fmaf(o1, o1, fmaf(o2, o2, o3 * o3)));
    #pragma unroll
    for (int o = 1; o < 32; o <<= 1) {
        s1 += __shfl_xor_sync(0xffffffffu, s1, o);
        s2 += __shfl_xor_sync(0xffffffffu, s2, o);
    }
    float mu  = s1 * (1.f / 128.f);
    float var = s2 * (1.f / 128.f) - mu * mu;
    var = var > 0.f ? var : 0.f;
    float rstd = rsqrtf(var + 1e-5f);
    float4 g4 = __ldg(reinterpret_cast<const float4*>(&gam[c0]));
    float4 b4 = __ldg(reinterpret_cast<const float4*>(&bet[c0]));
    float y0 = g4.x * (o0 - mu) * rstd + b4.x;
    float y1 = g4.y * (o1 - mu) * rstd + b4.y;
    float y2 = g4.z * (o2 - mu) * rstd + b4.z;
    float y3 = g4.w * (o3 - mu) * rstd + b4.w;
    const float is2 = 0.70710678118654752f;
    float gl0 = 0.5f * y0 * (1.f + erff(y0 * is2));
    float gl1 = 0.5f * y1 * (1.f + erff(y1 * is2));
    float gl2 = 0.5f * y2 * (1.f + erff(y2 * is2));
    float gl3 = 0.5f * y3 * (1.f + erff(y3 * is2));

    float4* hp = reinterpret_cast<float4*>(&g_h[(size_t)i * 128 + c0]);
    if (resflag) {
        float4 hv = *hp;
        hv.x += gl0; hv.y += gl1; hv.z += gl2; hv.w += gl3;
        *hp = hv;
    } else {
        *hp = make_float4(gl0, gl1, gl2, gl3);
    }
}

// ---------------- host launcher ----------------
extern "C" void kernel_launch(void* const* d_in, const int* in_sizes, int n_in,
                              void* d_out, int out_size)
{
    const float* x    = (const float*)d_in[0];
    const void*  ei   = d_in[1];
    const float* W_in = (const float*)d_in[2];
    const float* b_in = (const float*)d_in[3];
    const float *Wl[3], *bl[3], *Wr[3], *br[3], *att[3], *bo[3], *gg[3], *be[3];
    for (int l = 0; l < 3; ++l) {
        int base = 4 + l * 8;
        Wl[l]  = (const float*)d_in[base + 0];
        bl[l]  = (const float*)d_in[base + 1];
        Wr[l]  = (const float*)d_in[base + 2];
        br[l]  = (const float*)d_in[base + 3];
        att[l] = (const float*)d_in[base + 4];
        bo[l]  = (const float*)d_in[base + 5];
        gg[l]  = (const float*)d_in[base + 6];
        be[l]  = (const float*)d_in[base + 7];
    }
    const float* W_out = (const float*)d_in[28];
    const float* b_out = (const float*)d_in[29];

    int n = in_sizes[0] / 128;
    int e = in_sizes[1] / 2;

    float *hbuf, *xlbuf, *xrbuf;
    cudaGetSymbolAddress((void**)&hbuf,  g_h);
    cudaGetSymbolAddress((void**)&xlbuf, g_xl);
    cudaGetSymbolAddress((void**)&xrbuf, g_xr);

    dim3 gdual((n + 127) / 128, 2);
    dim3 gsingle((n + 127) / 128, 1);
    int aggblocks = (n + 3) / 4;

    // CSR build (scatter_edges is launch index 3 -> profiled)
    zero_detect<<<(n + 255) / 256, 256>>>(ei, e, n);
    convert_hist<<<(e + 255) / 256, 256>>>(ei, e);
    scan_all<<<1, 1024>>>(n);
    scatter_edges<<<(e + 255) / 256, 256>>>(e);
    sort_warp<<<(n + 7) / 8, 256>>>(n);

    // input projection
    gemm_in<<<(n + 7) / 8, 256>>>(x, W_in, b_in, hbuf, n);

    int ic = 32;
    for (int l = 0; l < 3; ++l) {
        gemm_ffma2<<<gdual, 256>>>(hbuf, Wl[l], bl[l], xlbuf,
                                   Wr[l], br[l], xrbuf, n, ic, 0);
        gat_agg<<<aggblocks, 128>>>(att[l], bo[l], gg[l], be[l], (l > 0) ? 1 : 0, n);
        ic = 128;
    }

    gemm_ffma2<<<gsingle, 256>>>(hbuf, W_out, b_out, (float*)d_out,
                                 W_out, b_out, (float*)d_out, n, 128, 1);
}

// round 5
// speedup vs baseline: 1.5970x; 1.0053x over previous
#include <cuda_runtime.h>
#include <math.h>

typedef unsigned long long ull;

#define NMAX 50048
#define EMAX 1000000

// ---------------- scratch (no allocations allowed) ----------------
__device__ int   g_src[EMAX];
__device__ int   g_dst[EMAX];
__device__ int   g_col[EMAX];
__device__ int   g_rowptr[NMAX + 1];
__device__ int   g_deg[NMAX];
__device__ int   g_cur[NMAX];
__device__ int   g_flag;   // 1 => edge_index is int32, 0 => int64
__device__ float g_h [(size_t)NMAX * 128];
__device__ float g_xl[(size_t)NMAX * 128];
__device__ float g_xr[(size_t)NMAX * 128];

// ---------------- f32x2 packed-FMA helpers (sm_103a FFMA2) ----------------
__device__ __forceinline__ ull pack2f(float x, float y) {
    ull r; asm("mov.b64 %0, {%1,%2};" : "=l"(r) : "f"(x), "f"(y)); return r;
}
__device__ __forceinline__ ull dup2f(float x) {
    ull r; asm("mov.b64 %0, {%1,%1};" : "=l"(r) : "f"(x)); return r;
}
__device__ __forceinline__ void ffma2(ull& d, ull a, ull b) {
    asm("fma.rn.f32x2 %0, %1, %2, %0;" : "+l"(d) : "l"(a), "l"(b));
}
__device__ __forceinline__ void unpack2f(ull v, float& lo, float& hi) {
    asm("mov.b64 {%0,%1}, %2;" : "=f"(lo), "=f"(hi) : "l"(v));
}

// ---------------- zero counters + edge dtype detection ----------------
__global__ void zero_detect(const void* ei, int e, int n) {
    int i = blockIdx.x * blockDim.x + threadIdx.x;
    if (i < n) { g_deg[i] = 0; g_cur[i] = 0; }
    if (blockIdx.x == 0) {
        __shared__ int any;
        if (threadIdx.x == 0) any = 0;
        __syncthreads();
        const int* w = (const int*)ei;
        int lim = 2048 < e ? 2048 : e;
        for (int k = threadIdx.x; k < lim; k += 256)
            if (w[2 * k + 1] != 0) any = 1;
        __syncthreads();
        if (threadIdx.x == 0) g_flag = any;
    }
}

// convert + degree histogram fused
__global__ void convert_hist(const void* ei, int e) {
    int i = blockIdx.x * blockDim.x + threadIdx.x;
    if (i >= e) return;
    int s, d;
    if (g_flag == 0) {
        const long long* p = (const long long*)ei;
        s = (int)p[i]; d = (int)p[e + i];
    } else {
        const int* p = (const int*)ei;
        s = p[i]; d = p[e + i];
    }
    g_src[i] = s;
    g_dst[i] = d;
    atomicAdd(&g_deg[d], 1);
}

// ---------------- single-block exclusive scan of g_deg -> g_rowptr -------
__global__ __launch_bounds__(1024) void scan_all(int n) {
    __shared__ int ws[32];
    int t = threadIdx.x;
    int lane = t & 31, w = t >> 5;
    int C = (n + 1023) >> 10;
    int b0 = t * C;
    int b1 = b0 + C; if (b1 > n) b1 = n; if (b0 > n) b0 = n;
    int s = 0;
    for (int i = b0; i < b1; ++i) s += g_deg[i];
    int incl = s;
    #pragma unroll
    for (int o = 1; o < 32; o <<= 1) {
        int u = __shfl_up_sync(0xffffffffu, incl, o);
        if (lane >= o) incl += u;
    }
    if (lane == 31) ws[w] = incl;
    __syncthreads();
    if (w == 0) {
        int v = ws[lane];
        int inc2 = v;
        #pragma unroll
        for (int o = 1; o < 32; o <<= 1) {
            int u = __shfl_up_sync(0xffffffffu, inc2, o);
            if (lane >= o) inc2 += u;
        }
        ws[lane] = inc2;
    }
    __syncthreads();
    int off = (w > 0 ? ws[w - 1] : 0) + (incl - s);
    int run = off;
    for (int i = b0; i < b1; ++i) { g_rowptr[i] = run; run += g_deg[i]; }
    if (t == 1023) g_rowptr[n] = off + s;
}

__global__ void scatter_edges(int e) {
    int i = blockIdx.x * blockDim.x + threadIdx.x;
    if (i >= e) return;
    int d = g_dst[i];
    int pos = g_rowptr[d] + atomicAdd(&g_cur[d], 1);
    g_col[pos] = i;   // edge id, for deterministic ordering
}

// warp-per-node rank sort of edge ids (unique), then map to src
__global__ __launch_bounds__(256) void sort_warp(int n) {
    int gw = (blockIdx.x * blockDim.x + threadIdx.x) >> 5;
    int lane = threadIdx.x & 31;
    if (gw >= n) return;
    int b = g_rowptr[gw], e = g_rowptr[gw + 1];
    int d = e - b;
    if (d <= 1) {
        if (d == 1 && lane == 0) g_col[b] = g_src[g_col[b]];
        return;
    }
    if (d <= 32) {
        int val = (lane < d) ? g_col[b + lane] : 0x7fffffff;
        int rank = 0;
        for (int j = 0; j < d; ++j) {
            int vj = __shfl_sync(0xffffffffu, val, j);
            rank += (vj < val);
        }
        if (lane < d) g_col[b + rank] = g_src[val];
    } else if (d <= 64) {
        int v0 = (lane < d)      ? g_col[b + lane]      : 0x7fffffff;
        int v1 = (32 + lane < d) ? g_col[b + 32 + lane] : 0x7fffffff;
        int r0 = 0, r1 = 0;
        for (int j = 0; j < d; ++j) {
            int vj = (j < 32) ? __shfl_sync(0xffffffffu, v0, j)
                              : __shfl_sync(0xffffffffu, v1, j - 32);
            r0 += (vj < v0);
            r1 += (vj < v1);
        }
        if (lane < d)      g_col[b + r0] = g_src[v0];
        if (32 + lane < d) g_col[b + r1] = g_src[v1];
    } else {
        if (lane == 0) {
            for (int k = b + 1; k < e; ++k) {
                int v = g_col[k];
                int j = k - 1;
                while (j >= b && g_col[j] > v) { g_col[j + 1] = g_col[j]; --j; }
                g_col[j + 1] = v;
            }
            for (int k = b; k < e; ++k) g_col[k] = g_src[g_col[k]];
        }
    }
}

// ---------------- input projection: h = gelu(x @ W_in + b_in), [N,128]->[N,32]
__global__ __launch_bounds__(256) void gemm_in(
    const float* __restrict__ x, const float* __restrict__ W,
    const float* __restrict__ b, float* __restrict__ h, int n)
{
    __shared__ __align__(16) float Ws[128 * 32];
    __shared__ __align__(16) float xs[8 * 128];
    int tid = threadIdx.x;
    for (int i = tid; i < 128 * 32 / 4; i += 256)
        *reinterpret_cast<float4*>(&Ws[i * 4]) = *reinterpret_cast<const float4*>(&W[i * 4]);
    int node0 = blockIdx.x * 8;
    for (int i = tid; i < 8 * 32; i += 256) {
        int r = i >> 5;
        int row = node0 + r;
        float4 v = make_float4(0.f, 0.f, 0.f, 0.f);
        if (row < n) v = *reinterpret_cast<const float4*>(&x[(size_t)row * 128 + (i & 31) * 4]);
        *reinterpret_cast<float4*>(&xs[r * 128 + (i & 31) * 4]) = v;
    }
    __syncthreads();
    int r = tid >> 5, c = tid & 31;
    float acc = 0.f;
    const float4* xsr = reinterpret_cast<const float4*>(&xs[r * 128]);
    #pragma unroll
    for (int k4 = 0; k4 < 32; ++k4) {
        float4 xv = xsr[k4];
        acc = fmaf(xv.x, Ws[(k4 * 4 + 0) * 32 + c], acc);
        acc = fmaf(xv.y, Ws[(k4 * 4 + 1) * 32 + c], acc);
        acc = fmaf(xv.z, Ws[(k4 * 4 + 2) * 32 + c], acc);
        acc = fmaf(xv.w, Ws[(k4 * 4 + 3) * 32 + c], acc);
    }
    acc += b[c];
    float gl = 0.5f * acc * (1.f + erff(acc * 0.70710678118654752f));
    int row = node0 + r;
    if (row < n) h[(size_t)row * 32 + c] = gl;
}

// ---------------- FFMA2 GEMM: C[n,128] = A[n,K] @ W[K,128] + bias
// dol2 != 0 => L2-normalize each output row (final projection) in epilogue
__global__ __launch_bounds__(256) void gemm_ffma2(
    const float* __restrict__ A,
    const float* __restrict__ W0, const float* __restrict__ b0, float* __restrict__ C0,
    const float* __restrict__ W1, const float* __restrict__ b1, float* __restrict__ C1,
    int n, int K, int dol2)
{
    const float* W    = blockIdx.y ? W1 : W0;
    const float* bias = blockIdx.y ? b1 : b0;
    float*       C    = blockIdx.y ? C1 : C0;

    __shared__ __align__(16) float As[2][16][132];   // [k][m], padded
    __shared__ __align__(16) float Ws[2][16][128];
    int tid  = threadIdx.x;
    int row0 = blockIdx.x * 128;
    int trow = tid >> 4;   // 0..15
    int tcol = tid & 15;   // 0..15

    ull accp[4][8];
    #pragma unroll
    for (int p = 0; p < 4; ++p)
        #pragma unroll
        for (int j = 0; j < 8; ++j) accp[p][j] = 0ull;

    int chunks = K >> 4;
    float4 ra[2], rw[2];

    #pragma unroll
    for (int j = 0; j < 2; ++j) {
        int idx = tid * 2 + j;
        int r = idx >> 2, k4 = idx & 3;
        ra[j] = *reinterpret_cast<const float4*>(&A[(size_t)(row0 + r) * K + k4 * 4]);
        int k = idx >> 5, c4 = idx & 31;
        rw[j] = *reinterpret_cast<const float4*>(&W[(size_t)k * 128 + c4 * 4]);
    }
    #pragma unroll
    for (int j = 0; j < 2; ++j) {
        int idx = tid * 2 + j;
        int r = idx >> 2, k4 = idx & 3;
        As[0][k4 * 4 + 0][r] = ra[j].x;
        As[0][k4 * 4 + 1][r] = ra[j].y;
        As[0][k4 * 4 + 2][r] = ra[j].z;
        As[0][k4 * 4 + 3][r] = ra[j].w;
        int k = idx >> 5, c4 = idx & 31;
        *reinterpret_cast<float4*>(&Ws[0][k][c4 * 4]) = rw[j];
    }
    __syncthreads();

    for (int c = 0; c < chunks; ++c) {
        int buf = c & 1;
        if (c + 1 < chunks) {
            int kc = (c + 1) * 16;
            #pragma unroll
            for (int j = 0; j < 2; ++j) {
                int idx = tid * 2 + j;
                int r = idx >> 2, k4 = idx & 3;
                ra[j] = *reinterpret_cast<const float4*>(&A[(size_t)(row0 + r) * K + kc + k4 * 4]);
                int k = idx >> 5, c4 = idx & 31;
                rw[j] = *reinterpret_cast<const float4*>(&W[(size_t)(kc + k) * 128 + c4 * 4]);
            }
        }
        #pragma unroll
        for (int kk = 0; kk < 16; ++kk) {
            float4 a0 = *reinterpret_cast<const float4*>(&As[buf][kk][trow * 8]);
            float4 a1 = *reinterpret_cast<const float4*>(&As[buf][kk][trow * 8 + 4]);
            float4 q0 = *reinterpret_cast<const float4*>(&Ws[buf][kk][tcol * 8]);
            float4 q1 = *reinterpret_cast<const float4*>(&Ws[buf][kk][tcol * 8 + 4]);
            ull ap[4];
            ap[0] = pack2f(a0.x, a0.y);
            ap[1] = pack2f(a0.z, a0.w);
            ap[2] = pack2f(a1.x, a1.y);
            ap[3] = pack2f(a1.z, a1.w);
            ull bd[8];
            bd[0] = dup2f(q0.x); bd[1] = dup2f(q0.y);
            bd[2] = dup2f(q0.z); bd[3] = dup2f(q0.w);
            bd[4] = dup2f(q1.x); bd[5] = dup2f(q1.y);
            bd[6] = dup2f(q1.z); bd[7] = dup2f(q1.w);
            #pragma unroll
            for (int p = 0; p < 4; ++p)
                #pragma unroll
                for (int j = 0; j < 8; ++j)
                    ffma2(accp[p][j], ap[p], bd[j]);
        }
        if (c + 1 < chunks) {
            int nb = buf ^ 1;
            #pragma unroll
            for (int j = 0; j < 2; ++j) {
                int idx = tid * 2 + j;
                int r = idx >> 2, k4 = idx & 3;
                As[nb][k4 * 4 + 0][r] = ra[j].x;
                As[nb][k4 * 4 + 1][r] = ra[j].y;
                As[nb][k4 * 4 + 2][r] = ra[j].z;
                As[nb][k4 * 4 + 3][r] = ra[j].w;
                int k = idx >> 5, c4 = idx & 31;
                *reinterpret_cast<float4*>(&Ws[nb][k][c4 * 4]) = rw[j];
            }
        }
        __syncthreads();
    }

    float4 bb0 = *reinterpret_cast<const float4*>(&bias[tcol * 8]);
    float4 bb1 = *reinterpret_cast<const float4*>(&bias[tcol * 8 + 4]);
    float bv[8] = {bb0.x, bb0.y, bb0.z, bb0.w, bb1.x, bb1.y, bb1.z, bb1.w};
    #pragma unroll
    for (int p = 0; p < 4; ++p) {
        float lo[8], hi[8];
        #pragma unroll
        for (int j = 0; j < 8; ++j) {
            unpack2f(accp[p][j], lo[j], hi[j]);
            lo[j] += bv[j];
            hi[j] += bv[j];
        }
        if (dol2) {
            float slo = 0.f, shi = 0.f;
            #pragma unroll
            for (int j = 0; j < 8; ++j) { slo = fmaf(lo[j], lo[j], slo); shi = fmaf(hi[j], hi[j], shi); }
            #pragma unroll
            for (int o = 1; o < 16; o <<= 1) {
                slo += __shfl_xor_sync(0xffffffffu, slo, o);
                shi += __shfl_xor_sync(0xffffffffu, shi, o);
            }
            float ilo = 1.f / fmaxf(sqrtf(slo), 1e-12f);
            float ihi = 1.f / fmaxf(sqrtf(shi), 1e-12f);
            #pragma unroll
            for (int j = 0; j < 8; ++j) { lo[j] *= ilo; hi[j] *= ihi; }
        }
        int r0 = row0 + trow * 8 + 2 * p;
        if (r0 < n) {
            float4 o0 = make_float4(lo[0], lo[1], lo[2], lo[3]);
            float4 o1 = make_float4(lo[4], lo[5], lo[6], lo[7]);
            *reinterpret_cast<float4*>(&C[(size_t)r0 * 128 + tcol * 8])     = o0;
            *reinterpret_cast<float4*>(&C[(size_t)r0 * 128 + tcol * 8 + 4]) = o1;
        }
        if (r0 + 1 < n) {
            float4 o0 = make_float4(hi[0], hi[1], hi[2], hi[3]);
            float4 o1 = make_float4(hi[4], hi[5], hi[6], hi[7]);
            *reinterpret_cast<float4*>(&C[(size_t)(r0 + 1) * 128 + tcol * 8])     = o0;
            *reinterpret_cast<float4*>(&C[(size_t)(r0 + 1) * 128 + tcol * 8 + 4]) = o1;
        }
    }
}

// ---------------- fused GATv2 aggregation + LayerNorm + GELU + residual
// ONE WARP per node; lane owns channels 4*lane..4*lane+3 (head = lane/8).
// 4-edge unroll with merge tree: MLP=4 gathers, 12 pipelined shfls, leaf-pair
// merges in parallel, only 2 sequential running merges per 4 edges.
__global__ __launch_bounds__(128) void gat_agg(
    const float* __restrict__ att, const float* __restrict__ bo,
    const float* __restrict__ gam, const float* __restrict__ bet,
    int resflag, int n)
{
    int warp = threadIdx.x >> 5;
    int lane = threadIdx.x & 31;
    int i = blockIdx.x * 4 + warp;
    if (i >= n) return;
    int c0 = lane * 4;

    float4 xl = *reinterpret_cast<const float4*>(&g_xl[(size_t)i * 128 + c0]);
    float4 a4 = __ldg(reinterpret_cast<const float4*>(&att[c0]));

    // self loop first
    float4 xs = *reinterpret_cast<const float4*>(&g_xr[(size_t)i * 128 + c0]);
    float t0 = xl.x + xs.x; t0 = fmaxf(t0, 0.2f * t0);
    float t1 = xl.y + xs.y; t1 = fmaxf(t1, 0.2f * t1);
    float t2 = xl.z + xs.z; t2 = fmaxf(t2, 0.2f * t2);
    float t3 = xl.w + xs.w; t3 = fmaxf(t3, 0.2f * t3);
    float v = fmaf(t0, a4.x, fmaf(t1, a4.y, fmaf(t2, a4.z, t3 * a4.w)));
    v += __shfl_xor_sync(0xffffffffu, v, 1);
    v += __shfl_xor_sync(0xffffffffu, v, 2);
    v += __shfl_xor_sync(0xffffffffu, v, 4);
    float m = v, den = 1.f;
    float4 acc = xs;

#define GAT_LOGIT(vv, xv)                                                    \
    {                                                                        \
        float u0 = xl.x + xv.x; u0 = fmaxf(u0, 0.2f * u0);                   \
        float u1 = xl.y + xv.y; u1 = fmaxf(u1, 0.2f * u1);                   \
        float u2 = xl.z + xv.z; u2 = fmaxf(u2, 0.2f * u2);                   \
        float u3 = xl.w + xv.w; u3 = fmaxf(u3, 0.2f * u3);                   \
        vv = fmaf(u0, a4.x, fmaf(u1, a4.y, fmaf(u2, a4.z, u3 * a4.w)));      \
    }

#define GAT_RUNMERGE(vv, xv)                                                 \
    {                                                                        \
        float nm = fmaxf(m, vv);                                             \
        float sc = __expf(m - nm);                                           \
        float pe = __expf(vv - nm);                                          \
        den = fmaf(den, sc, pe);                                             \
        acc.x = fmaf(acc.x, sc, pe * xv.x);                                  \
        acc.y = fmaf(acc.y, sc, pe * xv.y);                                  \
        acc.z = fmaf(acc.z, sc, pe * xv.z);                                  \
        acc.w = fmaf(acc.w, sc, pe * xv.w);                                  \
        m = nm;                                                              \
    }

    int beg = g_rowptr[i], end = g_rowptr[i + 1];
    int k = beg;
    for (; k + 4 <= end; k += 4) {
        int s0 = g_col[k];
        int s1 = g_col[k + 1];
        int s2 = g_col[k + 2];
        int s3 = g_col[k + 3];
        float4 xa = *reinterpret_cast<const float4*>(&g_xr[(size_t)s0 * 128 + c0]);
        float4 xb = *reinterpret_cast<const float4*>(&g_xr[(size_t)s1 * 128 + c0]);
        float4 xc = *reinterpret_cast<const float4*>(&g_xr[(size_t)s2 * 128 + c0]);
        float4 xd = *reinterpret_cast<const float4*>(&g_xr[(size_t)s3 * 128 + c0]);
        float va, vb, vc, vd;
        GAT_LOGIT(va, xa);
        GAT_LOGIT(vb, xb);
        GAT_LOGIT(vc, xc);
        GAT_LOGIT(vd, xd);
        va += __shfl_xor_sync(0xffffffffu, va, 1);
        vb += __shfl_xor_sync(0xffffffffu, vb, 1);
        vc += __shfl_xor_sync(0xffffffffu, vc, 1);
        vd += __shfl_xor_sync(0xffffffffu, vd, 1);
        va += __shfl_xor_sync(0xffffffffu, va, 2);
        vb += __shfl_xor_sync(0xffffffffu, vb, 2);
        vc += __shfl_xor_sync(0xffffffffu, vc, 2);
        vd += __shfl_xor_sync(0xffffffffu, vd, 2);
        va += __shfl_xor_sync(0xffffffffu, va, 4);
        vb += __shfl_xor_sync(0xffffffffu, vb, 4);
        vc += __shfl_xor_sync(0xffffffffu, vc, 4);
        vd += __shfl_xor_sync(0xffffffffu, vd, 4);

        // leaf pair (a,b)
        float mab = fmaxf(va, vb);
        float pa  = __expf(va - mab);
        float pb  = __expf(vb - mab);
        float dab = pa + pb;
        float4 aab;
        aab.x = fmaf(pa, xa.x, pb * xb.x);
        aab.y = fmaf(pa, xa.y, pb * xb.y);
        aab.z = fmaf(pa, xa.z, pb * xb.z);
        aab.w = fmaf(pa, xa.w, pb * xb.w);
        // leaf pair (c,d)
        float mcd = fmaxf(vc, vd);
        float pc  = __expf(vc - mcd);
        float pd  = __expf(vd - mcd);
        float dcd = pc + pd;
        float4 acd;
        acd.x = fmaf(pc, xc.x, pd * xd.x);
        acd.y = fmaf(pc, xc.y, pd * xd.y);
        acd.z = fmaf(pc, xc.z, pd * xd.z);
        acd.w = fmaf(pc, xc.w, pd * xd.w);

        // running merge with (ab)
        {
            float nm = fmaxf(m, mab);
            float sc = __expf(m - nm);
            float s2 = __expf(mab - nm);
            den = fmaf(den, sc, dab * s2);
            acc.x = fmaf(acc.x, sc, aab.x * s2);
            acc.y = fmaf(acc.y, sc, aab.y * s2);
            acc.z = fmaf(acc.z, sc, aab.z * s2);
            acc.w = fmaf(acc.w, sc, aab.w * s2);
            m = nm;
        }
        // running merge with (cd)
        {
            float nm = fmaxf(m, mcd);
            float sc = __expf(m - nm);
            float s2 = __expf(mcd - nm);
            den = fmaf(den, sc, dcd * s2);
            acc.x = fmaf(acc.x, sc, acd.x * s2);
            acc.y = fmaf(acc.y, sc, acd.y * s2);
            acc.z = fmaf(acc.z, sc, acd.z * s2);
            acc.w = fmaf(acc.w, sc, acd.w * s2);
            m = nm;
        }
    }
    if (k + 2 <= end) {
        int s0 = g_col[k];
        int s1 = g_col[k + 1];
        float4 xa = *reinterpret_cast<const float4*>(&g_xr[(size_t)s0 * 128 + c0]);
        float4 xb = *reinterpret_cast<const float4*>(&g_xr[(size_t)s1 * 128 + c0]);
        float va, vb;
        GAT_LOGIT(va, xa);
        GAT_LOGIT(vb, xb);
        va += __shfl_xor_sync(0xffffffffu, va, 1);
        vb += __shfl_xor_sync(0xffffffffu, vb, 1);
        va += __shfl_xor_sync(0xffffffffu, va, 2);
        vb += __shfl_xor_sync(0xffffffffu, vb, 2);
        va += __shfl_xor_sync(0xffffffffu, va, 4);
        vb += __shfl_xor_sync(0xffffffffu, vb, 4);
        GAT_RUNMERGE(va, xa);
        GAT_RUNMERGE(vb, xb);
        k += 2;
    }
    if (k < end) {
        int s0 = g_col[k];
        float4 xa = *reinterpret_cast<const float4*>(&g_xr[(size_t)s0 * 128 + c0]);
        float va;
        GAT_LOGIT(va, xa);
        va += __shfl_xor_sync(0xffffffffu, va, 1);
        va += __shfl_xor_sync(0xffffffffu, va, 2);
        va += __shfl_xor_sync(0xffffffffu, va, 4);
        GAT_RUNMERGE(va, xa);
    }
#undef GAT_LOGIT
#undef GAT_RUNMERGE

    float inv = 1.f / (den + 1e-16f);
    float4 bo4 = __ldg(reinterpret_cast<const float4*>(&bo[c0]));
    float o0 = fmaf(acc.x, inv, bo4.x);
    float o1 = fmaf(acc.y, inv, bo4.y);
    float o2 = fmaf(acc.z, inv, bo4.z);
    float o3 = fmaf(acc.w, inv, bo4.w);

    // LayerNorm over 128 channels (warp-wide butterfly)
    float s1 = o0 + o1 + o2 + o3;
    float s2 = fmaf(o0, o0, fmaf(o1, o1, fmaf(o2, o2, o3 * o3)));
    #pragma unroll
    for (int o = 1; o < 32; o <<= 1) {
        s1 += __shfl_xor_sync(0xffffffffu, s1, o);
        s2 += __shfl_xor_sync(0xffffffffu, s2, o);
    }
    float mu  = s1 * (1.f / 128.f);
    float var = s2 * (1.f / 128.f) - mu * mu;
    var = var > 0.f ? var : 0.f;
    float rstd = rsqrtf(var + 1e-5f);
    float4 g4 = __ldg(reinterpret_cast<const float4*>(&gam[c0]));
    float4 b4 = __ldg(reinterpret_cast<const float4*>(&bet[c0]));
    float y0 = g4.x * (o0 - mu) * rstd + b4.x;
    float y1 = g4.y * (o1 - mu) * rstd + b4.y;
    float y2 = g4.z * (o2 - mu) * rstd + b4.z;
    float y3 = g4.w * (o3 - mu) * rstd + b4.w;
    const float is2 = 0.70710678118654752f;
    float gl0 = 0.5f * y0 * (1.f + erff(y0 * is2));
    float gl1 = 0.5f * y1 * (1.f + erff(y1 * is2));
    float gl2 = 0.5f * y2 * (1.f + erff(y2 * is2));
    float gl3 = 0.5f * y3 * (1.f + erff(y3 * is2));

    float4* hp = reinterpret_cast<float4*>(&g_h[(size_t)i * 128 + c0]);
    if (resflag) {
        float4 hv = *hp;
        hv.x += gl0; hv.y += gl1; hv.z += gl2; hv.w += gl3;
        *hp = hv;
    } else {
        *hp = make_float4(gl0, gl1, gl2, gl3);
    }
}

// ---------------- host launcher ----------------
extern "C" void kernel_launch(void* const* d_in, const int* in_sizes, int n_in,
                              void* d_out, int out_size)
{
    const float* x    = (const float*)d_in[0];
    const void*  ei   = d_in[1];
    const float* W_in = (const float*)d_in[2];
    const float* b_in = (const float*)d_in[3];
    const float *Wl[3], *bl[3], *Wr[3], *br[3], *att[3], *bo[3], *gg[3], *be[3];
    for (int l = 0; l < 3; ++l) {
        int base = 4 + l * 8;
        Wl[l]  = (const float*)d_in[base + 0];
        bl[l]  = (const float*)d_in[base + 1];
        Wr[l]  = (const float*)d_in[base + 2];
        br[l]  = (const float*)d_in[base + 3];
        att[l] = (const float*)d_in[base + 4];
        bo[l]  = (const float*)d_in[base + 5];
        gg[l]  = (const float*)d_in[base + 6];
        be[l]  = (const float*)d_in[base + 7];
    }
    const float* W_out = (const float*)d_in[28];
    const float* b_out = (const float*)d_in[29];

    int n = in_sizes[0] / 128;
    int e = in_sizes[1] / 2;

    float *hbuf, *xlbuf, *xrbuf;
    cudaGetSymbolAddress((void**)&hbuf,  g_h);
    cudaGetSymbolAddress((void**)&xlbuf, g_xl);
    cudaGetSymbolAddress((void**)&xrbuf, g_xr);

    dim3 gdual((n + 127) / 128, 2);
    dim3 gsingle((n + 127) / 128, 1);
    int aggblocks = (n + 3) / 4;

    // index 3 = scan_all (profiled this round)
    gemm_in<<<(n + 7) / 8, 256>>>(x, W_in, b_in, hbuf, n);
    zero_detect<<<(n + 255) / 256, 256>>>(ei, e, n);
    convert_hist<<<(e + 255) / 256, 256>>>(ei, e);
    scan_all<<<1, 1024>>>(n);
    scatter_edges<<<(e + 255) / 256, 256>>>(e);
    sort_warp<<<(n + 7) / 8, 256>>>(n);

    int ic = 32;
    for (int l = 0; l < 3; ++l) {
        gemm_ffma2<<<gdual, 256>>>(hbuf, Wl[l], bl[l], xlbuf,
                                   Wr[l], br[l], xrbuf, n, ic, 0);
        gat_agg<<<aggblocks, 128>>>(att[l], bo[l], gg[l], be[l], (l > 0) ? 1 : 0, n);
        ic = 128;
    }

    gemm_ffma2<<<gsingle, 256>>>(hbuf, W_out, b_out, (float*)d_out,
                                 W_out, b_out, (float*)d_out, n, 128, 1);
}

// round 6
// speedup vs baseline: 1.6723x; 1.0472x over previous
#include <cuda_runtime.h>
#include <math.h>

typedef unsigned long long ull;

#define NMAX 50048
#define EMAX 1000000

// ---------------- scratch (no allocations allowed) ----------------
__device__ int   g_src[EMAX];
__device__ int   g_dst[EMAX];
__device__ int   g_col[EMAX];
__device__ int   g_rowptr[NMAX + 1];
__device__ int   g_deg[NMAX];
__device__ int   g_cur[NMAX];
__device__ int   g_part[64];
__device__ int   g_partoff[64];
__device__ int   g_flag;   // 1 => edge_index is int32, 0 => int64
__device__ float g_h [(size_t)NMAX * 128];
__device__ float g_xl[(size_t)NMAX * 128];
__device__ float g_xr[(size_t)NMAX * 128];

// ---------------- f32x2 packed-FMA helpers (sm_103a FFMA2) ----------------
__device__ __forceinline__ ull pack2f(float x, float y) {
    ull r; asm("mov.b64 %0, {%1,%2};" : "=l"(r) : "f"(x), "f"(y)); return r;
}
__device__ __forceinline__ ull dup2f(float x) {
    ull r; asm("mov.b64 %0, {%1,%1};" : "=l"(r) : "f"(x)); return r;
}
__device__ __forceinline__ void ffma2(ull& d, ull a, ull b) {
    asm("fma.rn.f32x2 %0, %1, %2, %0;" : "+l"(d) : "l"(a), "l"(b));
}
__device__ __forceinline__ void unpack2f(ull v, float& lo, float& hi) {
    asm("mov.b64 {%0,%1}, %2;" : "=f"(lo), "=f"(hi) : "l"(v));
}

// ---------------- zero counters + edge dtype detection ----------------
__global__ void zero_detect(const void* ei, int e, int n) {
    int i = blockIdx.x * blockDim.x + threadIdx.x;
    if (i < n) { g_deg[i] = 0; g_cur[i] = 0; }
    if (blockIdx.x == 0) {
        __shared__ int any;
        if (threadIdx.x == 0) any = 0;
        __syncthreads();
        const int* w = (const int*)ei;
        int lim = 2048 < e ? 2048 : e;
        for (int k = threadIdx.x; k < lim; k += 256)
            if (w[2 * k + 1] != 0) any = 1;
        __syncthreads();
        if (threadIdx.x == 0) g_flag = any;
    }
}

// convert + degree histogram fused
__global__ void convert_hist(const void* ei, int e) {
    int i = blockIdx.x * blockDim.x + threadIdx.x;
    if (i >= e) return;
    int s, d;
    if (g_flag == 0) {
        const long long* p = (const long long*)ei;
        s = (int)p[i]; d = (int)p[e + i];
    } else {
        const int* p = (const int*)ei;
        s = p[i]; d = p[e + i];
    }
    g_src[i] = s;
    g_dst[i] = d;
    atomicAdd(&g_deg[d], 1);
}

// ---------------- multi-block exclusive scan of g_deg -> g_rowptr --------
__global__ __launch_bounds__(256) void scan_part(int n) {
    __shared__ int wsum[8];
    int b = blockIdx.x, t = threadIdx.x;
    int base = b * 1024 + t * 4;
    int s = 0;
    #pragma unroll
    for (int j = 0; j < 4; ++j) s += (base + j < n) ? g_deg[base + j] : 0;
    #pragma unroll
    for (int o = 16; o; o >>= 1) s += __shfl_xor_sync(0xffffffffu, s, o);
    if ((t & 31) == 0) wsum[t >> 5] = s;
    __syncthreads();
    if (t == 0) {
        int tot = 0;
        #pragma unroll
        for (int w = 0; w < 8; ++w) tot += wsum[w];
        g_part[b] = tot;
    }
}

__global__ void scan_top(int P, int n) {
    __shared__ int sp[64];
    int t = threadIdx.x;
    if (t < P) sp[t] = g_part[t];
    __syncthreads();
    if (t == 0) {
        int run = 0;
        for (int b = 0; b < P; ++b) { g_partoff[b] = run; run += sp[b]; }
        g_rowptr[n] = run;
    }
}

__global__ __launch_bounds__(256) void scan_down(int n) {
    __shared__ int wsum[8];
    int b = blockIdx.x, t = threadIdx.x;
    int base = b * 1024 + t * 4;
    int v[4];
    #pragma unroll
    for (int j = 0; j < 4; ++j) v[j] = (base + j < n) ? g_deg[base + j] : 0;
    int s = v[0] + v[1] + v[2] + v[3];
    int incl = s;
    int lane = t & 31;
    #pragma unroll
    for (int o = 1; o < 32; o <<= 1) {
        int u = __shfl_up_sync(0xffffffffu, incl, o);
        if (lane >= o) incl += u;
    }
    if (lane == 31) wsum[t >> 5] = incl;
    __syncthreads();
    int woff = 0;
    int myw = t >> 5;
    #pragma unroll
    for (int w = 0; w < 8; ++w) if (w < myw) woff += wsum[w];
    int run = g_partoff[b] + woff + (incl - s);
    #pragma unroll
    for (int j = 0; j < 4; ++j) {
        if (base + j < n) g_rowptr[base + j] = run;
        run += v[j];
    }
}

__global__ void scatter_edges(int e) {
    int i = blockIdx.x * blockDim.x + threadIdx.x;
    if (i >= e) return;
    int d = g_dst[i];
    int pos = g_rowptr[d] + atomicAdd(&g_cur[d], 1);
    g_col[pos] = i;   // edge id, for deterministic ordering
}

// warp-per-node rank sort of edge ids (unique), then map to src
__global__ __launch_bounds__(256) void sort_warp(int n) {
    int gw = (blockIdx.x * blockDim.x + threadIdx.x) >> 5;
    int lane = threadIdx.x & 31;
    if (gw >= n) return;
    int b = g_rowptr[gw], e = g_rowptr[gw + 1];
    int d = e - b;
    if (d <= 1) {
        if (d == 1 && lane == 0) g_col[b] = g_src[g_col[b]];
        return;
    }
    if (d <= 32) {
        int val = (lane < d) ? g_col[b + lane] : 0x7fffffff;
        int rank = 0;
        for (int j = 0; j < d; ++j) {
            int vj = __shfl_sync(0xffffffffu, val, j);
            rank += (vj < val);
        }
        if (lane < d) g_col[b + rank] = g_src[val];
    } else if (d <= 64) {
        int v0 = (lane < d)      ? g_col[b + lane]      : 0x7fffffff;
        int v1 = (32 + lane < d) ? g_col[b + 32 + lane] : 0x7fffffff;
        int r0 = 0, r1 = 0;
        for (int j = 0; j < d; ++j) {
            int vj = (j < 32) ? __shfl_sync(0xffffffffu, v0, j)
                              : __shfl_sync(0xffffffffu, v1, j - 32);
            r0 += (vj < v0);
            r1 += (vj < v1);
        }
        if (lane < d)      g_col[b + r0] = g_src[v0];
        if (32 + lane < d) g_col[b + r1] = g_src[v1];
    } else {
        if (lane == 0) {
            for (int k = b + 1; k < e; ++k) {
                int v = g_col[k];
                int j = k - 1;
                while (j >= b && g_col[j] > v) { g_col[j + 1] = g_col[j]; --j; }
                g_col[j + 1] = v;
            }
            for (int k = b; k < e; ++k) g_col[k] = g_src[g_col[k]];
        }
    }
}

// ---------------- input projection: h = gelu(x @ W_in + b_in), [N,128]->[N,32]
__global__ __launch_bounds__(256) void gemm_in(
    const float* __restrict__ x, const float* __restrict__ W,
    const float* __restrict__ b, float* __restrict__ h, int n)
{
    __shared__ __align__(16) float Ws[128 * 32];
    __shared__ __align__(16) float xs[8 * 128];
    int tid = threadIdx.x;
    for (int i = tid; i < 128 * 32 / 4; i += 256)
        *reinterpret_cast<float4*>(&Ws[i * 4]) = *reinterpret_cast<const float4*>(&W[i * 4]);
    int node0 = blockIdx.x * 8;
    for (int i = tid; i < 8 * 32; i += 256) {
        int r = i >> 5;
        int row = node0 + r;
        float4 v = make_float4(0.f, 0.f, 0.f, 0.f);
        if (row < n) v = *reinterpret_cast<const float4*>(&x[(size_t)row * 128 + (i & 31) * 4]);
        *reinterpret_cast<float4*>(&xs[r * 128 + (i & 31) * 4]) = v;
    }
    __syncthreads();
    int r = tid >> 5, c = tid & 31;
    float acc = 0.f;
    const float4* xsr = reinterpret_cast<const float4*>(&xs[r * 128]);
    #pragma unroll
    for (int k4 = 0; k4 < 32; ++k4) {
        float4 xv = xsr[k4];
        acc = fmaf(xv.x, Ws[(k4 * 4 + 0) * 32 + c], acc);
        acc = fmaf(xv.y, Ws[(k4 * 4 + 1) * 32 + c], acc);
        acc = fmaf(xv.z, Ws[(k4 * 4 + 2) * 32 + c], acc);
        acc = fmaf(xv.w, Ws[(k4 * 4 + 3) * 32 + c], acc);
    }
    acc += b[c];
    float gl = 0.5f * acc * (1.f + erff(acc * 0.70710678118654752f));
    int row = node0 + r;
    if (row < n) h[(size_t)row * 32 + c] = gl;
}

// ---------------- FFMA2 GEMM: C[n,128] = A[n,K] @ W[K,128] + bias
// dol2 != 0 => L2-normalize each output row (final projection) in epilogue
__global__ __launch_bounds__(256) void gemm_ffma2(
    const float* __restrict__ A,
    const float* __restrict__ W0, const float* __restrict__ b0, float* __restrict__ C0,
    const float* __restrict__ W1, const float* __restrict__ b1, float* __restrict__ C1,
    int n, int K, int dol2)
{
    const float* W    = blockIdx.y ? W1 : W0;
    const float* bias = blockIdx.y ? b1 : b0;
    float*       C    = blockIdx.y ? C1 : C0;

    __shared__ __align__(16) float As[2][16][132];   // [k][m], padded
    __shared__ __align__(16) float Ws[2][16][128];
    int tid  = threadIdx.x;
    int row0 = blockIdx.x * 128;
    int trow = tid >> 4;   // 0..15
    int tcol = tid & 15;   // 0..15

    ull accp[4][8];
    #pragma unroll
    for (int p = 0; p < 4; ++p)
        #pragma unroll
        for (int j = 0; j < 8; ++j) accp[p][j] = 0ull;

    int chunks = K >> 4;
    float4 ra[2], rw[2];

    #pragma unroll
    for (int j = 0; j < 2; ++j) {
        int idx = tid * 2 + j;
        int r = idx >> 2, k4 = idx & 3;
        ra[j] = *reinterpret_cast<const float4*>(&A[(size_t)(row0 + r) * K + k4 * 4]);
        int k = idx >> 5, c4 = idx & 31;
        rw[j] = *reinterpret_cast<const float4*>(&W[(size_t)k * 128 + c4 * 4]);
    }
    #pragma unroll
    for (int j = 0; j < 2; ++j) {
        int idx = tid * 2 + j;
        int r = idx >> 2, k4 = idx & 3;
        As[0][k4 * 4 + 0][r] = ra[j].x;
        As[0][k4 * 4 + 1][r] = ra[j].y;
        As[0][k4 * 4 + 2][r] = ra[j].z;
        As[0][k4 * 4 + 3][r] = ra[j].w;
        int k = idx >> 5, c4 = idx & 31;
        *reinterpret_cast<float4*>(&Ws[0][k][c4 * 4]) = rw[j];
    }
    __syncthreads();

    for (int c = 0; c < chunks; ++c) {
        int buf = c & 1;
        if (c + 1 < chunks) {
            int kc = (c + 1) * 16;
            #pragma unroll
            for (int j = 0; j < 2; ++j) {
                int idx = tid * 2 + j;
                int r = idx >> 2, k4 = idx & 3;
                ra[j] = *reinterpret_cast<const float4*>(&A[(size_t)(row0 + r) * K + kc + k4 * 4]);
                int k = idx >> 5, c4 = idx & 31;
                rw[j] = *reinterpret_cast<const float4*>(&W[(size_t)(kc + k) * 128 + c4 * 4]);
            }
        }
        #pragma unroll
        for (int kk = 0; kk < 16; ++kk) {
            float4 a0 = *reinterpret_cast<const float4*>(&As[buf][kk][trow * 8]);
            float4 a1 = *reinterpret_cast<const float4*>(&As[buf][kk][trow * 8 + 4]);
            float4 q0 = *reinterpret_cast<const float4*>(&Ws[buf][kk][tcol * 8]);
            float4 q1 = *reinterpret_cast<const float4*>(&Ws[buf][kk][tcol * 8 + 4]);
            ull ap[4];
            ap[0] = pack2f(a0.x, a0.y);
            ap[1] = pack2f(a0.z, a0.w);
            ap[2] = pack2f(a1.x, a1.y);
            ap[3] = pack2f(a1.z, a1.w);
            ull bd[8];
            bd[0] = dup2f(q0.x); bd[1] = dup2f(q0.y);
            bd[2] = dup2f(q0.z); bd[3] = dup2f(q0.w);
            bd[4] = dup2f(q1.x); bd[5] = dup2f(q1.y);
            bd[6] = dup2f(q1.z); bd[7] = dup2f(q1.w);
            #pragma unroll
            for (int p = 0; p < 4; ++p)
                #pragma unroll
                for (int j = 0; j < 8; ++j)
                    ffma2(accp[p][j], ap[p], bd[j]);
        }
        if (c + 1 < chunks) {
            int nb = buf ^ 1;
            #pragma unroll
            for (int j = 0; j < 2; ++j) {
                int idx = tid * 2 + j;
                int r = idx >> 2, k4 = idx & 3;
                As[nb][k4 * 4 + 0][r] = ra[j].x;
                As[nb][k4 * 4 + 1][r] = ra[j].y;
                As[nb][k4 * 4 + 2][r] = ra[j].z;
                As[nb][k4 * 4 + 3][r] = ra[j].w;
                int k = idx >> 5, c4 = idx & 31;
                *reinterpret_cast<float4*>(&Ws[nb][k][c4 * 4]) = rw[j];
            }
        }
        __syncthreads();
    }

    float4 bb0 = *reinterpret_cast<const float4*>(&bias[tcol * 8]);
    float4 bb1 = *reinterpret_cast<const float4*>(&bias[tcol * 8 + 4]);
    float bv[8] = {bb0.x, bb0.y, bb0.z, bb0.w, bb1.x, bb1.y, bb1.z, bb1.w};
    #pragma unroll
    for (int p = 0; p < 4; ++p) {
        float lo[8], hi[8];
        #pragma unroll
        for (int j = 0; j < 8; ++j) {
            unpack2f(accp[p][j], lo[j], hi[j]);
            lo[j] += bv[j];
            hi[j] += bv[j];
        }
        if (dol2) {
            float slo = 0.f, shi = 0.f;
            #pragma unroll
            for (int j = 0; j < 8; ++j) { slo = fmaf(lo[j], lo[j], slo); shi = fmaf(hi[j], hi[j], shi); }
            #pragma unroll
            for (int o = 1; o < 16; o <<= 1) {
                slo += __shfl_xor_sync(0xffffffffu, slo, o);
                shi += __shfl_xor_sync(0xffffffffu, shi, o);
            }
            float ilo = 1.f / fmaxf(sqrtf(slo), 1e-12f);
            float ihi = 1.f / fmaxf(sqrtf(shi), 1e-12f);
            #pragma unroll
            for (int j = 0; j < 8; ++j) { lo[j] *= ilo; hi[j] *= ihi; }
        }
        int r0 = row0 + trow * 8 + 2 * p;
        if (r0 < n) {
            float4 o0 = make_float4(lo[0], lo[1], lo[2], lo[3]);
            float4 o1 = make_float4(lo[4], lo[5], lo[6], lo[7]);
            *reinterpret_cast<float4*>(&C[(size_t)r0 * 128 + tcol * 8])     = o0;
            *reinterpret_cast<float4*>(&C[(size_t)r0 * 128 + tcol * 8 + 4]) = o1;
        }
        if (r0 + 1 < n) {
            float4 o0 = make_float4(hi[0], hi[1], hi[2], hi[3]);
            float4 o1 = make_float4(hi[4], hi[5], hi[6], hi[7]);
            *reinterpret_cast<float4*>(&C[(size_t)(r0 + 1) * 128 + tcol * 8])     = o0;
            *reinterpret_cast<float4*>(&C[(size_t)(r0 + 1) * 128 + tcol * 8 + 4]) = o1;
        }
    }
}

// ---------------- fused GATv2 aggregation + LayerNorm + GELU + residual
// ONE WARP per node; lane owns channels 4*lane..4*lane+3 (head = lane/8).
// Software-pipelined: next 4 gathers issued before current 4 are consumed.
__global__ __launch_bounds__(256) void gat_agg(
    const float* __restrict__ att, const float* __restrict__ bo,
    const float* __restrict__ gam, const float* __restrict__ bet,
    int resflag, int n)
{
    int warp = threadIdx.x >> 5;
    int lane = threadIdx.x & 31;
    int i = blockIdx.x * 8 + warp;
    if (i >= n) return;
    int c0 = lane * 4;

    float4 xl = *reinterpret_cast<const float4*>(&g_xl[(size_t)i * 128 + c0]);
    float4 a4 = __ldg(reinterpret_cast<const float4*>(&att[c0]));

    // self loop first
    float4 xs = *reinterpret_cast<const float4*>(&g_xr[(size_t)i * 128 + c0]);
    float t0 = xl.x + xs.x; t0 = fmaxf(t0, 0.2f * t0);
    float t1 = xl.y + xs.y; t1 = fmaxf(t1, 0.2f * t1);
    float t2 = xl.z + xs.z; t2 = fmaxf(t2, 0.2f * t2);
    float t3 = xl.w + xs.w; t3 = fmaxf(t3, 0.2f * t3);
    float v = fmaf(t0, a4.x, fmaf(t1, a4.y, fmaf(t2, a4.z, t3 * a4.w)));
    v += __shfl_xor_sync(0xffffffffu, v, 1);
    v += __shfl_xor_sync(0xffffffffu, v, 2);
    v += __shfl_xor_sync(0xffffffffu, v, 4);
    float m = v, den = 1.f;
    float4 acc = xs;

#define GAT_LOGIT(vv, xv)                                                    \
    {                                                                        \
        float u0 = xl.x + xv.x; u0 = fmaxf(u0, 0.2f * u0);                   \
        float u1 = xl.y + xv.y; u1 = fmaxf(u1, 0.2f * u1);                   \
        float u2 = xl.z + xv.z; u2 = fmaxf(u2, 0.2f * u2);                   \
        float u3 = xl.w + xv.w; u3 = fmaxf(u3, 0.2f * u3);                   \
        vv = fmaf(u0, a4.x, fmaf(u1, a4.y, fmaf(u2, a4.z, u3 * a4.w)));      \
    }

#define GAT_RUNMERGE(vv, xv)                                                 \
    {                                                                        \
        float nm = fmaxf(m, vv);                                             \
        float sc = __expf(m - nm);                                           \
        float pe = __expf(vv - nm);                                          \
        den = fmaf(den, sc, pe);                                             \
        acc.x = fmaf(acc.x, sc, pe * xv.x);                                  \
        acc.y = fmaf(acc.y, sc, pe * xv.y);                                  \
        acc.z = fmaf(acc.z, sc, pe * xv.z);                                  \
        acc.w = fmaf(acc.w, sc, pe * xv.w);                                  \
        m = nm;                                                              \
    }

    // compute+merge of a resident group of 4 (merge tree; arithmetic order fixed)
#define GAT_BODY4(xa, xb, xc, xd)                                            \
    {                                                                        \
        float va, vb, vc, vd;                                                \
        GAT_LOGIT(va, xa);                                                   \
        GAT_LOGIT(vb, xb);                                                   \
        GAT_LOGIT(vc, xc);                                                   \
        GAT_LOGIT(vd, xd);                                                   \
        va += __shfl_xor_sync(0xffffffffu, va, 1);                           \
        vb += __shfl_xor_sync(0xffffffffu, vb, 1);                           \
        vc += __shfl_xor_sync(0xffffffffu, vc, 1);                           \
        vd += __shfl_xor_sync(0xffffffffu, vd, 1);                           \
        va += __shfl_xor_sync(0xffffffffu, va, 2);                           \
        vb += __shfl_xor_sync(0xffffffffu, vb, 2);                           \
        vc += __shfl_xor_sync(0xffffffffu, vc, 2);                           \
        vd += __shfl_xor_sync(0xffffffffu, vd, 2);                           \
        va += __shfl_xor_sync(0xffffffffu, va, 4);                           \
        vb += __shfl_xor_sync(0xffffffffu, vb, 4);                           \
        vc += __shfl_xor_sync(0xffffffffu, vc, 4);                           \
        vd += __shfl_xor_sync(0xffffffffu, vd, 4);                           \
        float mab = fmaxf(va, vb);                                           \
        float pa  = __expf(va - mab);                                        \
        float pb  = __expf(vb - mab);                                        \
        float dab = pa + pb;                                                 \
        float4 aab;                                                          \
        aab.x = fmaf(pa, xa.x, pb * xb.x);                                   \
        aab.y = fmaf(pa, xa.y, pb * xb.y);                                   \
        aab.z = fmaf(pa, xa.z, pb * xb.z);                                   \
        aab.w = fmaf(pa, xa.w, pb * xb.w);                                   \
        float mcd = fmaxf(vc, vd);                                           \
        float pc  = __expf(vc - mcd);                                        \
        float pd  = __expf(vd - mcd);                                        \
        float dcd = pc + pd;                                                 \
        float4 acd;                                                          \
        acd.x = fmaf(pc, xc.x, pd * xd.x);                                   \
        acd.y = fmaf(pc, xc.y, pd * xd.y);                                   \
        acd.z = fmaf(pc, xc.z, pd * xd.z);                                   \
        acd.w = fmaf(pc, xc.w, pd * xd.w);                                   \
        {                                                                    \
            float nm = fmaxf(m, mab);                                        \
            float sc = __expf(m - nm);                                       \
            float s2 = __expf(mab - nm);                                     \
            den = fmaf(den, sc, dab * s2);                                   \
            acc.x = fmaf(acc.x, sc, aab.x * s2);                             \
            acc.y = fmaf(acc.y, sc, aab.y * s2);                             \
            acc.z = fmaf(acc.z, sc, aab.z * s2);                             \
            acc.w = fmaf(acc.w, sc, aab.w * s2);                             \
            m = nm;                                                          \
        }                                                                    \
        {                                                                    \
            float nm = fmaxf(m, mcd);                                        \
            float sc = __expf(m - nm);                                       \
            float s2 = __expf(mcd - nm);                                     \
            den = fmaf(den, sc, dcd * s2);                                   \
            acc.x = fmaf(acc.x, sc, acd.x * s2);                             \
            acc.y = fmaf(acc.y, sc, acd.y * s2);                             \
            acc.z = fmaf(acc.z, sc, acd.z * s2);                             \
            acc.w = fmaf(acc.w, sc, acd.w * s2);                             \
            m = nm;                                                          \
        }                                                                    \
    }

    int beg = g_rowptr[i], end = g_rowptr[i + 1];
    int k = beg;

    float4 pxa, pxb, pxc, pxd;   // resident (current) group
    if (k + 4 <= end) {
        int s0 = g_col[k];
        int s1 = g_col[k + 1];
        int s2 = g_col[k + 2];
        int s3 = g_col[k + 3];
        pxa = *reinterpret_cast<const float4*>(&g_xr[(size_t)s0 * 128 + c0]);
        pxb = *reinterpret_cast<const float4*>(&g_xr[(size_t)s1 * 128 + c0]);
        pxc = *reinterpret_cast<const float4*>(&g_xr[(size_t)s2 * 128 + c0]);
        pxd = *reinterpret_cast<const float4*>(&g_xr[(size_t)s3 * 128 + c0]);
    }
    // pipelined: issue next group's gathers, then consume current
    for (; k + 8 <= end; k += 4) {
        int s0 = g_col[k + 4];
        int s1 = g_col[k + 5];
        int s2 = g_col[k + 6];
        int s3 = g_col[k + 7];
        float4 nxa = *reinterpret_cast<const float4*>(&g_xr[(size_t)s0 * 128 + c0]);
        float4 nxb = *reinterpret_cast<const float4*>(&g_xr[(size_t)s1 * 128 + c0]);
        float4 nxc = *reinterpret_cast<const float4*>(&g_xr[(size_t)s2 * 128 + c0]);
        float4 nxd = *reinterpret_cast<const float4*>(&g_xr[(size_t)s3 * 128 + c0]);
        GAT_BODY4(pxa, pxb, pxc, pxd);
        pxa = nxa; pxb = nxb; pxc = nxc; pxd = nxd;
    }
    if (k + 4 <= end) {
        GAT_BODY4(pxa, pxb, pxc, pxd);
        k += 4;
    }
    if (k + 2 <= end) {
        int s0 = g_col[k];
        int s1 = g_col[k + 1];
        float4 xa = *reinterpret_cast<const float4*>(&g_xr[(size_t)s0 * 128 + c0]);
        float4 xb = *reinterpret_cast<const float4*>(&g_xr[(size_t)s1 * 128 + c0]);
        float va, vb;
        GAT_LOGIT(va, xa);
        GAT_LOGIT(vb, xb);
        va += __shfl_xor_sync(0xffffffffu, va, 1);
        vb += __shfl_xor_sync(0xffffffffu, vb, 1);
        va += __shfl_xor_sync(0xffffffffu, va, 2);
        vb += __shfl_xor_sync(0xffffffffu, vb, 2);
        va += __shfl_xor_sync(0xffffffffu, va, 4);
        vb += __shfl_xor_sync(0xffffffffu, vb, 4);
        GAT_RUNMERGE(va, xa);
        GAT_RUNMERGE(vb, xb);
        k += 2;
    }
    if (k < end) {
        int s0 = g_col[k];
        float4 xa = *reinterpret_cast<const float4*>(&g_xr[(size_t)s0 * 128 + c0]);
        float va;
        GAT_LOGIT(va, xa);
        va += __shfl_xor_sync(0xffffffffu, va, 1);
        va += __shfl_xor_sync(0xffffffffu, va, 2);
        va += __shfl_xor_sync(0xffffffffu, va, 4);
        GAT_RUNMERGE(va, xa);
    }
#undef GAT_LOGIT
#undef GAT_RUNMERGE
#undef GAT_BODY4

    float inv = 1.f / (den + 1e-16f);
    float4 bo4 = __ldg(reinterpret_cast<const float4*>(&bo[c0]));
    float o0 = fmaf(acc.x, inv, bo4.x);
    float o1 = fmaf(acc.y, inv, bo4.y);
    float o2 = fmaf(acc.z, inv, bo4.z);
    float o3 = fmaf(acc.w, inv, bo4.w);

    // LayerNorm over 128 channels (warp-wide butterfly)
    float s1 = o0 + o1 + o2 + o3;
    float s2 = fmaf(o0, o0, fmaf(o1, o1, fmaf(o2, o2, o3 * o3)));
    #pragma unroll
    for (int o = 1; o < 32; o <<= 1) {
        s1 += __shfl_xor_sync(0xffffffffu, s1, o);
        s2 += __shfl_xor_sync(0xffffffffu, s2, o);
    }
    float mu  = s1 * (1.f / 128.f);
    float var = s2 * (1.f / 128.f) - mu * mu;
    var = var > 0.f ? var : 0.f;
    float rstd = rsqrtf(var + 1e-5f);
    float4 g4 = __ldg(reinterpret_cast<const float4*>(&gam[c0]));
    float4 b4 = __ldg(reinterpret_cast<const float4*>(&bet[c0]));
    float y0 = g4.x * (o0 - mu) * rstd + b4.x;
    float y1 = g4.y * (o1 - mu) * rstd + b4.y;
    float y2 = g4.z * (o2 - mu) * rstd + b4.z;
    float y3 = g4.w * (o3 - mu) * rstd + b4.w;
    const float is2 = 0.70710678118654752f;
    float gl0 = 0.5f * y0 * (1.f + erff(y0 * is2));
    float gl1 = 0.5f * y1 * (1.f + erff(y1 * is2));
    float gl2 = 0.5f * y2 * (1.f + erff(y2 * is2));
    float gl3 = 0.5f * y3 * (1.f + erff(y3 * is2));

    float4* hp = reinterpret_cast<float4*>(&g_h[(size_t)i * 128 + c0]);
    if (resflag) {
        float4 hv = *hp;
        hv.x += gl0; hv.y += gl1; hv.z += gl2; hv.w += gl3;
        *hp = hv;
    } else {
        *hp = make_float4(gl0, gl1, gl2, gl3);
    }
}

// ---------------- host launcher ----------------
extern "C" void kernel_launch(void* const* d_in, const int* in_sizes, int n_in,
                              void* d_out, int out_size)
{
    const float* x    = (const float*)d_in[0];
    const void*  ei   = d_in[1];
    const float* W_in = (const float*)d_in[2];
    const float* b_in = (const float*)d_in[3];
    const float *Wl[3], *bl[3], *Wr[3], *br[3], *att[3], *bo[3], *gg[3], *be[3];
    for (int l = 0; l < 3; ++l) {
        int base = 4 + l * 8;
        Wl[l]  = (const float*)d_in[base + 0];
        bl[l]  = (const float*)d_in[base + 1];
        Wr[l]  = (const float*)d_in[base + 2];
        br[l]  = (const float*)d_in[base + 3];
        att[l] = (const float*)d_in[base + 4];
        bo[l]  = (const float*)d_in[base + 5];
        gg[l]  = (const float*)d_in[base + 6];
        be[l]  = (const float*)d_in[base + 7];
    }
    const float* W_out = (const float*)d_in[28];
    const float* b_out = (const float*)d_in[29];

    int n = in_sizes[0] / 128;
    int e = in_sizes[1] / 2;
    int P = (n + 1023) / 1024;

    float *hbuf, *xlbuf, *xrbuf;
    cudaGetSymbolAddress((void**)&hbuf,  g_h);
    cudaGetSymbolAddress((void**)&xlbuf, g_xl);
    cudaGetSymbolAddress((void**)&xrbuf, g_xr);

    dim3 gdual((n + 127) / 128, 2);
    dim3 gsingle((n + 127) / 128, 1);
    int aggblocks = (n + 7) / 8;

    // index 3 = gemm_in (profiled this round)
    zero_detect<<<(n + 255) / 256, 256>>>(ei, e, n);
    convert_hist<<<(e + 255) / 256, 256>>>(ei, e);
    scan_part<<<P, 256>>>(n);
    gemm_in<<<(n + 7) / 8, 256>>>(x, W_in, b_in, hbuf, n);
    scan_top<<<1, 64>>>(P, n);
    scan_down<<<P, 256>>>(n);
    scatter_edges<<<(e + 255) / 256, 256>>>(e);
    sort_warp<<<(n + 7) / 8, 256>>>(n);

    int ic = 32;
    for (int l = 0; l < 3; ++l) {
        gemm_ffma2<<<gdual, 256>>>(hbuf, Wl[l], bl[l], xlbuf,
                                   Wr[l], br[l], xrbuf, n, ic, 0);
        gat_agg<<<aggblocks, 256>>>(att[l], bo[l], gg[l], be[l], (l > 0) ? 1 : 0, n);
        ic = 128;
    }

    gemm_ffma2<<<gsingle, 256>>>(hbuf, W_out, b_out, (float*)d_out,
                                 W_out, b_out, (float*)d_out, n, 128, 1);
}

// round 7
// speedup vs baseline: 1.7326x; 1.0361x over previous
#include <cuda_runtime.h>
#include <cuda_fp16.h>
#include <math.h>

typedef unsigned long long ull;

#define NMAX 50048
#define EMAX 1000000

// ---------------- scratch (no allocations allowed) ----------------
__device__ int   g_src[EMAX];
__device__ int   g_dst[EMAX];
__device__ int   g_col[EMAX];
__device__ int   g_rowptr[NMAX + 1];
__device__ int   g_deg[NMAX];
__device__ int   g_cur[NMAX];
__device__ int   g_part[64];
__device__ int   g_partoff[64];
__device__ int   g_flag;   // 1 => edge_index is int32, 0 => int64
__device__ float   g_h [(size_t)NMAX * 128];
__device__ float   g_xl[(size_t)NMAX * 128];
__device__ __half2 g_xrh[(size_t)NMAX * 64];   // xr in fp16 (gather payload)

// ---------------- f32x2 packed-FMA helpers (sm_103a FFMA2) ----------------
__device__ __forceinline__ ull pack2f(float x, float y) {
    ull r; asm("mov.b64 %0, {%1,%2};" : "=l"(r) : "f"(x), "f"(y)); return r;
}
__device__ __forceinline__ ull dup2f(float x) {
    ull r; asm("mov.b64 %0, {%1,%1};" : "=l"(r) : "f"(x)); return r;
}
__device__ __forceinline__ void ffma2(ull& d, ull a, ull b) {
    asm("fma.rn.f32x2 %0, %1, %2, %0;" : "+l"(d) : "l"(a), "l"(b));
}
__device__ __forceinline__ void unpack2f(ull v, float& lo, float& hi) {
    asm("mov.b64 {%0,%1}, %2;" : "=f"(lo), "=f"(hi) : "l"(v));
}

// gather 4 channels of xr (fp16) for node s, lane owns channels lane*4..+3
__device__ __forceinline__ float4 ldxr_h(int s, int lane) {
    uint2 u = *reinterpret_cast<const uint2*>(&g_xrh[(size_t)s * 64 + lane * 2]);
    __half2 h0 = *reinterpret_cast<__half2*>(&u.x);
    __half2 h1 = *reinterpret_cast<__half2*>(&u.y);
    float2 f0 = __half22float2(h0);
    float2 f1 = __half22float2(h1);
    return make_float4(f0.x, f0.y, f1.x, f1.y);
}

// ---------------- zero counters + edge dtype detection ----------------
__global__ void zero_detect(const void* ei, int e, int n) {
    int i = blockIdx.x * blockDim.x + threadIdx.x;
    if (i < n) { g_deg[i] = 0; g_cur[i] = 0; }
    if (blockIdx.x == 0) {
        __shared__ int any;
        if (threadIdx.x == 0) any = 0;
        __syncthreads();
        const int* w = (const int*)ei;
        int lim = 2048 < e ? 2048 : e;
        for (int k = threadIdx.x; k < lim; k += 256)
            if (w[2 * k + 1] != 0) any = 1;
        __syncthreads();
        if (threadIdx.x == 0) g_flag = any;
    }
}

// convert + degree histogram fused
__global__ void convert_hist(const void* ei, int e) {
    int i = blockIdx.x * blockDim.x + threadIdx.x;
    if (i >= e) return;
    int s, d;
    if (g_flag == 0) {
        const long long* p = (const long long*)ei;
        s = (int)p[i]; d = (int)p[e + i];
    } else {
        const int* p = (const int*)ei;
        s = p[i]; d = p[e + i];
    }
    g_src[i] = s;
    g_dst[i] = d;
    atomicAdd(&g_deg[d], 1);
}

// ---------------- multi-block exclusive scan of g_deg -> g_rowptr --------
__global__ __launch_bounds__(256) void scan_part(int n) {
    __shared__ int wsum[8];
    int b = blockIdx.x, t = threadIdx.x;
    int base = b * 1024 + t * 4;
    int s = 0;
    #pragma unroll
    for (int j = 0; j < 4; ++j) s += (base + j < n) ? g_deg[base + j] : 0;
    #pragma unroll
    for (int o = 16; o; o >>= 1) s += __shfl_xor_sync(0xffffffffu, s, o);
    if ((t & 31) == 0) wsum[t >> 5] = s;
    __syncthreads();
    if (t == 0) {
        int tot = 0;
        #pragma unroll
        for (int w = 0; w < 8; ++w) tot += wsum[w];
        g_part[b] = tot;
    }
}

__global__ void scan_top(int P, int n) {
    __shared__ int sp[64];
    int t = threadIdx.x;
    if (t < P) sp[t] = g_part[t];
    __syncthreads();
    if (t == 0) {
        int run = 0;
        for (int b = 0; b < P; ++b) { g_partoff[b] = run; run += sp[b]; }
        g_rowptr[n] = run;
    }
}

__global__ __launch_bounds__(256) void scan_down(int n) {
    __shared__ int wsum[8];
    int b = blockIdx.x, t = threadIdx.x;
    int base = b * 1024 + t * 4;
    int v[4];
    #pragma unroll
    for (int j = 0; j < 4; ++j) v[j] = (base + j < n) ? g_deg[base + j] : 0;
    int s = v[0] + v[1] + v[2] + v[3];
    int incl = s;
    int lane = t & 31;
    #pragma unroll
    for (int o = 1; o < 32; o <<= 1) {
        int u = __shfl_up_sync(0xffffffffu, incl, o);
        if (lane >= o) incl += u;
    }
    if (lane == 31) wsum[t >> 5] = incl;
    __syncthreads();
    int woff = 0;
    int myw = t >> 5;
    #pragma unroll
    for (int w = 0; w < 8; ++w) if (w < myw) woff += wsum[w];
    int run = g_partoff[b] + woff + (incl - s);
    #pragma unroll
    for (int j = 0; j < 4; ++j) {
        if (base + j < n) g_rowptr[base + j] = run;
        run += v[j];
    }
}

__global__ void scatter_edges(int e) {
    int i = blockIdx.x * blockDim.x + threadIdx.x;
    if (i >= e) return;
    int d = g_dst[i];
    int pos = g_rowptr[d] + atomicAdd(&g_cur[d], 1);
    g_col[pos] = i;   // edge id, for deterministic ordering
}

// warp-per-node rank sort of edge ids (unique), then map to src
__global__ __launch_bounds__(256) void sort_warp(int n) {
    int gw = (blockIdx.x * blockDim.x + threadIdx.x) >> 5;
    int lane = threadIdx.x & 31;
    if (gw >= n) return;
    int b = g_rowptr[gw], e = g_rowptr[gw + 1];
    int d = e - b;
    if (d <= 1) {
        if (d == 1 && lane == 0) g_col[b] = g_src[g_col[b]];
        return;
    }
    if (d <= 32) {
        int val = (lane < d) ? g_col[b + lane] : 0x7fffffff;
        int rank = 0;
        for (int j = 0; j < d; ++j) {
            int vj = __shfl_sync(0xffffffffu, val, j);
            rank += (vj < val);
        }
        if (lane < d) g_col[b + rank] = g_src[val];
    } else if (d <= 64) {
        int v0 = (lane < d)      ? g_col[b + lane]      : 0x7fffffff;
        int v1 = (32 + lane < d) ? g_col[b + 32 + lane] : 0x7fffffff;
        int r0 = 0, r1 = 0;
        for (int j = 0; j < d; ++j) {
            int vj = (j < 32) ? __shfl_sync(0xffffffffu, v0, j)
                              : __shfl_sync(0xffffffffu, v1, j - 32);
            r0 += (vj < v0);
            r1 += (vj < v1);
        }
        if (lane < d)      g_col[b + r0] = g_src[v0];
        if (32 + lane < d) g_col[b + r1] = g_src[v1];
    } else {
        if (lane == 0) {
            for (int k = b + 1; k < e; ++k) {
                int v = g_col[k];
                int j = k - 1;
                while (j >= b && g_col[j] > v) { g_col[j + 1] = g_col[j]; --j; }
                g_col[j + 1] = v;
            }
            for (int k = b; k < e; ++k) g_col[k] = g_src[g_col[k]];
        }
    }
}

// ---------------- input projection: h = gelu(x @ W_in + b_in), [N,128]->[N,32]
// warp = 8 rows x 32 cols; per k4: 4 conflict-free Ws LDS + 8 broadcast xs LDS
__global__ __launch_bounds__(256) void gemm_in(
    const float* __restrict__ x, const float* __restrict__ W,
    const float* __restrict__ b, float* __restrict__ h, int n)
{
    __shared__ __align__(16) float Ws[128 * 32];
    __shared__ __align__(16) float xs[64][128];
    int tid = threadIdx.x, warp = tid >> 5, lane = tid & 31;
    for (int i = tid; i < 1024; i += 256)
        *reinterpret_cast<float4*>(&Ws[i * 4]) = *reinterpret_cast<const float4*>(&W[i * 4]);
    int node0 = blockIdx.x * 64;
    for (int i = tid; i < 64 * 32; i += 256) {
        int r = i >> 5, k4 = i & 31;
        int row = node0 + r;
        float4 v = make_float4(0.f, 0.f, 0.f, 0.f);
        if (row < n) v = *reinterpret_cast<const float4*>(&x[(size_t)row * 128 + k4 * 4]);
        *reinterpret_cast<float4*>(&xs[r][k4 * 4]) = v;
    }
    __syncthreads();
    int r0 = warp * 8;
    float acc[8];
    #pragma unroll
    for (int r = 0; r < 8; ++r) acc[r] = 0.f;
    #pragma unroll 4
    for (int k4 = 0; k4 < 32; ++k4) {
        float w0 = Ws[(k4 * 4 + 0) * 32 + lane];
        float w1 = Ws[(k4 * 4 + 1) * 32 + lane];
        float w2 = Ws[(k4 * 4 + 2) * 32 + lane];
        float w3 = Ws[(k4 * 4 + 3) * 32 + lane];
        #pragma unroll
        for (int r = 0; r < 8; ++r) {
            float4 xv = *reinterpret_cast<const float4*>(&xs[r0 + r][k4 * 4]);
            acc[r] = fmaf(xv.x, w0, fmaf(xv.y, w1, fmaf(xv.z, w2, fmaf(xv.w, w3, acc[r]))));
        }
    }
    float bb = __ldg(&b[lane]);
    const float is2 = 0.70710678118654752f;
    #pragma unroll
    for (int r = 0; r < 8; ++r) {
        int row = node0 + r0 + r;
        if (row < n) {
            float a = acc[r] + bb;
            h[(size_t)row * 32 + lane] = 0.5f * a * (1.f + erff(a * is2));
        }
    }
}

// ---------------- FFMA2 GEMM: C[n,128] = A[n,K] @ W[K,128] + bias
// dol2 != 0 => L2-normalize rows (final projection).
// tohalf != 0 and blockIdx.y == 1 => write fp16 xr (g_xrh) INSTEAD of float C1.
__global__ __launch_bounds__(256) void gemm_ffma2(
    const float* __restrict__ A,
    const float* __restrict__ W0, const float* __restrict__ b0, float* __restrict__ C0,
    const float* __restrict__ W1, const float* __restrict__ b1, float* __restrict__ C1,
    int n, int K, int dol2, int tohalf)
{
    const float* W    = blockIdx.y ? W1 : W0;
    const float* bias = blockIdx.y ? b1 : b0;
    float*       C    = blockIdx.y ? C1 : C0;
    int wanthalf = tohalf && (blockIdx.y != 0);

    __shared__ __align__(16) float As[2][16][132];   // [k][m], padded
    __shared__ __align__(16) float Ws[2][16][128];
    int tid  = threadIdx.x;
    int row0 = blockIdx.x * 128;
    int trow = tid >> 4;   // 0..15
    int tcol = tid & 15;   // 0..15

    ull accp[4][8];
    #pragma unroll
    for (int p = 0; p < 4; ++p)
        #pragma unroll
        for (int j = 0; j < 8; ++j) accp[p][j] = 0ull;

    int chunks = K >> 4;
    float4 ra[2], rw[2];

    #pragma unroll
    for (int j = 0; j < 2; ++j) {
        int idx = tid * 2 + j;
        int r = idx >> 2, k4 = idx & 3;
        ra[j] = *reinterpret_cast<const float4*>(&A[(size_t)(row0 + r) * K + k4 * 4]);
        int k = idx >> 5, c4 = idx & 31;
        rw[j] = *reinterpret_cast<const float4*>(&W[(size_t)k * 128 + c4 * 4]);
    }
    #pragma unroll
    for (int j = 0; j < 2; ++j) {
        int idx = tid * 2 + j;
        int r = idx >> 2, k4 = idx & 3;
        As[0][k4 * 4 + 0][r] = ra[j].x;
        As[0][k4 * 4 + 1][r] = ra[j].y;
        As[0][k4 * 4 + 2][r] = ra[j].z;
        As[0][k4 * 4 + 3][r] = ra[j].w;
        int k = idx >> 5, c4 = idx & 31;
        *reinterpret_cast<float4*>(&Ws[0][k][c4 * 4]) = rw[j];
    }
    __syncthreads();

    for (int c = 0; c < chunks; ++c) {
        int buf = c & 1;
        if (c + 1 < chunks) {
            int kc = (c + 1) * 16;
            #pragma unroll
            for (int j = 0; j < 2; ++j) {
                int idx = tid * 2 + j;
                int r = idx >> 2, k4 = idx & 3;
                ra[j] = *reinterpret_cast<const float4*>(&A[(size_t)(row0 + r) * K + kc + k4 * 4]);
                int k = idx >> 5, c4 = idx & 31;
                rw[j] = *reinterpret_cast<const float4*>(&W[(size_t)(kc + k) * 128 + c4 * 4]);
            }
        }
        #pragma unroll
        for (int kk = 0; kk < 16; ++kk) {
            float4 a0 = *reinterpret_cast<const float4*>(&As[buf][kk][trow * 8]);
            float4 a1 = *reinterpret_cast<const float4*>(&As[buf][kk][trow * 8 + 4]);
            float4 q0 = *reinterpret_cast<const float4*>(&Ws[buf][kk][tcol * 8]);
            float4 q1 = *reinterpret_cast<const float4*>(&Ws[buf][kk][tcol * 8 + 4]);
            ull ap[4];
            ap[0] = pack2f(a0.x, a0.y);
            ap[1] = pack2f(a0.z, a0.w);
            ap[2] = pack2f(a1.x, a1.y);
            ap[3] = pack2f(a1.z, a1.w);
            ull bd[8];
            bd[0] = dup2f(q0.x); bd[1] = dup2f(q0.y);
            bd[2] = dup2f(q0.z); bd[3] = dup2f(q0.w);
            bd[4] = dup2f(q1.x); bd[5] = dup2f(q1.y);
            bd[6] = dup2f(q1.z); bd[7] = dup2f(q1.w);
            #pragma unroll
            for (int p = 0; p < 4; ++p)
                #pragma unroll
                for (int j = 0; j < 8; ++j)
                    ffma2(accp[p][j], ap[p], bd[j]);
        }
        if (c + 1 < chunks) {
            int nb = buf ^ 1;
            #pragma unroll
            for (int j = 0; j < 2; ++j) {
                int idx = tid * 2 + j;
                int r = idx >> 2, k4 = idx & 3;
                As[nb][k4 * 4 + 0][r] = ra[j].x;
                As[nb][k4 * 4 + 1][r] = ra[j].y;
                As[nb][k4 * 4 + 2][r] = ra[j].z;
                As[nb][k4 * 4 + 3][r] = ra[j].w;
                int k = idx >> 5, c4 = idx & 31;
                *reinterpret_cast<float4*>(&Ws[nb][k][c4 * 4]) = rw[j];
            }
        }
        __syncthreads();
    }

    float4 bb0 = *reinterpret_cast<const float4*>(&bias[tcol * 8]);
    float4 bb1 = *reinterpret_cast<const float4*>(&bias[tcol * 8 + 4]);
    float bv[8] = {bb0.x, bb0.y, bb0.z, bb0.w, bb1.x, bb1.y, bb1.z, bb1.w};
    #pragma unroll
    for (int p = 0; p < 4; ++p) {
        float lo[8], hi[8];
        #pragma unroll
        for (int j = 0; j < 8; ++j) {
            unpack2f(accp[p][j], lo[j], hi[j]);
            lo[j] += bv[j];
            hi[j] += bv[j];
        }
        if (dol2) {
            float slo = 0.f, shi = 0.f;
            #pragma unroll
            for (int j = 0; j < 8; ++j) { slo = fmaf(lo[j], lo[j], slo); shi = fmaf(hi[j], hi[j], shi); }
            #pragma unroll
            for (int o = 1; o < 16; o <<= 1) {
                slo += __shfl_xor_sync(0xffffffffu, slo, o);
                shi += __shfl_xor_sync(0xffffffffu, shi, o);
            }
            float ilo = 1.f / fmaxf(sqrtf(slo), 1e-12f);
            float ihi = 1.f / fmaxf(sqrtf(shi), 1e-12f);
            #pragma unroll
            for (int j = 0; j < 8; ++j) { lo[j] *= ilo; hi[j] *= ihi; }
        }
        int r0 = row0 + trow * 8 + 2 * p;
        if (wanthalf) {
            if (r0 < n) {
                __half2 h0 = __floats2half2_rn(lo[0], lo[1]);
                __half2 h1 = __floats2half2_rn(lo[2], lo[3]);
                __half2 h2 = __floats2half2_rn(lo[4], lo[5]);
                __half2 h3 = __floats2half2_rn(lo[6], lo[7]);
                uint4 o;
                o.x = *reinterpret_cast<unsigned*>(&h0);
                o.y = *reinterpret_cast<unsigned*>(&h1);
                o.z = *reinterpret_cast<unsigned*>(&h2);
                o.w = *reinterpret_cast<unsigned*>(&h3);
                *reinterpret_cast<uint4*>(&g_xrh[(size_t)r0 * 64 + tcol * 4]) = o;
            }
            if (r0 + 1 < n) {
                __half2 h0 = __floats2half2_rn(hi[0], hi[1]);
                __half2 h1 = __floats2half2_rn(hi[2], hi[3]);
                __half2 h2 = __floats2half2_rn(hi[4], hi[5]);
                __half2 h3 = __floats2half2_rn(hi[6], hi[7]);
                uint4 o;
                o.x = *reinterpret_cast<unsigned*>(&h0);
                o.y = *reinterpret_cast<unsigned*>(&h1);
                o.z = *reinterpret_cast<unsigned*>(&h2);
                o.w = *reinterpret_cast<unsigned*>(&h3);
                *reinterpret_cast<uint4*>(&g_xrh[(size_t)(r0 + 1) * 64 + tcol * 4]) = o;
            }
        } else {
            if (r0 < n) {
                float4 o0 = make_float4(lo[0], lo[1], lo[2], lo[3]);
                float4 o1 = make_float4(lo[4], lo[5], lo[6], lo[7]);
                *reinterpret_cast<float4*>(&C[(size_t)r0 * 128 + tcol * 8])     = o0;
                *reinterpret_cast<float4*>(&C[(size_t)r0 * 128 + tcol * 8 + 4]) = o1;
            }
            if (r0 + 1 < n) {
                float4 o0 = make_float4(hi[0], hi[1], hi[2], hi[3]);
                float4 o1 = make_float4(hi[4], hi[5], hi[6], hi[7]);
                *reinterpret_cast<float4*>(&C[(size_t)(r0 + 1) * 128 + tcol * 8])     = o0;
                *reinterpret_cast<float4*>(&C[(size_t)(r0 + 1) * 128 + tcol * 8 + 4]) = o1;
            }
        }
    }
}

// ---------------- fused GATv2 aggregation + LayerNorm + GELU + residual
// ONE WARP per node; lane owns channels 4*lane..4*lane+3 (head = lane/8).
// xr gathered in fp16 (256 B/edge). Software-pipelined gathers.
__global__ __launch_bounds__(256) void gat_agg(
    const float* __restrict__ att, const float* __restrict__ bo,
    const float* __restrict__ gam, const float* __restrict__ bet,
    int resflag, int n)
{
    int warp = threadIdx.x >> 5;
    int lane = threadIdx.x & 31;
    int i = blockIdx.x * 8 + warp;
    if (i >= n) return;
    int c0 = lane * 4;

    float4 xl = *reinterpret_cast<const float4*>(&g_xl[(size_t)i * 128 + c0]);
    float4 a4 = __ldg(reinterpret_cast<const float4*>(&att[c0]));

    // self loop first
    float4 xs = ldxr_h(i, lane);
    float t0 = xl.x + xs.x; t0 = fmaxf(t0, 0.2f * t0);
    float t1 = xl.y + xs.y; t1 = fmaxf(t1, 0.2f * t1);
    float t2 = xl.z + xs.z; t2 = fmaxf(t2, 0.2f * t2);
    float t3 = xl.w + xs.w; t3 = fmaxf(t3, 0.2f * t3);
    float v = fmaf(t0, a4.x, fmaf(t1, a4.y, fmaf(t2, a4.z, t3 * a4.w)));
    v += __shfl_xor_sync(0xffffffffu, v, 1);
    v += __shfl_xor_sync(0xffffffffu, v, 2);
    v += __shfl_xor_sync(0xffffffffu, v, 4);
    float m = v, den = 1.f;
    float4 acc = xs;

#define GAT_LOGIT(vv, xv)                                                    \
    {                                                                        \
        float u0 = xl.x + xv.x; u0 = fmaxf(u0, 0.2f * u0);                   \
        float u1 = xl.y + xv.y; u1 = fmaxf(u1, 0.2f * u1);                   \
        float u2 = xl.z + xv.z; u2 = fmaxf(u2, 0.2f * u2);                   \
        float u3 = xl.w + xv.w; u3 = fmaxf(u3, 0.2f * u3);                   \
        vv = fmaf(u0, a4.x, fmaf(u1, a4.y, fmaf(u2, a4.z, u3 * a4.w)));      \
    }

#define GAT_RUNMERGE(vv, xv)                                                 \
    {                                                                        \
        float nm = fmaxf(m, vv);                                             \
        float sc = __expf(m - nm);                                           \
        float pe = __expf(vv - nm);                                          \
        den = fmaf(den, sc, pe);                                             \
        acc.x = fmaf(acc.x, sc, pe * xv.x);                                  \
        acc.y = fmaf(acc.y, sc, pe * xv.y);                                  \
        acc.z = fmaf(acc.z, sc, pe * xv.z);                                  \
        acc.w = fmaf(acc.w, sc, pe * xv.w);                                  \
        m = nm;                                                              \
    }

#define GAT_BODY4(xa, xb, xc, xd)                                            \
    {                                                                        \
        float va, vb, vc, vd;                                                \
        GAT_LOGIT(va, xa);                                                   \
        GAT_LOGIT(vb, xb);                                                   \
        GAT_LOGIT(vc, xc);                                                   \
        GAT_LOGIT(vd, xd);                                                   \
        va += __shfl_xor_sync(0xffffffffu, va, 1);                           \
        vb += __shfl_xor_sync(0xffffffffu, vb, 1);                           \
        vc += __shfl_xor_sync(0xffffffffu, vc, 1);                           \
        vd += __shfl_xor_sync(0xffffffffu, vd, 1);                           \
        va += __shfl_xor_sync(0xffffffffu, va, 2);                           \
        vb += __shfl_xor_sync(0xffffffffu, vb, 2);                           \
        vc += __shfl_xor_sync(0xffffffffu, vc, 2);                           \
        vd += __shfl_xor_sync(0xffffffffu, vd, 2);                           \
        va += __shfl_xor_sync(0xffffffffu, va, 4);                           \
        vb += __shfl_xor_sync(0xffffffffu, vb, 4);                           \
        vc += __shfl_xor_sync(0xffffffffu, vc, 4);                           \
        vd += __shfl_xor_sync(0xffffffffu, vd, 4);                           \
        float mab = fmaxf(va, vb);                                           \
        float pa  = __expf(va - mab);                                        \
        float pb  = __expf(vb - mab);                                        \
        float dab = pa + pb;                                                 \
        float4 aab;                                                          \
        aab.x = fmaf(pa, xa.x, pb * xb.x);                                   \
        aab.y = fmaf(pa, xa.y, pb * xb.y);                                   \
        aab.z = fmaf(pa, xa.z, pb * xb.z);                                   \
        aab.w = fmaf(pa, xa.w, pb * xb.w);                                   \
        float mcd = fmaxf(vc, vd);                                           \
        float pc  = __expf(vc - mcd);                                        \
        float pd  = __expf(vd - mcd);                                        \
        float dcd = pc + pd;                                                 \
        float4 acd;                                                          \
        acd.x = fmaf(pc, xc.x, pd * xd.x);                                   \
        acd.y = fmaf(pc, xc.y, pd * xd.y);                                   \
        acd.z = fmaf(pc, xc.z, pd * xd.z);                                   \
        acd.w = fmaf(pc, xc.w, pd * xd.w);                                   \
        {                                                                    \
            float nm = fmaxf(m, mab);                                        \
            float sc = __expf(m - nm);                                       \
            float s2 = __expf(mab - nm);                                     \
            den = fmaf(den, sc, dab * s2);                                   \
            acc.x = fmaf(acc.x, sc, aab.x * s2);                             \
            acc.y = fmaf(acc.y, sc, aab.y * s2);                             \
            acc.z = fmaf(acc.z, sc, aab.z * s2);                             \
            acc.w = fmaf(acc.w, sc, aab.w * s2);                             \
            m = nm;                                                          \
        }                                                                    \
        {                                                                    \
            float nm = fmaxf(m, mcd);                                        \
            float sc = __expf(m - nm);                                       \
            float s2 = __expf(mcd - nm);                                     \
            den = fmaf(den, sc, dcd * s2);                                   \
            acc.x = fmaf(acc.x, sc, acd.x * s2);                             \
            acc.y = fmaf(acc.y, sc, acd.y * s2);                             \
            acc.z = fmaf(acc.z, sc, acd.z * s2);                             \
            acc.w = fmaf(acc.w, sc, acd.w * s2);                             \
            m = nm;                                                          \
        }                                                                    \
    }

    int beg = g_rowptr[i], end = g_rowptr[i + 1];
    int k = beg;

    float4 pxa, pxb, pxc, pxd;   // resident (current) group
    if (k + 4 <= end) {
        int s0 = g_col[k];
        int s1 = g_col[k + 1];
        int s2 = g_col[k + 2];
        int s3 = g_col[k + 3];
        pxa = ldxr_h(s0, lane);
        pxb = ldxr_h(s1, lane);
        pxc = ldxr_h(s2, lane);
        pxd = ldxr_h(s3, lane);
    }
    for (; k + 8 <= end; k += 4) {
        int s0 = g_col[k + 4];
        int s1 = g_col[k + 5];
        int s2 = g_col[k + 6];
        int s3 = g_col[k + 7];
        float4 nxa = ldxr_h(s0, lane);
        float4 nxb = ldxr_h(s1, lane);
        float4 nxc = ldxr_h(s2, lane);
        float4 nxd = ldxr_h(s3, lane);
        GAT_BODY4(pxa, pxb, pxc, pxd);
        pxa = nxa; pxb = nxb; pxc = nxc; pxd = nxd;
    }
    if (k + 4 <= end) {
        GAT_BODY4(pxa, pxb, pxc, pxd);
        k += 4;
    }
    if (k + 2 <= end) {
        int s0 = g_col[k];
        int s1 = g_col[k + 1];
        float4 xa = ldxr_h(s0, lane);
        float4 xb = ldxr_h(s1, lane);
        float va, vb;
        GAT_LOGIT(va, xa);
        GAT_LOGIT(vb, xb);
        va += __shfl_xor_sync(0xffffffffu, va, 1);
        vb += __shfl_xor_sync(0xffffffffu, vb, 1);
        va += __shfl_xor_sync(0xffffffffu, va, 2);
        vb += __shfl_xor_sync(0xffffffffu, vb, 2);
        va += __shfl_xor_sync(0xffffffffu, va, 4);
        vb += __shfl_xor_sync(0xffffffffu, vb, 4);
        GAT_RUNMERGE(va, xa);
        GAT_RUNMERGE(vb, xb);
        k += 2;
    }
    if (k < end) {
        int s0 = g_col[k];
        float4 xa = ldxr_h(s0, lane);
        float va;
        GAT_LOGIT(va, xa);
        va += __shfl_xor_sync(0xffffffffu, va, 1);
        va += __shfl_xor_sync(0xffffffffu, va, 2);
        va += __shfl_xor_sync(0xffffffffu, va, 4);
        GAT_RUNMERGE(va, xa);
    }
#undef GAT_LOGIT
#undef GAT_RUNMERGE
#undef GAT_BODY4

    float inv = 1.f / (den + 1e-16f);
    float4 bo4 = __ldg(reinterpret_cast<const float4*>(&bo[c0]));
    float o0 = fmaf(acc.x, inv, bo4.x);
    float o1 = fmaf(acc.y, inv, bo4.y);
    float o2 = fmaf(acc.z, inv, bo4.z);
    float o3 = fmaf(acc.w, inv, bo4.w);

    // LayerNorm over 128 channels (warp-wide butterfly)
    float s1 = o0 + o1 + o2 + o3;
    float s2 = fmaf(o0, o0, fmaf(o1, o1, fmaf(o2, o2, o3 * o3)));
    #pragma unroll
    for (int o = 1; o < 32; o <<= 1) {
        s1 += __shfl_xor_sync(0xffffffffu, s1, o);
        s2 += __shfl_xor_sync(0xffffffffu, s2, o);
    }
    float mu  = s1 * (1.f / 128.f);
    float var = s2 * (1.f / 128.f) - mu * mu;
    var = var > 0.f ? var : 0.f;
    float rstd = rsqrtf(var + 1e-5f);
    float4 g4 = __ldg(reinterpret_cast<const float4*>(&gam[c0]));
    float4 b4 = __ldg(reinterpret_cast<const float4*>(&bet[c0]));
    float y0 = g4.x * (o0 - mu) * rstd + b4.x;
    float y1 = g4.y * (o1 - mu) * rstd + b4.y;
    float y2 = g4.z * (o2 - mu) * rstd + b4.z;
    float y3 = g4.w * (o3 - mu) * rstd + b4.w;
    const float is2 = 0.70710678118654752f;
    float gl0 = 0.5f * y0 * (1.f + erff(y0 * is2));
    float gl1 = 0.5f * y1 * (1.f + erff(y1 * is2));
    float gl2 = 0.5f * y2 * (1.f + erff(y2 * is2));
    float gl3 = 0.5f * y3 * (1.f + erff(y3 * is2));

    float4* hp = reinterpret_cast<float4*>(&g_h[(size_t)i * 128 + c0]);
    if (resflag) {
        float4 hv = *hp;
        hv.x += gl0; hv.y += gl1; hv.z += gl2; hv.w += gl3;
        *hp = hv;
    } else {
        *hp = make_float4(gl0, gl1, gl2, gl3);
    }
}

// ---------------- host launcher ----------------
extern "C" void kernel_launch(void* const* d_in, const int* in_sizes, int n_in,
                              void* d_out, int out_size)
{
    const float* x    = (const float*)d_in[0];
    const void*  ei   = d_in[1];
    const float* W_in = (const float*)d_in[2];
    const float* b_in = (const float*)d_in[3];
    const float *Wl[3], *bl[3], *Wr[3], *br[3], *att[3], *bo[3], *gg[3], *be[3];
    for (int l = 0; l < 3; ++l) {
        int base = 4 + l * 8;
        Wl[l]  = (const float*)d_in[base + 0];
        bl[l]  = (const float*)d_in[base + 1];
        Wr[l]  = (const float*)d_in[base + 2];
        br[l]  = (const float*)d_in[base + 3];
        att[l] = (const float*)d_in[base + 4];
        bo[l]  = (const float*)d_in[base + 5];
        gg[l]  = (const float*)d_in[base + 6];
        be[l]  = (const float*)d_in[base + 7];
    }
    const float* W_out = (const float*)d_in[28];
    const float* b_out = (const float*)d_in[29];

    int n = in_sizes[0] / 128;
    int e = in_sizes[1] / 2;
    int P = (n + 1023) / 1024;

    float *hbuf, *xlbuf;
    cudaGetSymbolAddress((void**)&hbuf,  g_h);
    cudaGetSymbolAddress((void**)&xlbuf, g_xl);

    dim3 gdual((n + 127) / 128, 2);
    dim3 gsingle((n + 127) / 128, 1);
    int aggblocks = (n + 7) / 8;

    // index 3 = new gemm_in (profiled this round)
    zero_detect<<<(n + 255) / 256, 256>>>(ei, e, n);
    convert_hist<<<(e + 255) / 256, 256>>>(ei, e);
    scan_part<<<P, 256>>>(n);
    gemm_in<<<(n + 63) / 64, 256>>>(x, W_in, b_in, hbuf, n);
    scan_top<<<1, 64>>>(P, n);
    scan_down<<<P, 256>>>(n);
    scatter_edges<<<(e + 255) / 256, 256>>>(e);
    sort_warp<<<(n + 7) / 8, 256>>>(n);

    int ic = 32;
    for (int l = 0; l < 3; ++l) {
        gemm_ffma2<<<gdual, 256>>>(hbuf, Wl[l], bl[l], xlbuf,
                                   Wr[l], br[l], /*C1 unused for half*/ xlbuf,
                                   n, ic, 0, 1);
        gat_agg<<<aggblocks, 256>>>(att[l], bo[l], gg[l], be[l], (l > 0) ? 1 : 0, n);
        ic = 128;
    }

    gemm_ffma2<<<gsingle, 256>>>(hbuf, W_out, b_out, (float*)d_out,
                                 W_out, b_out, (float*)d_out, n, 128, 1, 0);
}

// round 8
// speedup vs baseline: 2.0754x; 1.1978x over previous
#include <cuda_runtime.h>
#include <cuda_fp16.h>
#include <math.h>

typedef unsigned long long ull;

#define NMAX 50048
#define EMAX 1000000

// ---------------- scratch (no allocations allowed) ----------------
__device__ int   g_src[EMAX];
__device__ int   g_dst[EMAX];
__device__ int   g_col[EMAX];
__device__ int   g_rowptr[NMAX + 1];
__device__ int   g_deg[NMAX];
__device__ int   g_cur[NMAX];
__device__ int   g_part[64];
__device__ int   g_partoff[64];
__device__ int   g_flag;   // 1 => edge_index is int32, 0 => int64
__device__ float   g_h [(size_t)NMAX * 128];
__device__ float   g_xl[(size_t)NMAX * 128];
__device__ __half2 g_xrh[(size_t)NMAX * 64];   // xr in fp16 (gather payload)

// ---------------- f32x2 packed-FMA helpers (sm_103a FFMA2) ----------------
__device__ __forceinline__ ull pack2f(float x, float y) {
    ull r; asm("mov.b64 %0, {%1,%2};" : "=l"(r) : "f"(x), "f"(y)); return r;
}
__device__ __forceinline__ ull dup2f(float x) {
    ull r; asm("mov.b64 %0, {%1,%1};" : "=l"(r) : "f"(x)); return r;
}
__device__ __forceinline__ void ffma2(ull& d, ull a, ull b) {
    asm("fma.rn.f32x2 %0, %1, %2, %0;" : "+l"(d) : "l"(a), "l"(b));
}
__device__ __forceinline__ void unpack2f(ull v, float& lo, float& hi) {
    asm("mov.b64 {%0,%1}, %2;" : "=f"(lo), "=f"(hi) : "l"(v));
}
__device__ __forceinline__ float f2tf32(float f) {
    unsigned u; asm("cvt.rna.tf32.f32 %0, %1;" : "=r"(u) : "f"(f));
    return __uint_as_float(u);
}

// gather 4 channels of xr (fp16) for node s, lane owns channels lane*4..+3
__device__ __forceinline__ float4 ldxr_h(int s, int lane) {
    uint2 u = *reinterpret_cast<const uint2*>(&g_xrh[(size_t)s * 64 + lane * 2]);
    __half2 h0 = *reinterpret_cast<__half2*>(&u.x);
    __half2 h1 = *reinterpret_cast<__half2*>(&u.y);
    float2 f0 = __half22float2(h0);
    float2 f1 = __half22float2(h1);
    return make_float4(f0.x, f0.y, f1.x, f1.y);
}

// ---------------- zero counters + edge dtype detection ----------------
__global__ void zero_detect(const void* ei, int e, int n) {
    int i = blockIdx.x * blockDim.x + threadIdx.x;
    if (i < n) { g_deg[i] = 0; g_cur[i] = 0; }
    if (blockIdx.x == 0) {
        __shared__ int any;
        if (threadIdx.x == 0) any = 0;
        __syncthreads();
        const int* w = (const int*)ei;
        int lim = 2048 < e ? 2048 : e;
        for (int k = threadIdx.x; k < lim; k += 256)
            if (w[2 * k + 1] != 0) any = 1;
        __syncthreads();
        if (threadIdx.x == 0) g_flag = any;
    }
}

// convert + degree histogram fused
__global__ void convert_hist(const void* ei, int e) {
    int i = blockIdx.x * blockDim.x + threadIdx.x;
    if (i >= e) return;
    int s, d;
    if (g_flag == 0) {
        const long long* p = (const long long*)ei;
        s = (int)p[i]; d = (int)p[e + i];
    } else {
        const int* p = (const int*)ei;
        s = p[i]; d = p[e + i];
    }
    g_src[i] = s;
    g_dst[i] = d;
    atomicAdd(&g_deg[d], 1);
}

// ---------------- multi-block exclusive scan of g_deg -> g_rowptr --------
__global__ __launch_bounds__(256) void scan_part(int n) {
    __shared__ int wsum[8];
    int b = blockIdx.x, t = threadIdx.x;
    int base = b * 1024 + t * 4;
    int s = 0;
    #pragma unroll
    for (int j = 0; j < 4; ++j) s += (base + j < n) ? g_deg[base + j] : 0;
    #pragma unroll
    for (int o = 16; o; o >>= 1) s += __shfl_xor_sync(0xffffffffu, s, o);
    if ((t & 31) == 0) wsum[t >> 5] = s;
    __syncthreads();
    if (t == 0) {
        int tot = 0;
        #pragma unroll
        for (int w = 0; w < 8; ++w) tot += wsum[w];
        g_part[b] = tot;
    }
}

__global__ void scan_top(int P, int n) {
    __shared__ int sp[64];
    int t = threadIdx.x;
    if (t < P) sp[t] = g_part[t];
    __syncthreads();
    if (t == 0) {
        int run = 0;
        for (int b = 0; b < P; ++b) { g_partoff[b] = run; run += sp[b]; }
        g_rowptr[n] = run;
    }
}

__global__ __launch_bounds__(256) void scan_down(int n) {
    __shared__ int wsum[8];
    int b = blockIdx.x, t = threadIdx.x;
    int base = b * 1024 + t * 4;
    int v[4];
    #pragma unroll
    for (int j = 0; j < 4; ++j) v[j] = (base + j < n) ? g_deg[base + j] : 0;
    int s = v[0] + v[1] + v[2] + v[3];
    int incl = s;
    int lane = t & 31;
    #pragma unroll
    for (int o = 1; o < 32; o <<= 1) {
        int u = __shfl_up_sync(0xffffffffu, incl, o);
        if (lane >= o) incl += u;
    }
    if (lane == 31) wsum[t >> 5] = incl;
    __syncthreads();
    int woff = 0;
    int myw = t >> 5;
    #pragma unroll
    for (int w = 0; w < 8; ++w) if (w < myw) woff += wsum[w];
    int run = g_partoff[b] + woff + (incl - s);
    #pragma unroll
    for (int j = 0; j < 4; ++j) {
        if (base + j < n) g_rowptr[base + j] = run;
        run += v[j];
    }
}

__global__ void scatter_edges(int e) {
    int i = blockIdx.x * blockDim.x + threadIdx.x;
    if (i >= e) return;
    int d = g_dst[i];
    int pos = g_rowptr[d] + atomicAdd(&g_cur[d], 1);
    g_col[pos] = i;   // edge id, for deterministic ordering
}

// warp-per-node rank sort of edge ids (unique), then map to src
__global__ __launch_bounds__(256) void sort_warp(int n) {
    int gw = (blockIdx.x * blockDim.x + threadIdx.x) >> 5;
    int lane = threadIdx.x & 31;
    if (gw >= n) return;
    int b = g_rowptr[gw], e = g_rowptr[gw + 1];
    int d = e - b;
    if (d <= 1) {
        if (d == 1 && lane == 0) g_col[b] = g_src[g_col[b]];
        return;
    }
    if (d <= 32) {
        int val = (lane < d) ? g_col[b + lane] : 0x7fffffff;
        int rank = 0;
        for (int j = 0; j < d; ++j) {
            int vj = __shfl_sync(0xffffffffu, val, j);
            rank += (vj < val);
        }
        if (lane < d) g_col[b + rank] = g_src[val];
    } else if (d <= 64) {
        int v0 = (lane < d)      ? g_col[b + lane]      : 0x7fffffff;
        int v1 = (32 + lane < d) ? g_col[b + 32 + lane] : 0x7fffffff;
        int r0 = 0, r1 = 0;
        for (int j = 0; j < d; ++j) {
            int vj = (j < 32) ? __shfl_sync(0xffffffffu, v0, j)
                              : __shfl_sync(0xffffffffu, v1, j - 32);
            r0 += (vj < v0);
            r1 += (vj < v1);
        }
        if (lane < d)      g_col[b + r0] = g_src[v0];
        if (32 + lane < d) g_col[b + r1] = g_src[v1];
    } else {
        if (lane == 0) {
            for (int k = b + 1; k < e; ++k) {
                int v = g_col[k];
                int j = k - 1;
                while (j >= b && g_col[j] > v) { g_col[j + 1] = g_col[j]; --j; }
                g_col[j + 1] = v;
            }
            for (int k = b; k < e; ++k) g_col[k] = g_src[g_col[k]];
        }
    }
}

// ---------------- input projection: h = gelu(x @ W_in + b_in), [N,128]->[N,32]
__global__ __launch_bounds__(256) void gemm_in(
    const float* __restrict__ x, const float* __restrict__ W,
    const float* __restrict__ b, float* __restrict__ h, int n)
{
    __shared__ __align__(16) float Ws[128 * 32];
    __shared__ __align__(16) float xs[64][128];
    int tid = threadIdx.x, warp = tid >> 5, lane = tid & 31;
    for (int i = tid; i < 1024; i += 256)
        *reinterpret_cast<float4*>(&Ws[i * 4]) = *reinterpret_cast<const float4*>(&W[i * 4]);
    int node0 = blockIdx.x * 64;
    for (int i = tid; i < 64 * 32; i += 256) {
        int r = i >> 5, k4 = i & 31;
        int row = node0 + r;
        float4 v = make_float4(0.f, 0.f, 0.f, 0.f);
        if (row < n) v = *reinterpret_cast<const float4*>(&x[(size_t)row * 128 + k4 * 4]);
        *reinterpret_cast<float4*>(&xs[r][k4 * 4]) = v;
    }
    __syncthreads();
    int r0 = warp * 8;
    float acc[8];
    #pragma unroll
    for (int r = 0; r < 8; ++r) acc[r] = 0.f;
    #pragma unroll 4
    for (int k4 = 0; k4 < 32; ++k4) {
        float w0 = Ws[(k4 * 4 + 0) * 32 + lane];
        float w1 = Ws[(k4 * 4 + 1) * 32 + lane];
        float w2 = Ws[(k4 * 4 + 2) * 32 + lane];
        float w3 = Ws[(k4 * 4 + 3) * 32 + lane];
        #pragma unroll
        for (int r = 0; r < 8; ++r) {
            float4 xv = *reinterpret_cast<const float4*>(&xs[r0 + r][k4 * 4]);
            acc[r] = fmaf(xv.x, w0, fmaf(xv.y, w1, fmaf(xv.z, w2, fmaf(xv.w, w3, acc[r]))));
        }
    }
    float bb = __ldg(&b[lane]);
    const float is2 = 0.70710678118654752f;
    #pragma unroll
    for (int r = 0; r < 8; ++r) {
        int row = node0 + r0 + r;
        if (row < n) {
            float a = acc[r] + bb;
            h[(size_t)row * 32 + lane] = 0.5f * a * (1.f + erff(a * is2));
        }
    }
}

// ---------------- TF32 tensor-core GEMM (dual): xl = A@Wl+bl (fp32),
//                  xr = A@Wr+br (fp16 to g_xrh). blockIdx.y selects.
// BM=128, BN=128, BK=16, 256 thr = 8 warps (4 along M x 2 along N),
// warp tile 32x64, mma.m16n8k8.tf32. smem stride 136 -> conflict-free frags.
__global__ __launch_bounds__(256) void gemm_mma(
    const float* __restrict__ A,
    const float* __restrict__ W0, const float* __restrict__ b0, float* __restrict__ C0,
    const float* __restrict__ W1, const float* __restrict__ b1,
    int n, int K)
{
    const float* W    = blockIdx.y ? W1 : W0;
    const float* bias = blockIdx.y ? b1 : b0;

    __shared__ float As[2][16][136];   // [k][m]
    __shared__ float Ws[2][16][136];   // [k][n]
    int tid  = threadIdx.x;
    int warp = tid >> 5, lane = tid & 31;
    int g    = lane >> 2, tig = lane & 3;
    int warp_m = warp & 3, warp_n = warp >> 2;
    int row0 = blockIdx.x * 128;

    float acc[2][8][4];
    #pragma unroll
    for (int mt = 0; mt < 2; ++mt)
        #pragma unroll
        for (int nt = 0; nt < 8; ++nt)
            #pragma unroll
            for (int q = 0; q < 4; ++q) acc[mt][nt][q] = 0.f;

    int chunks = K >> 4;
    float4 ra[2], rw[2];

    // prologue: load chunk 0
    #pragma unroll
    for (int j = 0; j < 2; ++j) {
        int idx = tid * 2 + j;
        int r = idx >> 2, k4 = idx & 3;
        ra[j] = *reinterpret_cast<const float4*>(&A[(size_t)(row0 + r) * K + k4 * 4]);
        int k = idx >> 5, c4 = idx & 31;
        rw[j] = *reinterpret_cast<const float4*>(&W[(size_t)k * 128 + c4 * 4]);
    }
    #pragma unroll
    for (int j = 0; j < 2; ++j) {
        int idx = tid * 2 + j;
        int r = idx >> 2, k4 = idx & 3;
        As[0][k4 * 4 + 0][r] = f2tf32(ra[j].x);
        As[0][k4 * 4 + 1][r] = f2tf32(ra[j].y);
        As[0][k4 * 4 + 2][r] = f2tf32(ra[j].z);
        As[0][k4 * 4 + 3][r] = f2tf32(ra[j].w);
        int k = idx >> 5, c4 = idx & 31;
        Ws[0][k][c4 * 4 + 0] = f2tf32(rw[j].x);
        Ws[0][k][c4 * 4 + 1] = f2tf32(rw[j].y);
        Ws[0][k][c4 * 4 + 2] = f2tf32(rw[j].z);
        Ws[0][k][c4 * 4 + 3] = f2tf32(rw[j].w);
    }
    __syncthreads();

    for (int c = 0; c < chunks; ++c) {
        int buf = c & 1;
        if (c + 1 < chunks) {
            int kc = (c + 1) * 16;
            #pragma unroll
            for (int j = 0; j < 2; ++j) {
                int idx = tid * 2 + j;
                int r = idx >> 2, k4 = idx & 3;
                ra[j] = *reinterpret_cast<const float4*>(&A[(size_t)(row0 + r) * K + kc + k4 * 4]);
                int k = idx >> 5, c4 = idx & 31;
                rw[j] = *reinterpret_cast<const float4*>(&W[(size_t)(kc + k) * 128 + c4 * 4]);
            }
        }
        #pragma unroll
        for (int ks = 0; ks < 2; ++ks) {
            int kb = ks * 8;
            // A fragments (2 m-tiles)
            unsigned af[2][4];
            #pragma unroll
            for (int mt = 0; mt < 2; ++mt) {
                int mr = warp_m * 32 + mt * 16;
                af[mt][0] = __float_as_uint(As[buf][kb + tig    ][mr + g]);
                af[mt][1] = __float_as_uint(As[buf][kb + tig    ][mr + g + 8]);
                af[mt][2] = __float_as_uint(As[buf][kb + tig + 4][mr + g]);
                af[mt][3] = __float_as_uint(As[buf][kb + tig + 4][mr + g + 8]);
            }
            #pragma unroll
            for (int nt = 0; nt < 8; ++nt) {
                int nc = warp_n * 64 + nt * 8;
                unsigned bf0 = __float_as_uint(Ws[buf][kb + tig    ][nc + g]);
                unsigned bf1 = __float_as_uint(Ws[buf][kb + tig + 4][nc + g]);
                #pragma unroll
                for (int mt = 0; mt < 2; ++mt) {
                    asm volatile(
                        "mma.sync.aligned.m16n8k8.row.col.f32.tf32.tf32.f32 "
                        "{%0,%1,%2,%3}, {%4,%5,%6,%7}, {%8,%9}, {%0,%1,%2,%3};"
                        : "+f"(acc[mt][nt][0]), "+f"(acc[mt][nt][1]),
                          "+f"(acc[mt][nt][2]), "+f"(acc[mt][nt][3])
                        : "r"(af[mt][0]), "r"(af[mt][1]), "r"(af[mt][2]), "r"(af[mt][3]),
                          "r"(bf0), "r"(bf1));
                }
            }
        }
        if (c + 1 < chunks) {
            int nb = buf ^ 1;
            #pragma unroll
            for (int j = 0; j < 2; ++j) {
                int idx = tid * 2 + j;
                int r = idx >> 2, k4 = idx & 3;
                As[nb][k4 * 4 + 0][r] = f2tf32(ra[j].x);
                As[nb][k4 * 4 + 1][r] = f2tf32(ra[j].y);
                As[nb][k4 * 4 + 2][r] = f2tf32(ra[j].z);
                As[nb][k4 * 4 + 3][r] = f2tf32(ra[j].w);
                int k = idx >> 5, c4 = idx & 31;
                Ws[nb][k][c4 * 4 + 0] = f2tf32(rw[j].x);
                Ws[nb][k][c4 * 4 + 1] = f2tf32(rw[j].y);
                Ws[nb][k][c4 * 4 + 2] = f2tf32(rw[j].z);
                Ws[nb][k][c4 * 4 + 3] = f2tf32(rw[j].w);
            }
        }
        __syncthreads();
    }

    // epilogue
    int wantxl = (blockIdx.y == 0);
    #pragma unroll
    for (int nt = 0; nt < 8; ++nt) {
        int col = warp_n * 64 + nt * 8 + 2 * tig;
        float2 bb = *reinterpret_cast<const float2*>(&bias[col]);
        #pragma unroll
        for (int mt = 0; mt < 2; ++mt) {
            int row_a = row0 + warp_m * 32 + mt * 16 + g;
            int row_b = row_a + 8;
            float c0 = acc[mt][nt][0] + bb.x;
            float c1 = acc[mt][nt][1] + bb.y;
            float c2 = acc[mt][nt][2] + bb.x;
            float c3 = acc[mt][nt][3] + bb.y;
            if (wantxl) {
                if (row_a < n)
                    *reinterpret_cast<float2*>(&C0[(size_t)row_a * 128 + col]) = make_float2(c0, c1);
                if (row_b < n)
                    *reinterpret_cast<float2*>(&C0[(size_t)row_b * 128 + col]) = make_float2(c2, c3);
            } else {
                if (row_a < n)
                    g_xrh[(size_t)row_a * 64 + (col >> 1)] = __floats2half2_rn(c0, c1);
                if (row_b < n)
                    g_xrh[(size_t)row_b * 64 + (col >> 1)] = __floats2half2_rn(c2, c3);
            }
        }
    }
}

// ---------------- FFMA2 GEMM (final projection, fp32 + fused L2 norm)
__global__ __launch_bounds__(256) void gemm_ffma2(
    const float* __restrict__ A,
    const float* __restrict__ W, const float* __restrict__ bias, float* __restrict__ C,
    int n, int K)
{
    __shared__ __align__(16) float As[2][16][132];   // [k][m], padded
    __shared__ __align__(16) float Ws[2][16][128];
    int tid  = threadIdx.x;
    int row0 = blockIdx.x * 128;
    int trow = tid >> 4;   // 0..15
    int tcol = tid & 15;   // 0..15

    ull accp[4][8];
    #pragma unroll
    for (int p = 0; p < 4; ++p)
        #pragma unroll
        for (int j = 0; j < 8; ++j) accp[p][j] = 0ull;

    int chunks = K >> 4;
    float4 ra[2], rw[2];

    #pragma unroll
    for (int j = 0; j < 2; ++j) {
        int idx = tid * 2 + j;
        int r = idx >> 2, k4 = idx & 3;
        ra[j] = *reinterpret_cast<const float4*>(&A[(size_t)(row0 + r) * K + k4 * 4]);
        int k = idx >> 5, c4 = idx & 31;
        rw[j] = *reinterpret_cast<const float4*>(&W[(size_t)k * 128 + c4 * 4]);
    }
    #pragma unroll
    for (int j = 0; j < 2; ++j) {
        int idx = tid * 2 + j;
        int r = idx >> 2, k4 = idx & 3;
        As[0][k4 * 4 + 0][r] = ra[j].x;
        As[0][k4 * 4 + 1][r] = ra[j].y;
        As[0][k4 * 4 + 2][r] = ra[j].z;
        As[0][k4 * 4 + 3][r] = ra[j].w;
        int k = idx >> 5, c4 = idx & 31;
        *reinterpret_cast<float4*>(&Ws[0][k][c4 * 4]) = rw[j];
    }
    __syncthreads();

    for (int c = 0; c < chunks; ++c) {
        int buf = c & 1;
        if (c + 1 < chunks) {
            int kc = (c + 1) * 16;
            #pragma unroll
            for (int j = 0; j < 2; ++j) {
                int idx = tid * 2 + j;
                int r = idx >> 2, k4 = idx & 3;
                ra[j] = *reinterpret_cast<const float4*>(&A[(size_t)(row0 + r) * K + kc + k4 * 4]);
                int k = idx >> 5, c4 = idx & 31;
                rw[j] = *reinterpret_cast<const float4*>(&W[(size_t)(kc + k) * 128 + c4 * 4]);
            }
        }
        #pragma unroll
        for (int kk = 0; kk < 16; ++kk) {
            float4 a0 = *reinterpret_cast<const float4*>(&As[buf][kk][trow * 8]);
            float4 a1 = *reinterpret_cast<const float4*>(&As[buf][kk][trow * 8 + 4]);
            float4 q0 = *reinterpret_cast<const float4*>(&Ws[buf][kk][tcol * 8]);
            float4 q1 = *reinterpret_cast<const float4*>(&Ws[buf][kk][tcol * 8 + 4]);
            ull ap[4];
            ap[0] = pack2f(a0.x, a0.y);
            ap[1] = pack2f(a0.z, a0.w);
            ap[2] = pack2f(a1.x, a1.y);
            ap[3] = pack2f(a1.z, a1.w);
            ull bd[8];
            bd[0] = dup2f(q0.x); bd[1] = dup2f(q0.y);
            bd[2] = dup2f(q0.z); bd[3] = dup2f(q0.w);
            bd[4] = dup2f(q1.x); bd[5] = dup2f(q1.y);
            bd[6] = dup2f(q1.z); bd[7] = dup2f(q1.w);
            #pragma unroll
            for (int p = 0; p < 4; ++p)
                #pragma unroll
                for (int j = 0; j < 8; ++j)
                    ffma2(accp[p][j], ap[p], bd[j]);
        }
        if (c + 1 < chunks) {
            int nb = buf ^ 1;
            #pragma unroll
            for (int j = 0; j < 2; ++j) {
                int idx = tid * 2 + j;
                int r = idx >> 2, k4 = idx & 3;
                As[nb][k4 * 4 + 0][r] = ra[j].x;
                As[nb][k4 * 4 + 1][r] = ra[j].y;
                As[nb][k4 * 4 + 2][r] = ra[j].z;
                As[nb][k4 * 4 + 3][r] = ra[j].w;
                int k = idx >> 5, c4 = idx & 31;
                *reinterpret_cast<float4*>(&Ws[nb][k][c4 * 4]) = rw[j];
            }
        }
        __syncthreads();
    }

    float4 bb0 = *reinterpret_cast<const float4*>(&bias[tcol * 8]);
    float4 bb1 = *reinterpret_cast<const float4*>(&bias[tcol * 8 + 4]);
    float bv[8] = {bb0.x, bb0.y, bb0.z, bb0.w, bb1.x, bb1.y, bb1.z, bb1.w};
    #pragma unroll
    for (int p = 0; p < 4; ++p) {
        float lo[8], hi[8];
        #pragma unroll
        for (int j = 0; j < 8; ++j) {
            unpack2f(accp[p][j], lo[j], hi[j]);
            lo[j] += bv[j];
            hi[j] += bv[j];
        }
        // row-wise L2 norm: the 16 threads sharing trow hold the full row
        float slo = 0.f, shi = 0.f;
        #pragma unroll
        for (int j = 0; j < 8; ++j) { slo = fmaf(lo[j], lo[j], slo); shi = fmaf(hi[j], hi[j], shi); }
        #pragma unroll
        for (int o = 1; o < 16; o <<= 1) {
            slo += __shfl_xor_sync(0xffffffffu, slo, o);
            shi += __shfl_xor_sync(0xffffffffu, shi, o);
        }
        float ilo = 1.f / fmaxf(sqrtf(slo), 1e-12f);
        float ihi = 1.f / fmaxf(sqrtf(shi), 1e-12f);
        #pragma unroll
        for (int j = 0; j < 8; ++j) { lo[j] *= ilo; hi[j] *= ihi; }
        int r0 = row0 + trow * 8 + 2 * p;
        if (r0 < n) {
            float4 o0 = make_float4(lo[0], lo[1], lo[2], lo[3]);
            float4 o1 = make_float4(lo[4], lo[5], lo[6], lo[7]);
            *reinterpret_cast<float4*>(&C[(size_t)r0 * 128 + tcol * 8])     = o0;
            *reinterpret_cast<float4*>(&C[(size_t)r0 * 128 + tcol * 8 + 4]) = o1;
        }
        if (r0 + 1 < n) {
            float4 o0 = make_float4(hi[0], hi[1], hi[2], hi[3]);
            float4 o1 = make_float4(hi[4], hi[5], hi[6], hi[7]);
            *reinterpret_cast<float4*>(&C[(size_t)(r0 + 1) * 128 + tcol * 8])     = o0;
            *reinterpret_cast<float4*>(&C[(size_t)(r0 + 1) * 128 + tcol * 8 + 4]) = o1;
        }
    }
}

// ---------------- fused GATv2 aggregation + LayerNorm + GELU + residual
__global__ __launch_bounds__(256) void gat_agg(
    const float* __restrict__ att, const float* __restrict__ bo,
    const float* __restrict__ gam, const float* __restrict__ bet,
    int resflag, int n)
{
    int warp = threadIdx.x >> 5;
    int lane = threadIdx.x & 31;
    int i = blockIdx.x * 8 + warp;
    if (i >= n) return;
    int c0 = lane * 4;

    float4 xl = *reinterpret_cast<const float4*>(&g_xl[(size_t)i * 128 + c0]);
    float4 a4 = __ldg(reinterpret_cast<const float4*>(&att[c0]));

    float4 xs = ldxr_h(i, lane);
    float t0 = xl.x + xs.x; t0 = fmaxf(t0, 0.2f * t0);
    float t1 = xl.y + xs.y; t1 = fmaxf(t1, 0.2f * t1);
    float t2 = xl.z + xs.z; t2 = fmaxf(t2, 0.2f * t2);
    float t3 = xl.w + xs.w; t3 = fmaxf(t3, 0.2f * t3);
    float v = fmaf(t0, a4.x, fmaf(t1, a4.y, fmaf(t2, a4.z, t3 * a4.w)));
    v += __shfl_xor_sync(0xffffffffu, v, 1);
    v += __shfl_xor_sync(0xffffffffu, v, 2);
    v += __shfl_xor_sync(0xffffffffu, v, 4);
    float m = v, den = 1.f;
    float4 acc = xs;

#define GAT_LOGIT(vv, xv)                                                    \
    {                                                                        \
        float u0 = xl.x + xv.x; u0 = fmaxf(u0, 0.2f * u0);                   \
        float u1 = xl.y + xv.y; u1 = fmaxf(u1, 0.2f * u1);                   \
        float u2 = xl.z + xv.z; u2 = fmaxf(u2, 0.2f * u2);                   \
        float u3 = xl.w + xv.w; u3 = fmaxf(u3, 0.2f * u3);                   \
        vv = fmaf(u0, a4.x, fmaf(u1, a4.y, fmaf(u2, a4.z, u3 * a4.w)));      \
    }

#define GAT_RUNMERGE(vv, xv)                                                 \
    {                                                                        \
        float nm = fmaxf(m, vv);                                             \
        float sc = __expf(m - nm);                                           \
        float pe = __expf(vv - nm);                                          \
        den = fmaf(den, sc, pe);                                             \
        acc.x = fmaf(acc.x, sc, pe * xv.x);                                  \
        acc.y = fmaf(acc.y, sc, pe * xv.y);                                  \
        acc.z = fmaf(acc.z, sc, pe * xv.z);                                  \
        acc.w = fmaf(acc.w, sc, pe * xv.w);                                  \
        m = nm;                                                              \
    }

#define GAT_BODY4(xa, xb, xc, xd)                                            \
    {                                                                        \
        float va, vb, vc, vd;                                                \
        GAT_LOGIT(va, xa);                                                   \
        GAT_LOGIT(vb, xb);                                                   \
        GAT_LOGIT(vc, xc);                                                   \
        GAT_LOGIT(vd, xd);                                                   \
        va += __shfl_xor_sync(0xffffffffu, va, 1);                           \
        vb += __shfl_xor_sync(0xffffffffu, vb, 1);                           \
        vc += __shfl_xor_sync(0xffffffffu, vc, 1);                           \
        vd += __shfl_xor_sync(0xffffffffu, vd, 1);                           \
        va += __shfl_xor_sync(0xffffffffu, va, 2);                           \
        vb += __shfl_xor_sync(0xffffffffu, vb, 2);                           \
        vc += __shfl_xor_sync(0xffffffffu, vc, 2);                           \
        vd += __shfl_xor_sync(0xffffffffu, vd, 2);                           \
        va += __shfl_xor_sync(0xffffffffu, va, 4);                           \
        vb += __shfl_xor_sync(0xffffffffu, vb, 4);                           \
        vc += __shfl_xor_sync(0xffffffffu, vc, 4);                           \
        vd += __shfl_xor_sync(0xffffffffu, vd, 4);                           \
        float mab = fmaxf(va, vb);                                           \
        float pa  = __expf(va - mab);                                        \
        float pb  = __expf(vb - mab);                                        \
        float dab = pa + pb;                                                 \
        float4 aab;                                                          \
        aab.x = fmaf(pa, xa.x, pb * xb.x);                                   \
        aab.y = fmaf(pa, xa.y, pb * xb.y);                                   \
        aab.z = fmaf(pa, xa.z, pb * xb.z);                                   \
        aab.w = fmaf(pa, xa.w, pb * xb.w);                                   \
        float mcd = fmaxf(vc, vd);                                           \
        float pc  = __expf(vc - mcd);                                        \
        float pd  = __expf(vd - mcd);                                        \
        float dcd = pc + pd;                                                 \
        float4 acd;                                                          \
        acd.x = fmaf(pc, xc.x, pd * xd.x);                                   \
        acd.y = fmaf(pc, xc.y, pd * xd.y);                                   \
        acd.z = fmaf(pc, xc.z, pd * xd.z);                                   \
        acd.w = fmaf(pc, xc.w, pd * xd.w);                                   \
        {                                                                    \
            float nm = fmaxf(m, mab);                                        \
            float sc = __expf(m - nm);                                       \
            float s2 = __expf(mab - nm);                                     \
            den = fmaf(den, sc, dab * s2);                                   \
            acc.x = fmaf(acc.x, sc, aab.x * s2);                             \
            acc.y = fmaf(acc.y, sc, aab.y * s2);                             \
            acc.z = fmaf(acc.z, sc, aab.z * s2);                             \
            acc.w = fmaf(acc.w, sc, aab.w * s2);                             \
            m = nm;                                                          \
        }                                                                    \
        {                                                                    \
            float nm = fmaxf(m, mcd);                                        \
            float sc = __expf(m - nm);                                       \
            float s2 = __expf(mcd - nm);                                     \
            den = fmaf(den, sc, dcd * s2);                                   \
            acc.x = fmaf(acc.x, sc, acd.x * s2);                             \
            acc.y = fmaf(acc.y, sc, acd.y * s2);                             \
            acc.z = fmaf(acc.z, sc, acd.z * s2);                             \
            acc.w = fmaf(acc.w, sc, acd.w * s2);                             \
            m = nm;                                                          \
        }                                                                    \
    }

    int beg = g_rowptr[i], end = g_rowptr[i + 1];
    int k = beg;

    float4 pxa, pxb, pxc, pxd;
    if (k + 4 <= end) {
        int s0 = g_col[k];
        int s1 = g_col[k + 1];
        int s2 = g_col[k + 2];
        int s3 = g_col[k + 3];
        pxa = ldxr_h(s0, lane);
        pxb = ldxr_h(s1, lane);
        pxc = ldxr_h(s2, lane);
        pxd = ldxr_h(s3, lane);
    }
    for (; k + 8 <= end; k += 4) {
        int s0 = g_col[k + 4];
        int s1 = g_col[k + 5];
        int s2 = g_col[k + 6];
        int s3 = g_col[k + 7];
        float4 nxa = ldxr_h(s0, lane);
        float4 nxb = ldxr_h(s1, lane);
        float4 nxc = ldxr_h(s2, lane);
        float4 nxd = ldxr_h(s3, lane);
        GAT_BODY4(pxa, pxb, pxc, pxd);
        pxa = nxa; pxb = nxb; pxc = nxc; pxd = nxd;
    }
    if (k + 4 <= end) {
        GAT_BODY4(pxa, pxb, pxc, pxd);
        k += 4;
    }
    if (k + 2 <= end) {
        int s0 = g_col[k];
        int s1 = g_col[k + 1];
        float4 xa = ldxr_h(s0, lane);
        float4 xb = ldxr_h(s1, lane);
        float va, vb;
        GAT_LOGIT(va, xa);
        GAT_LOGIT(vb, xb);
        va += __shfl_xor_sync(0xffffffffu, va, 1);
        vb += __shfl_xor_sync(0xffffffffu, vb, 1);
        va += __shfl_xor_sync(0xffffffffu, va, 2);
        vb += __shfl_xor_sync(0xffffffffu, vb, 2);
        va += __shfl_xor_sync(0xffffffffu, va, 4);
        vb += __shfl_xor_sync(0xffffffffu, vb, 4);
        GAT_RUNMERGE(va, xa);
        GAT_RUNMERGE(vb, xb);
        k += 2;
    }
    if (k < end) {
        int s0 = g_col[k];
        float4 xa = ldxr_h(s0, lane);
        float va;
        GAT_LOGIT(va, xa);
        va += __shfl_xor_sync(0xffffffffu, va, 1);
        va += __shfl_xor_sync(0xffffffffu, va, 2);
        va += __shfl_xor_sync(0xffffffffu, va, 4);
        GAT_RUNMERGE(va, xa);
    }
#undef GAT_LOGIT
#undef GAT_RUNMERGE
#undef GAT_BODY4

    float inv = 1.f / (den + 1e-16f);
    float4 bo4 = __ldg(reinterpret_cast<const float4*>(&bo[c0]));
    float o0 = fmaf(acc.x, inv, bo4.x);
    float o1 = fmaf(acc.y, inv, bo4.y);
    float o2 = fmaf(acc.z, inv, bo4.z);
    float o3 = fmaf(acc.w, inv, bo4.w);

    float s1 = o0 + o1 + o2 + o3;
    float s2 = fmaf(o0, o0, fmaf(o1, o1, fmaf(o2, o2, o3 * o3)));
    #pragma unroll
    for (int o = 1; o < 32; o <<= 1) {
        s1 += __shfl_xor_sync(0xffffffffu, s1, o);
        s2 += __shfl_xor_sync(0xffffffffu, s2, o);
    }
    float mu  = s1 * (1.f / 128.f);
    float var = s2 * (1.f / 128.f) - mu * mu;
    var = var > 0.f ? var : 0.f;
    float rstd = rsqrtf(var + 1e-5f);
    float4 g4 = __ldg(reinterpret_cast<const float4*>(&gam[c0]));
    float4 b4 = __ldg(reinterpret_cast<const float4*>(&bet[c0]));
    float y0 = g4.x * (o0 - mu) * rstd + b4.x;
    float y1 = g4.y * (o1 - mu) * rstd + b4.y;
    float y2 = g4.z * (o2 - mu) * rstd + b4.z;
    float y3 = g4.w * (o3 - mu) * rstd + b4.w;
    const float is2 = 0.70710678118654752f;
    float gl0 = 0.5f * y0 * (1.f + erff(y0 * is2));
    float gl1 = 0.5f * y1 * (1.f + erff(y1 * is2));
    float gl2 = 0.5f * y2 * (1.f + erff(y2 * is2));
    float gl3 = 0.5f * y3 * (1.f + erff(y3 * is2));

    float4* hp = reinterpret_cast<float4*>(&g_h[(size_t)i * 128 + c0]);
    if (resflag) {
        float4 hv = *hp;
        hv.x += gl0; hv.y += gl1; hv.z += gl2; hv.w += gl3;
        *hp = hv;
    } else {
        *hp = make_float4(gl0, gl1, gl2, gl3);
    }
}

// ---------------- host launcher ----------------
extern "C" void kernel_launch(void* const* d_in, const int* in_sizes, int n_in,
                              void* d_out, int out_size)
{
    const float* x    = (const float*)d_in[0];
    const void*  ei   = d_in[1];
    const float* W_in = (const float*)d_in[2];
    const float* b_in = (const float*)d_in[3];
    const float *Wl[3], *bl[3], *Wr[3], *br[3], *att[3], *bo[3], *gg[3], *be[3];
    for (int l = 0; l < 3; ++l) {
        int base = 4 + l * 8;
        Wl[l]  = (const float*)d_in[base + 0];
        bl[l]  = (const float*)d_in[base + 1];
        Wr[l]  = (const float*)d_in[base + 2];
        br[l]  = (const float*)d_in[base + 3];
        att[l] = (const float*)d_in[base + 4];
        bo[l]  = (const float*)d_in[base + 5];
        gg[l]  = (const float*)d_in[base + 6];
        be[l]  = (const float*)d_in[base + 7];
    }
    const float* W_out = (const float*)d_in[28];
    const float* b_out = (const float*)d_in[29];

    int n = in_sizes[0] / 128;
    int e = in_sizes[1] / 2;
    int P = (n + 1023) / 1024;

    float *hbuf, *xlbuf;
    cudaGetSymbolAddress((void**)&hbuf,  g_h);
    cudaGetSymbolAddress((void**)&xlbuf, g_xl);

    dim3 gdual((n + 127) / 128, 2);
    dim3 gsingle((n + 127) / 128, 1);
    int aggblocks = (n + 7) / 8;

    // index 3 = gemm_mma layer 0 (profiled this round)
    zero_detect<<<(n + 255) / 256, 256>>>(ei, e, n);
    convert_hist<<<(e + 255) / 256, 256>>>(ei, e);
    gemm_in<<<(n + 63) / 64, 256>>>(x, W_in, b_in, hbuf, n);
    gemm_mma<<<gdual, 256>>>(hbuf, Wl[0], bl[0], xlbuf, Wr[0], br[0], n, 32);
    scan_part<<<P, 256>>>(n);
    scan_top<<<1, 64>>>(P, n);
    scan_down<<<P, 256>>>(n);
    scatter_edges<<<(e + 255) / 256, 256>>>(e);
    sort_warp<<<(n + 7) / 8, 256>>>(n);

    gat_agg<<<aggblocks, 256>>>(att[0], bo[0], gg[0], be[0], 0, n);
    for (int l = 1; l < 3; ++l) {
        gemm_mma<<<gdual, 256>>>(hbuf, Wl[l], bl[l], xlbuf, Wr[l], br[l], n, 128);
        gat_agg<<<aggblocks, 256>>>(att[l], bo[l], gg[l], be[l], 1, n);
    }

    gemm_ffma2<<<gsingle, 256>>>(hbuf, W_out, b_out, (float*)d_out, n, 128);
}

// round 9
// speedup vs baseline: 2.1699x; 1.0455x over previous
#include <cuda_runtime.h>
#include <cuda_fp16.h>
#include <math.h>

#define NMAX 50048
#define EMAX 1000000

// ---------------- scratch (no allocations allowed) ----------------
__device__ int   g_src[EMAX];
__device__ int   g_dst[EMAX];
__device__ int   g_col[EMAX];
__device__ int   g_rowptr[NMAX + 1];
__device__ int   g_deg[NMAX];
__device__ int   g_cur[NMAX];
__device__ int   g_part[64];
__device__ int   g_flag;   // 1 => edge_index is int32, 0 => int64
__device__ float   g_h [(size_t)NMAX * 128];
__device__ float   g_xl[(size_t)NMAX * 128];
__device__ __half2 g_xrh[(size_t)NMAX * 64];   // xr in fp16 (gather payload)

__device__ __forceinline__ float f2tf32(float f) {
    unsigned u; asm("cvt.rna.tf32.f32 %0, %1;" : "=r"(u) : "f"(f));
    return __uint_as_float(u);
}

// gather 4 channels of xr (fp16) for node s, lane owns channels lane*4..+3
__device__ __forceinline__ float4 ldxr_h(int s, int lane) {
    uint2 u = *reinterpret_cast<const uint2*>(&g_xrh[(size_t)s * 64 + lane * 2]);
    __half2 h0 = *reinterpret_cast<__half2*>(&u.x);
    __half2 h1 = *reinterpret_cast<__half2*>(&u.y);
    float2 f0 = __half22float2(h0);
    float2 f1 = __half22float2(h1);
    return make_float4(f0.x, f0.y, f1.x, f1.y);
}

// ---------------- zero counters + edge dtype detection ----------------
__global__ void zero_detect(const void* ei, int e, int n) {
    int i = blockIdx.x * blockDim.x + threadIdx.x;
    if (i < n) { g_deg[i] = 0; g_cur[i] = 0; }
    if (blockIdx.x == 0) {
        __shared__ int any;
        if (threadIdx.x == 0) any = 0;
        __syncthreads();
        const int* w = (const int*)ei;
        int lim = 2048 < e ? 2048 : e;
        for (int k = threadIdx.x; k < lim; k += 256)
            if (w[2 * k + 1] != 0) any = 1;
        __syncthreads();
        if (threadIdx.x == 0) g_flag = any;
    }
}

// convert + degree histogram fused
__global__ void convert_hist(const void* ei, int e) {
    int i = blockIdx.x * blockDim.x + threadIdx.x;
    if (i >= e) return;
    int s, d;
    if (g_flag == 0) {
        const long long* p = (const long long*)ei;
        s = (int)p[i]; d = (int)p[e + i];
    } else {
        const int* p = (const int*)ei;
        s = p[i]; d = p[e + i];
    }
    g_src[i] = s;
    g_dst[i] = d;
    atomicAdd(&g_deg[d], 1);
}

// ---------------- scan phase 1: per-1024-block totals ----------------
__global__ __launch_bounds__(256) void scan_part(int n) {
    __shared__ int wsum[8];
    int b = blockIdx.x, t = threadIdx.x;
    int base = b * 1024 + t * 4;
    int s = 0;
    #pragma unroll
    for (int j = 0; j < 4; ++j) s += (base + j < n) ? g_deg[base + j] : 0;
    #pragma unroll
    for (int o = 16; o; o >>= 1) s += __shfl_xor_sync(0xffffffffu, s, o);
    if ((t & 31) == 0) wsum[t >> 5] = s;
    __syncthreads();
    if (t == 0) {
        int tot = 0;
        #pragma unroll
        for (int w = 0; w < 8; ++w) tot += wsum[w];
        g_part[b] = tot;
    }
}

// ---------------- scan phase 2: block scan + inline top prefix --------
__global__ __launch_bounds__(256) void scan_down(int n, int P) {
    __shared__ int wsum[8];
    __shared__ int s_off, s_tot;
    int b = blockIdx.x, t = threadIdx.x;
    int lane = t & 31;
    if (t < 32) {
        int v0 = (lane < P) ? g_part[lane] : 0;
        int v1 = (lane + 32 < P) ? g_part[lane + 32] : 0;
        int sb = ((lane < b) ? v0 : 0) + ((lane + 32 < b) ? v1 : 0);
        int sa = v0 + v1;
        #pragma unroll
        for (int o = 16; o; o >>= 1) {
            sb += __shfl_xor_sync(0xffffffffu, sb, o);
            sa += __shfl_xor_sync(0xffffffffu, sa, o);
        }
        if (lane == 0) { s_off = sb; s_tot = sa; }
    }
    int base = b * 1024 + t * 4;
    int v[4];
    #pragma unroll
    for (int j = 0; j < 4; ++j) v[j] = (base + j < n) ? g_deg[base + j] : 0;
    int s = v[0] + v[1] + v[2] + v[3];
    int incl = s;
    #pragma unroll
    for (int o = 1; o < 32; o <<= 1) {
        int u = __shfl_up_sync(0xffffffffu, incl, o);
        if (lane >= o) incl += u;
    }
    if (lane == 31) wsum[t >> 5] = incl;
    __syncthreads();
    int woff = 0;
    int myw = t >> 5;
    #pragma unroll
    for (int w = 0; w < 8; ++w) if (w < myw) woff += wsum[w];
    int run = s_off + woff + (incl - s);
    #pragma unroll
    for (int j = 0; j < 4; ++j) {
        if (base + j < n) g_rowptr[base + j] = run;
        run += v[j];
    }
    if (b == gridDim.x - 1 && t == 0) g_rowptr[n] = s_tot;
}

__global__ void scatter_edges(int e) {
    int i = blockIdx.x * blockDim.x + threadIdx.x;
    if (i >= e) return;
    int d = g_dst[i];
    int pos = g_rowptr[d] + atomicAdd(&g_cur[d], 1);
    g_col[pos] = i;   // edge id, for deterministic ordering
}

// warp-per-node rank sort of edge ids (unique), then map to src
__global__ __launch_bounds__(256) void sort_warp(int n) {
    int gw = (blockIdx.x * blockDim.x + threadIdx.x) >> 5;
    int lane = threadIdx.x & 31;
    if (gw >= n) return;
    int b = g_rowptr[gw], e = g_rowptr[gw + 1];
    int d = e - b;
    if (d <= 1) {
        if (d == 1 && lane == 0) g_col[b] = g_src[g_col[b]];
        return;
    }
    if (d <= 32) {
        int val = (lane < d) ? g_col[b + lane] : 0x7fffffff;
        int rank = 0;
        for (int j = 0; j < d; ++j) {
            int vj = __shfl_sync(0xffffffffu, val, j);
            rank += (vj < val);
        }
        if (lane < d) g_col[b + rank] = g_src[val];
    } else if (d <= 64) {
        int v0 = (lane < d)      ? g_col[b + lane]      : 0x7fffffff;
        int v1 = (32 + lane < d) ? g_col[b + 32 + lane] : 0x7fffffff;
        int r0 = 0, r1 = 0;
        for (int j = 0; j < d; ++j) {
            int vj = (j < 32) ? __shfl_sync(0xffffffffu, v0, j)
                              : __shfl_sync(0xffffffffu, v1, j - 32);
            r0 += (vj < v0);
            r1 += (vj < v1);
        }
        if (lane < d)      g_col[b + r0] = g_src[v0];
        if (32 + lane < d) g_col[b + r1] = g_src[v1];
    } else {
        if (lane == 0) {
            for (int k = b + 1; k < e; ++k) {
                int v = g_col[k];
                int j = k - 1;
                while (j >= b && g_col[j] > v) { g_col[j + 1] = g_col[j]; --j; }
                g_col[j + 1] = v;
            }
            for (int k = b; k < e; ++k) g_col[k] = g_src[g_col[k]];
        }
    }
}

// ---------------- FUSED: h = gelu(x@W_in+b_in) in smem (tf32),
//                  then xl = h@Wl+bl (fp32), xr = h@Wr+br (fp16), K=32 mma.
// 128 rows per block, 256 threads. Dynamic smem: Wi 16K | xs 32K | hT 17K | BT 17K.
#define FUSED_SMEM (16384 + 32768 + 17408 + 17408)
__global__ __launch_bounds__(256) void fused_in_l0(
    const float* __restrict__ x, const float* __restrict__ Wi_g,
    const float* __restrict__ bi,
    const float* __restrict__ Wl, const float* __restrict__ bl,
    const float* __restrict__ Wr, const float* __restrict__ br,
    float* __restrict__ xl_out, int n)
{
    extern __shared__ char smraw[];
    float* Wi = (float*)smraw;                                    // [128*32]
    float (*xs)[128] = (float(*)[128])(smraw + 16384);            // [64][128]
    float (*hT)[136] = (float(*)[136])(smraw + 16384 + 32768);    // [32][136] k-major
    float (*BT)[136] = (float(*)[136])(smraw + 16384 + 32768 + 17408); // [32][136]

    int tid = threadIdx.x, warp = tid >> 5, lane = tid & 31;
    int node0 = blockIdx.x * 128;

    for (int i = tid; i < 1024; i += 256)
        *reinterpret_cast<float4*>(&Wi[i * 4]) = *reinterpret_cast<const float4*>(&Wi_g[i * 4]);

    const float is2 = 0.70710678118654752f;
    float bb_in = __ldg(&bi[lane]);

    // ---- phase 1: compute h (two halves of 64 rows), write tf32 hT[k][m]
    for (int half = 0; half < 2; ++half) {
        __syncthreads();
        int base = node0 + half * 64;
        for (int i = tid; i < 64 * 32; i += 256) {
            int r = i >> 5, k4 = i & 31;
            int row = base + r;
            float4 v = make_float4(0.f, 0.f, 0.f, 0.f);
            if (row < n) v = *reinterpret_cast<const float4*>(&x[(size_t)row * 128 + k4 * 4]);
            *reinterpret_cast<float4*>(&xs[r][k4 * 4]) = v;
        }
        __syncthreads();
        int r0 = warp * 8;
        float acc[8];
        #pragma unroll
        for (int r = 0; r < 8; ++r) acc[r] = 0.f;
        #pragma unroll 4
        for (int k4 = 0; k4 < 32; ++k4) {
            float w0 = Wi[(k4 * 4 + 0) * 32 + lane];
            float w1 = Wi[(k4 * 4 + 1) * 32 + lane];
            float w2 = Wi[(k4 * 4 + 2) * 32 + lane];
            float w3 = Wi[(k4 * 4 + 3) * 32 + lane];
            #pragma unroll
            for (int r = 0; r < 8; ++r) {
                float4 xv = *reinterpret_cast<const float4*>(&xs[r0 + r][k4 * 4]);
                acc[r] = fmaf(xv.x, w0, fmaf(xv.y, w1, fmaf(xv.z, w2, fmaf(xv.w, w3, acc[r]))));
            }
        }
        #pragma unroll
        for (int r = 0; r < 8; ++r) {
            float a = acc[r] + bb_in;
            float gl = 0.5f * a * (1.f + erff(a * is2));
            hT[lane][half * 64 + r0 + r] = f2tf32(gl);
        }
    }

    // ---- phase 2: dual K=32 mma (Wl then Wr)
    __syncthreads();
    for (int i = tid; i < 32 * 128; i += 256) {
        int k = i >> 7, c = i & 127;
        BT[k][c] = f2tf32(Wl[i]);
    }
    __syncthreads();

    int g = lane >> 2, tig = lane & 3;
    int warp_m = warp & 3, warp_n = warp >> 2;

    for (int pass = 0; pass < 2; ++pass) {
        float macc[2][8][4];
        #pragma unroll
        for (int mt = 0; mt < 2; ++mt)
            #pragma unroll
            for (int nt = 0; nt < 8; ++nt)
                #pragma unroll
                for (int q = 0; q < 4; ++q) macc[mt][nt][q] = 0.f;

        #pragma unroll
        for (int ks = 0; ks < 4; ++ks) {
            int kb = ks * 8;
            unsigned af[2][4];
            #pragma unroll
            for (int mt = 0; mt < 2; ++mt) {
                int mr = warp_m * 32 + mt * 16;
                af[mt][0] = __float_as_uint(hT[kb + tig    ][mr + g]);
                af[mt][1] = __float_as_uint(hT[kb + tig    ][mr + g + 8]);
                af[mt][2] = __float_as_uint(hT[kb + tig + 4][mr + g]);
                af[mt][3] = __float_as_uint(hT[kb + tig + 4][mr + g + 8]);
            }
            #pragma unroll
            for (int nt = 0; nt < 8; ++nt) {
                int nc = warp_n * 64 + nt * 8;
                unsigned bf0 = __float_as_uint(BT[kb + tig    ][nc + g]);
                unsigned bf1 = __float_as_uint(BT[kb + tig + 4][nc + g]);
                #pragma unroll
                for (int mt = 0; mt < 2; ++mt) {
                    asm volatile(
                        "mma.sync.aligned.m16n8k8.row.col.f32.tf32.tf32.f32 "
                        "{%0,%1,%2,%3}, {%4,%5,%6,%7}, {%8,%9}, {%0,%1,%2,%3};"
                        : "+f"(macc[mt][nt][0]), "+f"(macc[mt][nt][1]),
                          "+f"(macc[mt][nt][2]), "+f"(macc[mt][nt][3])
                        : "r"(af[mt][0]), "r"(af[mt][1]), "r"(af[mt][2]), "r"(af[mt][3]),
                          "r"(bf0), "r"(bf1));
                }
            }
        }

        const float* bias = pass ? br : bl;
        #pragma unroll
        for (int nt = 0; nt < 8; ++nt) {
            int col = warp_n * 64 + nt * 8 + 2 * tig;
            float2 bb = *reinterpret_cast<const float2*>(&bias[col]);
            #pragma unroll
            for (int mt = 0; mt < 2; ++mt) {
                int row_a = node0 + warp_m * 32 + mt * 16 + g;
                int row_b = row_a + 8;
                float c0 = macc[mt][nt][0] + bb.x;
                float c1 = macc[mt][nt][1] + bb.y;
                float c2 = macc[mt][nt][2] + bb.x;
                float c3 = macc[mt][nt][3] + bb.y;
                if (pass == 0) {
                    if (row_a < n)
                        *reinterpret_cast<float2*>(&xl_out[(size_t)row_a * 128 + col]) = make_float2(c0, c1);
                    if (row_b < n)
                        *reinterpret_cast<float2*>(&xl_out[(size_t)row_b * 128 + col]) = make_float2(c2, c3);
                } else {
                    if (row_a < n) g_xrh[(size_t)row_a * 64 + (col >> 1)] = __floats2half2_rn(c0, c1);
                    if (row_b < n) g_xrh[(size_t)row_b * 64 + (col >> 1)] = __floats2half2_rn(c2, c3);
                }
            }
        }
        if (pass == 0) {
            __syncthreads();
            for (int i = tid; i < 32 * 128; i += 256) {
                int k = i >> 7, c = i & 127;
                BT[k][c] = f2tf32(Wr[i]);
            }
            __syncthreads();
        }
    }
}

// ---------------- TF32 tensor-core GEMM (dual): xl/xr, K=128 layers ----
__global__ __launch_bounds__(256) void gemm_mma(
    const float* __restrict__ A,
    const float* __restrict__ W0, const float* __restrict__ b0, float* __restrict__ C0,
    const float* __restrict__ W1, const float* __restrict__ b1,
    int n, int K)
{
    const float* W    = blockIdx.y ? W1 : W0;
    const float* bias = blockIdx.y ? b1 : b0;

    __shared__ float As[2][16][136];   // [k][m]
    __shared__ float Ws[2][16][136];   // [k][n]
    int tid  = threadIdx.x;
    int warp = tid >> 5, lane = tid & 31;
    int g    = lane >> 2, tig = lane & 3;
    int warp_m = warp & 3, warp_n = warp >> 2;
    int row0 = blockIdx.x * 128;

    float acc[2][8][4];
    #pragma unroll
    for (int mt = 0; mt < 2; ++mt)
        #pragma unroll
        for (int nt = 0; nt < 8; ++nt)
            #pragma unroll
            for (int q = 0; q < 4; ++q) acc[mt][nt][q] = 0.f;

    int chunks = K >> 4;
    float4 ra[2], rw[2];

    #pragma unroll
    for (int j = 0; j < 2; ++j) {
        int idx = tid * 2 + j;
        int r = idx >> 2, k4 = idx & 3;
        ra[j] = *reinterpret_cast<const float4*>(&A[(size_t)(row0 + r) * K + k4 * 4]);
        int k = idx >> 5, c4 = idx & 31;
        rw[j] = *reinterpret_cast<const float4*>(&W[(size_t)k * 128 + c4 * 4]);
    }
    #pragma unroll
    for (int j = 0; j < 2; ++j) {
        int idx = tid * 2 + j;
        int r = idx >> 2, k4 = idx & 3;
        As[0][k4 * 4 + 0][r] = f2tf32(ra[j].x);
        As[0][k4 * 4 + 1][r] = f2tf32(ra[j].y);
        As[0][k4 * 4 + 2][r] = f2tf32(ra[j].z);
        As[0][k4 * 4 + 3][r] = f2tf32(ra[j].w);
        int k = idx >> 5, c4 = idx & 31;
        Ws[0][k][c4 * 4 + 0] = f2tf32(rw[j].x);
        Ws[0][k][c4 * 4 + 1] = f2tf32(rw[j].y);
        Ws[0][k][c4 * 4 + 2] = f2tf32(rw[j].z);
        Ws[0][k][c4 * 4 + 3] = f2tf32(rw[j].w);
    }
    __syncthreads();

    for (int c = 0; c < chunks; ++c) {
        int buf = c & 1;
        if (c + 1 < chunks) {
            int kc = (c + 1) * 16;
            #pragma unroll
            for (int j = 0; j < 2; ++j) {
                int idx = tid * 2 + j;
                int r = idx >> 2, k4 = idx & 3;
                ra[j] = *reinterpret_cast<const float4*>(&A[(size_t)(row0 + r) * K + kc + k4 * 4]);
                int k = idx >> 5, c4 = idx & 31;
                rw[j] = *reinterpret_cast<const float4*>(&W[(size_t)(kc + k) * 128 + c4 * 4]);
            }
        }
        #pragma unroll
        for (int ks = 0; ks < 2; ++ks) {
            int kb = ks * 8;
            unsigned af[2][4];
            #pragma unroll
            for (int mt = 0; mt < 2; ++mt) {
                int mr = warp_m * 32 + mt * 16;
                af[mt][0] = __float_as_uint(As[buf][kb + tig    ][mr + g]);
                af[mt][1] = __float_as_uint(As[buf][kb + tig    ][mr + g + 8]);
                af[mt][2] = __float_as_uint(As[buf][kb + tig + 4][mr + g]);
                af[mt][3] = __float_as_uint(As[buf][kb + tig + 4][mr + g + 8]);
            }
            #pragma unroll
            for (int nt = 0; nt < 8; ++nt) {
                int nc = warp_n * 64 + nt * 8;
                unsigned bf0 = __float_as_uint(Ws[buf][kb + tig    ][nc + g]);
                unsigned bf1 = __float_as_uint(Ws[buf][kb + tig + 4][nc + g]);
                #pragma unroll
                for (int mt = 0; mt < 2; ++mt) {
                    asm volatile(
                        "mma.sync.aligned.m16n8k8.row.col.f32.tf32.tf32.f32 "
                        "{%0,%1,%2,%3}, {%4,%5,%6,%7}, {%8,%9}, {%0,%1,%2,%3};"
                        : "+f"(acc[mt][nt][0]), "+f"(acc[mt][nt][1]),
                          "+f"(acc[mt][nt][2]), "+f"(acc[mt][nt][3])
                        : "r"(af[mt][0]), "r"(af[mt][1]), "r"(af[mt][2]), "r"(af[mt][3]),
                          "r"(bf0), "r"(bf1));
                }
            }
        }
        if (c + 1 < chunks) {
            int nb = buf ^ 1;
            #pragma unroll
            for (int j = 0; j < 2; ++j) {
                int idx = tid * 2 + j;
                int r = idx >> 2, k4 = idx & 3;
                As[nb][k4 * 4 + 0][r] = f2tf32(ra[j].x);
                As[nb][k4 * 4 + 1][r] = f2tf32(ra[j].y);
                As[nb][k4 * 4 + 2][r] = f2tf32(ra[j].z);
                As[nb][k4 * 4 + 3][r] = f2tf32(ra[j].w);
                int k = idx >> 5, c4 = idx & 31;
                Ws[nb][k][c4 * 4 + 0] = f2tf32(rw[j].x);
                Ws[nb][k][c4 * 4 + 1] = f2tf32(rw[j].y);
                Ws[nb][k][c4 * 4 + 2] = f2tf32(rw[j].z);
                Ws[nb][k][c4 * 4 + 3] = f2tf32(rw[j].w);
            }
        }
        __syncthreads();
    }

    int wantxl = (blockIdx.y == 0);
    #pragma unroll
    for (int nt = 0; nt < 8; ++nt) {
        int col = warp_n * 64 + nt * 8 + 2 * tig;
        float2 bb = *reinterpret_cast<const float2*>(&bias[col]);
        #pragma unroll
        for (int mt = 0; mt < 2; ++mt) {
            int row_a = row0 + warp_m * 32 + mt * 16 + g;
            int row_b = row_a + 8;
            float c0 = acc[mt][nt][0] + bb.x;
            float c1 = acc[mt][nt][1] + bb.y;
            float c2 = acc[mt][nt][2] + bb.x;
            float c3 = acc[mt][nt][3] + bb.y;
            if (wantxl) {
                if (row_a < n)
                    *reinterpret_cast<float2*>(&C0[(size_t)row_a * 128 + col]) = make_float2(c0, c1);
                if (row_b < n)
                    *reinterpret_cast<float2*>(&C0[(size_t)row_b * 128 + col]) = make_float2(c2, c3);
            } else {
                if (row_a < n)
                    g_xrh[(size_t)row_a * 64 + (col >> 1)] = __floats2half2_rn(c0, c1);
                if (row_b < n)
                    g_xrh[(size_t)row_b * 64 + (col >> 1)] = __floats2half2_rn(c2, c3);
            }
        }
    }
}

// ---------------- TF32 mma final projection with fused row L2 norm ----
__global__ __launch_bounds__(256) void gemm_out_mma(
    const float* __restrict__ A,
    const float* __restrict__ W, const float* __restrict__ bias,
    float* __restrict__ C, int n)
{
    __shared__ float As[2][16][136];
    __shared__ float Ws[2][16][136];
    __shared__ float rsum[128][2];
    const int K = 128;
    int tid  = threadIdx.x;
    int warp = tid >> 5, lane = tid & 31;
    int g    = lane >> 2, tig = lane & 3;
    int warp_m = warp & 3, warp_n = warp >> 2;
    int row0 = blockIdx.x * 128;

    float acc[2][8][4];
    #pragma unroll
    for (int mt = 0; mt < 2; ++mt)
        #pragma unroll
        for (int nt = 0; nt < 8; ++nt)
            #pragma unroll
            for (int q = 0; q < 4; ++q) acc[mt][nt][q] = 0.f;

    int chunks = K >> 4;
    float4 ra[2], rw[2];
    #pragma unroll
    for (int j = 0; j < 2; ++j) {
        int idx = tid * 2 + j;
        int r = idx >> 2, k4 = idx & 3;
        ra[j] = *reinterpret_cast<const float4*>(&A[(size_t)(row0 + r) * K + k4 * 4]);
        int k = idx >> 5, c4 = idx & 31;
        rw[j] = *reinterpret_cast<const float4*>(&W[(size_t)k * 128 + c4 * 4]);
    }
    #pragma unroll
    for (int j = 0; j < 2; ++j) {
        int idx = tid * 2 + j;
        int r = idx >> 2, k4 = idx & 3;
        As[0][k4 * 4 + 0][r] = f2tf32(ra[j].x);
        As[0][k4 * 4 + 1][r] = f2tf32(ra[j].y);
        As[0][k4 * 4 + 2][r] = f2tf32(ra[j].z);
        As[0][k4 * 4 + 3][r] = f2tf32(ra[j].w);
        int k = idx >> 5, c4 = idx & 31;
        Ws[0][k][c4 * 4 + 0] = f2tf32(rw[j].x);
        Ws[0][k][c4 * 4 + 1] = f2tf32(rw[j].y);
        Ws[0][k][c4 * 4 + 2] = f2tf32(rw[j].z);
        Ws[0][k][c4 * 4 + 3] = f2tf32(rw[j].w);
    }
    __syncthreads();

    for (int c = 0; c < chunks; ++c) {
        int buf = c & 1;
        if (c + 1 < chunks) {
            int kc = (c + 1) * 16;
            #pragma unroll
            for (int j = 0; j < 2; ++j) {
                int idx = tid * 2 + j;
                int r = idx >> 2, k4 = idx & 3;
                ra[j] = *reinterpret_cast<const float4*>(&A[(size_t)(row0 + r) * K + kc + k4 * 4]);
                int k = idx >> 5, c4 = idx & 31;
                rw[j] = *reinterpret_cast<const float4*>(&W[(size_t)(kc + k) * 128 + c4 * 4]);
            }
        }
        #pragma unroll
        for (int ks = 0; ks < 2; ++ks) {
            int kb = ks * 8;
            unsigned af[2][4];
            #pragma unroll
            for (int mt = 0; mt < 2; ++mt) {
                int mr = warp_m * 32 + mt * 16;
                af[mt][0] = __float_as_uint(As[buf][kb + tig    ][mr + g]);
                af[mt][1] = __float_as_uint(As[buf][kb + tig    ][mr + g + 8]);
                af[mt][2] = __float_as_uint(As[buf][kb + tig + 4][mr + g]);
                af[mt][3] = __float_as_uint(As[buf][kb + tig + 4][mr + g + 8]);
            }
            #pragma unroll
            for (int nt = 0; nt < 8; ++nt) {
                int nc = warp_n * 64 + nt * 8;
                unsigned bf0 = __float_as_uint(Ws[buf][kb + tig    ][nc + g]);
                unsigned bf1 = __float_as_uint(Ws[buf][kb + tig + 4][nc + g]);
                #pragma unroll
                for (int mt = 0; mt < 2; ++mt) {
                    asm volatile(
                        "mma.sync.aligned.m16n8k8.row.col.f32.tf32.tf32.f32 "
                        "{%0,%1,%2,%3}, {%4,%5,%6,%7}, {%8,%9}, {%0,%1,%2,%3};"
                        : "+f"(acc[mt][nt][0]), "+f"(acc[mt][nt][1]),
                          "+f"(acc[mt][nt][2]), "+f"(acc[mt][nt][3])
                        : "r"(af[mt][0]), "r"(af[mt][1]), "r"(af[mt][2]), "r"(af[mt][3]),
                          "r"(bf0), "r"(bf1));
                }
            }
        }
        if (c + 1 < chunks) {
            int nb = buf ^ 1;
            #pragma unroll
            for (int j = 0; j < 2; ++j) {
                int idx = tid * 2 + j;
                int r = idx >> 2, k4 = idx & 3;
                As[nb][k4 * 4 + 0][r] = f2tf32(ra[j].x);
                As[nb][k4 * 4 + 1][r] = f2tf32(ra[j].y);
                As[nb][k4 * 4 + 2][r] = f2tf32(ra[j].z);
                As[nb][k4 * 4 + 3][r] = f2tf32(ra[j].w);
                int k = idx >> 5, c4 = idx & 31;
                Ws[nb][k][c4 * 4 + 0] = f2tf32(rw[j].x);
                Ws[nb][k][c4 * 4 + 1] = f2tf32(rw[j].y);
                Ws[nb][k][c4 * 4 + 2] = f2tf32(rw[j].z);
                Ws[nb][k][c4 * 4 + 3] = f2tf32(rw[j].w);
            }
        }
        __syncthreads();
    }

    // epilogue: bias + per-row sum of squares (quad shfl + cross-warp smem)
    float sa[2] = {0.f, 0.f}, sb[2] = {0.f, 0.f};
    #pragma unroll
    for (int nt = 0; nt < 8; ++nt) {
        int col = warp_n * 64 + nt * 8 + 2 * tig;
        float2 bb = *reinterpret_cast<const float2*>(&bias[col]);
        #pragma unroll
        for (int mt = 0; mt < 2; ++mt) {
            acc[mt][nt][0] += bb.x;
            acc[mt][nt][1] += bb.y;
            acc[mt][nt][2] += bb.x;
            acc[mt][nt][3] += bb.y;
            sa[mt] = fmaf(acc[mt][nt][0], acc[mt][nt][0], fmaf(acc[mt][nt][1], acc[mt][nt][1], sa[mt]));
            sb[mt] = fmaf(acc[mt][nt][2], acc[mt][nt][2], fmaf(acc[mt][nt][3], acc[mt][nt][3], sb[mt]));
        }
    }
    #pragma unroll
    for (int mt = 0; mt < 2; ++mt) {
        sa[mt] += __shfl_xor_sync(0xffffffffu, sa[mt], 1);
        sa[mt] += __shfl_xor_sync(0xffffffffu, sa[mt], 2);
        sb[mt] += __shfl_xor_sync(0xffffffffu, sb[mt], 1);
        sb[mt] += __shfl_xor_sync(0xffffffffu, sb[mt], 2);
        if (tig == 0) {
            int rla = warp_m * 32 + mt * 16 + g;
            rsum[rla][warp_n]     = sa[mt];
            rsum[rla + 8][warp_n] = sb[mt];
        }
    }
    __syncthreads();
    #pragma unroll
    for (int mt = 0; mt < 2; ++mt) {
        int rla = warp_m * 32 + mt * 16 + g;
        float inva = 1.f / fmaxf(sqrtf(rsum[rla][0]     + rsum[rla][1]),     1e-12f);
        float invb = 1.f / fmaxf(sqrtf(rsum[rla + 8][0] + rsum[rla + 8][1]), 1e-12f);
        int row_a = row0 + rla;
        int row_b = row_a + 8;
        #pragma unroll
        for (int nt = 0; nt < 8; ++nt) {
            int col = warp_n * 64 + nt * 8 + 2 * tig;
            if (row_a < n)
                *reinterpret_cast<float2*>(&C[(size_t)row_a * 128 + col]) =
                    make_float2(acc[mt][nt][0] * inva, acc[mt][nt][1] * inva);
            if (row_b < n)
                *reinterpret_cast<float2*>(&C[(size_t)row_b * 128 + col]) =
                    make_float2(acc[mt][nt][2] * invb, acc[mt][nt][3] * invb);
        }
    }
}

// ---------------- fused GATv2 aggregation + LayerNorm + GELU + residual
__global__ __launch_bounds__(256) void gat_agg(
    const float* __restrict__ att, const float* __restrict__ bo,
    const float* __restrict__ gam, const float* __restrict__ bet,
    int resflag, int n)
{
    int warp = threadIdx.x >> 5;
    int lane = threadIdx.x & 31;
    int i = blockIdx.x * 8 + warp;
    if (i >= n) return;
    int c0 = lane * 4;

    float4 xl = *reinterpret_cast<const float4*>(&g_xl[(size_t)i * 128 + c0]);
    float4 a4 = __ldg(reinterpret_cast<const float4*>(&att[c0]));

    float4 xs = ldxr_h(i, lane);
    float t0 = xl.x + xs.x; t0 = fmaxf(t0, 0.2f * t0);
    float t1 = xl.y + xs.y; t1 = fmaxf(t1, 0.2f * t1);
    float t2 = xl.z + xs.z; t2 = fmaxf(t2, 0.2f * t2);
    float t3 = xl.w + xs.w; t3 = fmaxf(t3, 0.2f * t3);
    float v = fmaf(t0, a4.x, fmaf(t1, a4.y, fmaf(t2, a4.z, t3 * a4.w)));
    v += __shfl_xor_sync(0xffffffffu, v, 1);
    v += __shfl_xor_sync(0xffffffffu, v, 2);
    v += __shfl_xor_sync(0xffffffffu, v, 4);
    float m = v, den = 1.f;
    float4 acc = xs;

#define GAT_LOGIT(vv, xv)                                                    \
    {                                                                        \
        float u0 = xl.x + xv.x; u0 = fmaxf(u0, 0.2f * u0);                   \
        float u1 = xl.y + xv.y; u1 = fmaxf(u1, 0.2f * u1);                   \
        float u2 = xl.z + xv.z; u2 = fmaxf(u2, 0.2f * u2);                   \
        float u3 = xl.w + xv.w; u3 = fmaxf(u3, 0.2f * u3);                   \
        vv = fmaf(u0, a4.x, fmaf(u1, a4.y, fmaf(u2, a4.z, u3 * a4.w)));      \
    }

#define GAT_RUNMERGE(vv, xv)                                                 \
    {                                                                        \
        float nm = fmaxf(m, vv);                                             \
        float sc = __expf(m - nm);                                           \
        float pe = __expf(vv - nm);                                          \
        den = fmaf(den, sc, pe);                                             \
        acc.x = fmaf(acc.x, sc, pe * xv.x);                                  \
        acc.y = fmaf(acc.y, sc, pe * xv.y);                                  \
        acc.z = fmaf(acc.z, sc, pe * xv.z);                                  \
        acc.w = fmaf(acc.w, sc, pe * xv.w);                                  \
        m = nm;                                                              \
    }

#define GAT_BODY4(xa, xb, xc, xd)                                            \
    {                                                                        \
        float va, vb, vc, vd;                                                \
        GAT_LOGIT(va, xa);                                                   \
        GAT_LOGIT(vb, xb);                                                   \
        GAT_LOGIT(vc, xc);                                                   \
        GAT_LOGIT(vd, xd);                                                   \
        va += __shfl_xor_sync(0xffffffffu, va, 1);                           \
        vb += __shfl_xor_sync(0xffffffffu, vb, 1);                           \
        vc += __shfl_xor_sync(0xffffffffu, vc, 1);                           \
        vd += __shfl_xor_sync(0xffffffffu, vd, 1);                           \
        va += __shfl_xor_sync(0xffffffffu, va, 2);                           \
        vb += __shfl_xor_sync(0xffffffffu, vb, 2);                           \
        vc += __shfl_xor_sync(0xffffffffu, vc, 2);                           \
        vd += __shfl_xor_sync(0xffffffffu, vd, 2);                           \
        va += __shfl_xor_sync(0xffffffffu, va, 4);                           \
        vb += __shfl_xor_sync(0xffffffffu, vb, 4);                           \
        vc += __shfl_xor_sync(0xffffffffu, vc, 4);                           \
        vd += __shfl_xor_sync(0xffffffffu, vd, 4);                           \
        float mab = fmaxf(va, vb);                                           \
        float pa  = __expf(va - mab);                                        \
        float pb  = __expf(vb - mab);                                        \
        float dab = pa + pb;                                                 \
        float4 aab;                                                          \
        aab.x = fmaf(pa, xa.x, pb * xb.x);                                   \
        aab.y = fmaf(pa, xa.y, pb * xb.y);                                   \
        aab.z = fmaf(pa, xa.z, pb * xb.z);                                   \
        aab.w = fmaf(pa, xa.w, pb * xb.w);                                   \
        float mcd = fmaxf(vc, vd);                                           \
        float pc  = __expf(vc - mcd);                                        \
        float pd  = __expf(vd - mcd);                                        \
        float dcd = pc + pd;                                                 \
        float4 acd;                                                          \
        acd.x = fmaf(pc, xc.x, pd * xd.x);                                   \
        acd.y = fmaf(pc, xc.y, pd * xd.y);                                   \
        acd.z = fmaf(pc, xc.z, pd * xd.z);                                   \
        acd.w = fmaf(pc, xc.w, pd * xd.w);                                   \
        {                                                                    \
            float nm = fmaxf(m, mab);                                        \
            float sc = __expf(m - nm);                                       \
            float s2 = __expf(mab - nm);                                     \
            den = fmaf(den, sc, dab * s2);                                   \
            acc.x = fmaf(acc.x, sc, aab.x * s2);                             \
            acc.y = fmaf(acc.y, sc, aab.y * s2);                             \
            acc.z = fmaf(acc.z, sc, aab.z * s2);                             \
            acc.w = fmaf(acc.w, sc, aab.w * s2);                             \
            m = nm;                                                          \
        }                                                                    \
        {                                                                    \
            float nm = fmaxf(m, mcd);                                        \
            float sc = __expf(m - nm);                                       \
            float s2 = __expf(mcd - nm);                                     \
            den = fmaf(den, sc, dcd * s2);                                   \
            acc.x = fmaf(acc.x, sc, acd.x * s2);                             \
            acc.y = fmaf(acc.y, sc, acd.y * s2);                             \
            acc.z = fmaf(acc.z, sc, acd.z * s2);                             \
            acc.w = fmaf(acc.w, sc, acd.w * s2);                             \
            m = nm;                                                          \
        }                                                                    \
    }

    int beg = g_rowptr[i], end = g_rowptr[i + 1];
    int k = beg;

    float4 pxa, pxb, pxc, pxd;
    if (k + 4 <= end) {
        pxa = ldxr_h(g_col[k], lane);
        pxb = ldxr_h(g_col[k + 1], lane);
        pxc = ldxr_h(g_col[k + 2], lane);
        pxd = ldxr_h(g_col[k + 3], lane);
    }
    for (; k + 8 <= end; k += 4) {
        float4 nxa = ldxr_h(g_col[k + 4], lane);
        float4 nxb = ldxr_h(g_col[k + 5], lane);
        float4 nxc = ldxr_h(g_col[k + 6], lane);
        float4 nxd = ldxr_h(g_col[k + 7], lane);
        GAT_BODY4(pxa, pxb, pxc, pxd);
        pxa = nxa; pxb = nxb; pxc = nxc; pxd = nxd;
    }
    if (k + 4 <= end) {
        GAT_BODY4(pxa, pxb, pxc, pxd);
        k += 4;
    }
    if (k + 2 <= end) {
        float4 xa = ldxr_h(g_col[k], lane);
        float4 xb = ldxr_h(g_col[k + 1], lane);
        float va, vb;
        GAT_LOGIT(va, xa);
        GAT_LOGIT(vb, xb);
        va += __shfl_xor_sync(0xffffffffu, va, 1);
        vb += __shfl_xor_sync(0xffffffffu, vb, 1);
        va += __shfl_xor_sync(0xffffffffu, va, 2);
        vb += __shfl_xor_sync(0xffffffffu, vb, 2);
        va += __shfl_xor_sync(0xffffffffu, va, 4);
        vb += __shfl_xor_sync(0xffffffffu, vb, 4);
        GAT_RUNMERGE(va, xa);
        GAT_RUNMERGE(vb, xb);
        k += 2;
    }
    if (k < end) {
        float4 xa = ldxr_h(g_col[k], lane);
        float va;
        GAT_LOGIT(va, xa);
        va += __shfl_xor_sync(0xffffffffu, va, 1);
        va += __shfl_xor_sync(0xffffffffu, va, 2);
        va += __shfl_xor_sync(0xffffffffu, va, 4);
        GAT_RUNMERGE(va, xa);
    }
#undef GAT_LOGIT
#undef GAT_RUNMERGE
#undef GAT_BODY4

    float inv = 1.f / (den + 1e-16f);
    float4 bo4 = __ldg(reinterpret_cast<const float4*>(&bo[c0]));
    float o0 = fmaf(acc.x, inv, bo4.x);
    float o1 = fmaf(acc.y, inv, bo4.y);
    float o2 = fmaf(acc.z, inv, bo4.z);
    float o3 = fmaf(acc.w, inv, bo4.w);

    float s1 = o0 + o1 + o2 + o3;
    float s2 = fmaf(o0, o0, fmaf(o1, o1, fmaf(o2, o2, o3 * o3)));
    #pragma unroll
    for (int o = 1; o < 32; o <<= 1) {
        s1 += __shfl_xor_sync(0xffffffffu, s1, o);
        s2 += __shfl_xor_sync(0xffffffffu, s2, o);
    }
    float mu  = s1 * (1.f / 128.f);
    float var = s2 * (1.f / 128.f) - mu * mu;
    var = var > 0.f ? var : 0.f;
    float rstd = rsqrtf(var + 1e-5f);
    float4 g4 = __ldg(reinterpret_cast<const float4*>(&gam[c0]));
    float4 b4 = __ldg(reinterpret_cast<const float4*>(&bet[c0]));
    float y0 = g4.x * (o0 - mu) * rstd + b4.x;
    float y1 = g4.y * (o1 - mu) * rstd + b4.y;
    float y2 = g4.z * (o2 - mu) * rstd + b4.z;
    float y3 = g4.w * (o3 - mu) * rstd + b4.w;
    const float is2 = 0.70710678118654752f;
    float gl0 = 0.5f * y0 * (1.f + erff(y0 * is2));
    float gl1 = 0.5f * y1 * (1.f + erff(y1 * is2));
    float gl2 = 0.5f * y2 * (1.f + erff(y2 * is2));
    float gl3 = 0.5f * y3 * (1.f + erff(y3 * is2));

    float4* hp = reinterpret_cast<float4*>(&g_h[(size_t)i * 128 + c0]);
    if (resflag) {
        float4 hv = *hp;
        hv.x += gl0; hv.y += gl1; hv.z += gl2; hv.w += gl3;
        *hp = hv;
    } else {
        *hp = make_float4(gl0, gl1, gl2, gl3);
    }
}

// ---------------- host launcher ----------------
extern "C" void kernel_launch(void* const* d_in, const int* in_sizes, int n_in,
                              void* d_out, int out_size)
{
    const float* x    = (const float*)d_in[0];
    const void*  ei   = d_in[1];
    const float* W_in = (const float*)d_in[2];
    const float* b_in = (const float*)d_in[3];
    const float *Wl[3], *bl[3], *Wr[3], *br[3], *att[3], *bo[3], *gg[3], *be[3];
    for (int l = 0; l < 3; ++l) {
        int base = 4 + l * 8;
        Wl[l]  = (const float*)d_in[base + 0];
        bl[l]  = (const float*)d_in[base + 1];
        Wr[l]  = (const float*)d_in[base + 2];
        br[l]  = (const float*)d_in[base + 3];
        att[l] = (const float*)d_in[base + 4];
        bo[l]  = (const float*)d_in[base + 5];
        gg[l]  = (const float*)d_in[base + 6];
        be[l]  = (const float*)d_in[base + 7];
    }
    const float* W_out = (const float*)d_in[28];
    const float* b_out = (const float*)d_in[29];

    int n = in_sizes[0] / 128;
    int e = in_sizes[1] / 2;
    int P = (n + 1023) / 1024;

    float *hbuf, *xlbuf;
    cudaGetSymbolAddress((void**)&hbuf,  g_h);
    cudaGetSymbolAddress((void**)&xlbuf, g_xl);

    static int smem_set = 0;
    if (!smem_set) {
        cudaFuncSetAttribute(fused_in_l0,
                             cudaFuncAttributeMaxDynamicSharedMemorySize, FUSED_SMEM);
        smem_set = 1;
    }

    dim3 gdual((n + 127) / 128, 2);
    int gsingle = (n + 127) / 128;
    int aggblocks = (n + 7) / 8;

    // index 3 = fused_in_l0 (profiled this round)
    zero_detect<<<(n + 255) / 256, 256>>>(ei, e, n);
    convert_hist<<<(e + 255) / 256, 256>>>(ei, e);
    scan_part<<<P, 256>>>(n);
    fused_in_l0<<<gsingle, 256, FUSED_SMEM>>>(x, W_in, b_in,
                                              Wl[0], bl[0], Wr[0], br[0],
                                              xlbuf, n);
    scan_down<<<P, 256>>>(n, P);
    scatter_edges<<<(e + 255) / 256, 256>>>(e);
    sort_warp<<<(n + 7) / 8, 256>>>(n);

    gat_agg<<<aggblocks, 256>>>(att[0], bo[0], gg[0], be[0], 0, n);
    for (int l = 1; l < 3; ++l) {
        gemm_mma<<<gdual, 256>>>(hbuf, Wl[l], bl[l], xlbuf, Wr[l], br[l], n, 128);
        gat_agg<<<aggblocks, 256>>>(att[l], bo[l], gg[l], be[l], 1, n);
    }

    gemm_out_mma<<<gsingle, 256>>>(hbuf, W_out, b_out, (float*)d_out, n);
}